// round 7
// baseline (speedup 1.0000x reference)
#include <cuda_runtime.h>
#include <math.h>
#include <stdint.h>

// ---------------- problem constants ----------------
#define NLAYER 4
#define NHEAD  8
#define DMODEL 512
#define TLEN   2048
#define BATCH  2
#define VOCAB  32000
#define HDIM   64
#define MROWS  (BATCH * TLEN)   // 4096
#define EPS    1e-5f

// ---------------- scratch (static device globals; no allocs allowed) -------
__device__ float g_x  [MROWS * DMODEL];
__device__ float g_h  [MROWS * DMODEL];
__device__ float g_qkv[MROWS * 3 * DMODEL];
__device__ float g_att[MROWS * DMODEL];
__device__ float g_fc [MROWS * 4 * DMODEL];

// ---------------- embedding ----------------
__global__ void embed_kernel(const float* __restrict__ wte,
                             const float* __restrict__ wpe,
                             const int*   __restrict__ idx,
                             float* __restrict__ x) {
    int m = blockIdx.x;
    int t = m % TLEN;
    int tok = idx[m];
    const float* we = wte + (size_t)tok * DMODEL;
    const float* pe = wpe + (size_t)t * DMODEL;
    float* xr = x + (size_t)m * DMODEL;
    for (int d = threadIdx.x; d < DMODEL; d += blockDim.x)
        xr[d] = we[d] + pe[d];
}

// ---------------- layernorm ----------------
__global__ __launch_bounds__(256)
void ln_kernel(const float* __restrict__ x, const float* __restrict__ w,
               const float* __restrict__ b, float* __restrict__ y) {
    int row = blockIdx.x;
    int tid = threadIdx.x;
    const float* xr = x + (size_t)row * DMODEL;
    float v0 = xr[tid];
    float v1 = xr[tid + 256];

    __shared__ float red[8];
    __shared__ float bc;

    float s = v0 + v1;
    #pragma unroll
    for (int o = 16; o; o >>= 1) s += __shfl_xor_sync(0xffffffffu, s, o);
    if ((tid & 31) == 0) red[tid >> 5] = s;
    __syncthreads();
    if (tid == 0) {
        float t = 0.f;
        #pragma unroll
        for (int i = 0; i < 8; i++) t += red[i];
        bc = t;
    }
    __syncthreads();
    float mu = bc * (1.f / DMODEL);
    float d0 = v0 - mu, d1 = v1 - mu;

    float s2 = d0 * d0 + d1 * d1;
    #pragma unroll
    for (int o = 16; o; o >>= 1) s2 += __shfl_xor_sync(0xffffffffu, s2, o);
    __syncthreads();
    if ((tid & 31) == 0) red[tid >> 5] = s2;
    __syncthreads();
    if (tid == 0) {
        float t = 0.f;
        #pragma unroll
        for (int i = 0; i < 8; i++) t += red[i];
        bc = t;
    }
    __syncthreads();
    float inv = rsqrtf(bc * (1.f / DMODEL) + EPS);

    float* yr = y + (size_t)row * DMODEL;
    yr[tid]       = d0 * inv * w[tid]       + b[tid];
    yr[tid + 256] = d1 * inv * w[tid + 256] + b[tid + 256];
}

// ---------------- tf32 helpers ----------------------------------------------
__device__ __forceinline__ uint32_t f2tf32(float v) {
    uint32_t r;
    asm("cvt.rna.tf32.f32 %0, %1;" : "=r"(r) : "f"(v));
    return r;
}

__device__ __forceinline__ void mma_tf32(float* d, const uint32_t* a, const uint32_t* b) {
    asm volatile(
        "mma.sync.aligned.m16n8k8.row.col.f32.tf32.tf32.f32 "
        "{%0,%1,%2,%3},{%4,%5,%6,%7},{%8,%9},{%0,%1,%2,%3};\n"
        : "+f"(d[0]), "+f"(d[1]), "+f"(d[2]), "+f"(d[3])
        : "r"(a[0]), "r"(a[1]), "r"(a[2]), "r"(a[3]), "r"(b[0]), "r"(b[1]));
}

// ---------------- pipelined tf32 tensor-core GEMM ----------------------------
// (round-4 proven kernel: double-buffered smem, one sync per k-iter)
#define AP 20
#define BP 136
template<bool BTRANS>
__global__ __launch_bounds__(256)
void gemm_tf32(const float* __restrict__ A, const float* __restrict__ Bm,
               const float* __restrict__ bias, const float* __restrict__ resid,
               float* __restrict__ Cm, int M, int N, int K, int gelu_flag) {
    __shared__ uint32_t As[2][128 * AP];
    __shared__ uint32_t Bs[2][16 * BP];

    int tid  = threadIdx.x;
    int lane = tid & 31;
    int w    = tid >> 5;
    int g    = lane >> 2;
    int tig  = lane & 3;
    int wm   = (w >> 2) * 64;
    int wn   = (w & 3) * 32;
    int m0 = (BTRANS ? blockIdx.x : blockIdx.y) * 128;
    int n0 = (BTRANS ? blockIdx.y : blockIdx.x) * 128;

    int aR0 = tid >> 2,            aC0 = (tid & 3) * 4;
    int aR1 = (tid + 256) >> 2,    aC1 = aC0;
    int bKr0, bNc0, bKr1, bNc1;
    if (!BTRANS) { bKr0 = tid >> 5; bNc0 = (tid & 31) * 4;
                   bKr1 = (tid + 256) >> 5; bNc1 = bNc0; }
    else         { bKr0 = (tid & 3) * 4; bNc0 = tid >> 2;
                   bKr1 = bKr0; bNc1 = (tid + 256) >> 2; }

    float4 arg0, arg1, brg0, brg1;

    auto load_tile = [&](int k0) {
        arg0 = *(const float4*)&A[(size_t)(m0 + aR0) * K + k0 + aC0];
        arg1 = *(const float4*)&A[(size_t)(m0 + aR1) * K + k0 + aC1];
        if (!BTRANS) {
            brg0 = *(const float4*)&Bm[(size_t)(k0 + bKr0) * N + n0 + bNc0];
            brg1 = *(const float4*)&Bm[(size_t)(k0 + bKr1) * N + n0 + bNc1];
        } else {
            brg0 = *(const float4*)&Bm[(size_t)(n0 + bNc0) * K + k0 + bKr0];
            brg1 = *(const float4*)&Bm[(size_t)(n0 + bNc1) * K + k0 + bKr1];
        }
    };
    auto store_tile = [&](int buf) {
        uint32_t* ap = &As[buf][aR0 * AP + aC0];
        ap[0] = f2tf32(arg0.x); ap[1] = f2tf32(arg0.y);
        ap[2] = f2tf32(arg0.z); ap[3] = f2tf32(arg0.w);
        ap = &As[buf][aR1 * AP + aC1];
        ap[0] = f2tf32(arg1.x); ap[1] = f2tf32(arg1.y);
        ap[2] = f2tf32(arg1.z); ap[3] = f2tf32(arg1.w);
        if (!BTRANS) {
            uint32_t* bp = &Bs[buf][bKr0 * BP + bNc0];
            bp[0] = f2tf32(brg0.x); bp[1] = f2tf32(brg0.y);
            bp[2] = f2tf32(brg0.z); bp[3] = f2tf32(brg0.w);
            bp = &Bs[buf][bKr1 * BP + bNc1];
            bp[0] = f2tf32(brg1.x); bp[1] = f2tf32(brg1.y);
            bp[2] = f2tf32(brg1.z); bp[3] = f2tf32(brg1.w);
        } else {
            Bs[buf][(bKr0 + 0) * BP + bNc0] = f2tf32(brg0.x);
            Bs[buf][(bKr0 + 1) * BP + bNc0] = f2tf32(brg0.y);
            Bs[buf][(bKr0 + 2) * BP + bNc0] = f2tf32(brg0.z);
            Bs[buf][(bKr0 + 3) * BP + bNc0] = f2tf32(brg0.w);
            Bs[buf][(bKr1 + 0) * BP + bNc1] = f2tf32(brg1.x);
            Bs[buf][(bKr1 + 1) * BP + bNc1] = f2tf32(brg1.y);
            Bs[buf][(bKr1 + 2) * BP + bNc1] = f2tf32(brg1.z);
            Bs[buf][(bKr1 + 3) * BP + bNc1] = f2tf32(brg1.w);
        }
    };

    float d[4][4][4];
    #pragma unroll
    for (int i = 0; i < 4; i++)
        #pragma unroll
        for (int j = 0; j < 4; j++)
            #pragma unroll
            for (int r = 0; r < 4; r++) d[i][j][r] = 0.f;

    load_tile(0);
    store_tile(0);
    __syncthreads();

    int buf = 0;
    for (int k0 = 0; k0 < K; k0 += 16) {
        int nk = k0 + 16;
        if (nk < K) load_tile(nk);

        const uint32_t* Ac = As[buf];
        const uint32_t* Bc = Bs[buf];
        #pragma unroll
        for (int kk = 0; kk < 16; kk += 8) {
            uint32_t af[4][4];
            #pragma unroll
            for (int mi = 0; mi < 4; mi++) {
                int rb = wm + mi * 16;
                af[mi][0] = Ac[(rb + g    ) * AP + kk + tig    ];
                af[mi][1] = Ac[(rb + g + 8) * AP + kk + tig    ];
                af[mi][2] = Ac[(rb + g    ) * AP + kk + tig + 4];
                af[mi][3] = Ac[(rb + g + 8) * AP + kk + tig + 4];
            }
            uint32_t bf[4][2];
            #pragma unroll
            for (int nj = 0; nj < 4; nj++) {
                int cb = wn + nj * 8;
                bf[nj][0] = Bc[(kk + tig    ) * BP + cb + g];
                bf[nj][1] = Bc[(kk + tig + 4) * BP + cb + g];
            }
            #pragma unroll
            for (int mi = 0; mi < 4; mi++)
                #pragma unroll
                for (int nj = 0; nj < 4; nj++)
                    mma_tf32(d[mi][nj], af[mi], bf[nj]);
        }

        if (nk < K) store_tile(buf ^ 1);
        __syncthreads();
        buf ^= 1;
    }

    #pragma unroll
    for (int mi = 0; mi < 4; mi++) {
        #pragma unroll
        for (int rr = 0; rr < 2; rr++) {
            int m = m0 + wm + mi * 16 + g + rr * 8;
            float* crow = Cm + (size_t)m * N;
            const float* rrow = resid ? resid + (size_t)m * N : nullptr;
            #pragma unroll
            for (int nj = 0; nj < 4; nj++) {
                int n = n0 + wn + nj * 8 + tig * 2;
                #pragma unroll
                for (int cc = 0; cc < 2; cc++) {
                    float c = d[mi][nj][rr * 2 + cc];
                    if (bias) c += bias[n + cc];
                    if (rrow) c += rrow[n + cc];
                    if (gelu_flag)
                        c = 0.5f * c * (1.f + erff(c * 0.70710678118654752f));
                    crow[n + cc] = c;
                }
            }
        }
    }
}

// ---------------- tensor-core causal flash attention -------------------------
// 128 q-rows per CTA (256 threads, 8 warps x 16 rows): each K/V tile fill
// serves 2x the MMA work vs the 64-row version. Split-tf32 QK^T, tf32 PV,
// register softmax. Ps is a dedicated 128-row buffer aliasing Q? No —
// Ps aliases Kl only for 64 rows; with 8 warps' 128 distinct row bands we
// give Ps its own fold: each warp's 16-row band maps to (wrow&63)+g, and
// warps 0-3 vs 4-7 never collide because bands (wrow&63) are 0,16,32,48
// for both halves — SO THEY WOULD COLLIDE. Fix: Ps gets rows indexed by
// warp id directly: prow = wid*16 + g (0..127) in a 128-row buffer that
// aliases the Qh tile? Qh is still live (reused every j0 iter). Therefore
// Ps gets its own 128-row region; smem total = (2*128 + 3*64 + 128) * 72
// words = 165888 B < 227 KB. Still 1 CTA/SM (as measured, occupancy is not
// the binding constraint).
#define AT_P 72
#define ATTN_SMEM_TC ((2 * 128 + 3 * 64 + 128) * AT_P * (int)sizeof(uint32_t))

__global__ __launch_bounds__(256)
void attn_tc_kernel(const float* __restrict__ qkv, float* __restrict__ out) {
    extern __shared__ uint32_t smu[];
    uint32_t* Qh = smu;                    // [128][72]
    uint32_t* Ql = Qh + 128 * AT_P;        // [128][72]
    uint32_t* Kh = Ql + 128 * AT_P;        // [64][72]
    uint32_t* Kl = Kh + 64 * AT_P;         // [64][72]
    uint32_t* Vt = Kl + 64 * AT_P;         // [64][72]
    uint32_t* Ps = Vt + 64 * AT_P;         // [128][72]

    int tid  = threadIdx.x;
    int lane = tid & 31;
    int wid  = tid >> 5;
    int g    = lane >> 2;
    int tig  = lane & 3;
    int b = blockIdx.y >> 3, h = blockIdx.y & 7;
    int q0 = (int)(gridDim.x - 1 - blockIdx.x) * 128;   // heavy tiles first
    const int RS = 3 * DMODEL;
    const float* qbase = qkv + (size_t)b * TLEN * RS + h * HDIM;
    const float* kbase = qbase + DMODEL;
    const float* vbase = qbase + 2 * DMODEL;

    // load Q tile (128 x 64), scaled + split hi/lo
    for (int i = tid; i < 128 * 16; i += 256) {
        int r = i >> 4, d4 = (i & 15) * 4;
        float4 v = *(const float4*)&qbase[(size_t)(q0 + r) * RS + d4];
        float q4[4] = {v.x, v.y, v.z, v.w};
        #pragma unroll
        for (int c = 0; c < 4; c++) {
            float qs = q4[c] * 0.125f;
            uint32_t hi = f2tf32(qs);
            Qh[r * AT_P + d4 + c] = hi;
            Ql[r * AT_P + d4 + c] = f2tf32(qs - __uint_as_float(hi));
        }
    }

    float o[8][4];
    #pragma unroll
    for (int nj = 0; nj < 8; nj++)
        #pragma unroll
        for (int c = 0; c < 4; c++) o[nj][c] = 0.f;
    float m0 = -1e30f, m1 = -1e30f, l0 = 0.f, l1 = 0.f;
    int wrow = wid * 16;
    int rowA = wrow + g, rowB = wrow + g + 8;

    for (int j0 = 0; j0 <= q0 + 64; j0 += 64) {
        bool active = (j0 <= q0 + wrow + 15);

        __syncthreads();   // prev iter's PV reads of Vt done before refill
        for (int i = tid; i < 64 * 16; i += 256) {
            int r = i >> 4, d4 = (i & 15) * 4;
            float4 kv = *(const float4*)&kbase[(size_t)(j0 + r) * RS + d4];
            float4 vv = *(const float4*)&vbase[(size_t)(j0 + r) * RS + d4];
            float k4[4] = {kv.x, kv.y, kv.z, kv.w};
            float v4[4] = {vv.x, vv.y, vv.z, vv.w};
            #pragma unroll
            for (int c = 0; c < 4; c++) {
                uint32_t hi = f2tf32(k4[c]);
                Kh[r * AT_P + d4 + c] = hi;
                Kl[r * AT_P + d4 + c] = f2tf32(k4[c] - __uint_as_float(hi));
                Vt[r * AT_P + d4 + c] = f2tf32(v4[c]);
            }
        }
        __syncthreads();

        if (active) {
            float s[8][4];
            #pragma unroll
            for (int nj = 0; nj < 8; nj++)
                #pragma unroll
                for (int c = 0; c < 4; c++) s[nj][c] = 0.f;

            #pragma unroll
            for (int k8 = 0; k8 < 64; k8 += 8) {
                uint32_t ah[4], al[4];
                ah[0] = Qh[rowA * AT_P + k8 + tig];
                ah[1] = Qh[rowB * AT_P + k8 + tig];
                ah[2] = Qh[rowA * AT_P + k8 + tig + 4];
                ah[3] = Qh[rowB * AT_P + k8 + tig + 4];
                al[0] = Ql[rowA * AT_P + k8 + tig];
                al[1] = Ql[rowB * AT_P + k8 + tig];
                al[2] = Ql[rowA * AT_P + k8 + tig + 4];
                al[3] = Ql[rowB * AT_P + k8 + tig + 4];
                #pragma unroll
                for (int nj = 0; nj < 8; nj++) {
                    int kr = nj * 8 + g;
                    uint32_t bh2[2] = {Kh[kr * AT_P + k8 + tig], Kh[kr * AT_P + k8 + tig + 4]};
                    uint32_t bl2[2] = {Kl[kr * AT_P + k8 + tig], Kl[kr * AT_P + k8 + tig + 4]};
                    mma_tf32(s[nj], ah, bh2);
                    mma_tf32(s[nj], al, bh2);
                    mma_tf32(s[nj], ah, bl2);
                }
            }

            if (j0 + 63 > q0 + wrow) {
                int qA = q0 + rowA, qB = q0 + rowB;
                #pragma unroll
                for (int nj = 0; nj < 8; nj++) {
                    int c0 = j0 + nj * 8 + 2 * tig;
                    if (c0     > qA) s[nj][0] = -1e30f;
                    if (c0 + 1 > qA) s[nj][1] = -1e30f;
                    if (c0     > qB) s[nj][2] = -1e30f;
                    if (c0 + 1 > qB) s[nj][3] = -1e30f;
                }
            }

            float mx0 = m0, mx1 = m1;
            #pragma unroll
            for (int nj = 0; nj < 8; nj++) {
                mx0 = fmaxf(mx0, fmaxf(s[nj][0], s[nj][1]));
                mx1 = fmaxf(mx1, fmaxf(s[nj][2], s[nj][3]));
            }
            mx0 = fmaxf(mx0, __shfl_xor_sync(0xffffffffu, mx0, 1));
            mx0 = fmaxf(mx0, __shfl_xor_sync(0xffffffffu, mx0, 2));
            mx1 = fmaxf(mx1, __shfl_xor_sync(0xffffffffu, mx1, 1));
            mx1 = fmaxf(mx1, __shfl_xor_sync(0xffffffffu, mx1, 2));

            float fac0 = __expf(m0 - mx0), fac1 = __expf(m1 - mx1);
            float sum0 = 0.f, sum1 = 0.f;
            #pragma unroll
            for (int nj = 0; nj < 8; nj++) {
                s[nj][0] = __expf(s[nj][0] - mx0);
                s[nj][1] = __expf(s[nj][1] - mx0);
                s[nj][2] = __expf(s[nj][2] - mx1);
                s[nj][3] = __expf(s[nj][3] - mx1);
                sum0 += s[nj][0] + s[nj][1];
                sum1 += s[nj][2] + s[nj][3];
            }
            sum0 += __shfl_xor_sync(0xffffffffu, sum0, 1);
            sum0 += __shfl_xor_sync(0xffffffffu, sum0, 2);
            sum1 += __shfl_xor_sync(0xffffffffu, sum1, 1);
            sum1 += __shfl_xor_sync(0xffffffffu, sum1, 2);
            l0 = l0 * fac0 + sum0;
            l1 = l1 * fac1 + sum1;
            m0 = mx0; m1 = mx1;
            #pragma unroll
            for (int nj = 0; nj < 8; nj++) {
                o[nj][0] *= fac0; o[nj][1] *= fac0;
                o[nj][2] *= fac1; o[nj][3] *= fac1;
            }

            // Ps rows are per-warp private (row band wid*16..+15)
            #pragma unroll
            for (int nj = 0; nj < 8; nj++) {
                int cc = nj * 8 + 2 * tig;
                Ps[rowA * AT_P + cc]     = f2tf32(s[nj][0]);
                Ps[rowA * AT_P + cc + 1] = f2tf32(s[nj][1]);
                Ps[rowB * AT_P + cc]     = f2tf32(s[nj][2]);
                Ps[rowB * AT_P + cc + 1] = f2tf32(s[nj][3]);
            }
            __syncwarp();

            #pragma unroll
            for (int k8 = 0; k8 < 64; k8 += 8) {
                uint32_t a[4];
                a[0] = Ps[rowA * AT_P + k8 + tig];
                a[1] = Ps[rowB * AT_P + k8 + tig];
                a[2] = Ps[rowA * AT_P + k8 + tig + 4];
                a[3] = Ps[rowB * AT_P + k8 + tig + 4];
                #pragma unroll
                for (int nj = 0; nj < 8; nj++) {
                    uint32_t bv[2] = {Vt[(k8 + tig) * AT_P + nj * 8 + g],
                                      Vt[(k8 + tig + 4) * AT_P + nj * 8 + g]};
                    mma_tf32(o[nj], a, bv);
                }
            }
        }
    }

    float inv0 = 1.f / l0, inv1 = 1.f / l1;
    size_t rA = (size_t)(b * TLEN + q0 + rowA) * DMODEL + h * HDIM;
    size_t rB = (size_t)(b * TLEN + q0 + rowB) * DMODEL + h * HDIM;
    #pragma unroll
    for (int nj = 0; nj < 8; nj++) {
        int cc = nj * 8 + 2 * tig;
        out[rA + cc]     = o[nj][0] * inv0;
        out[rA + cc + 1] = o[nj][1] * inv0;
        out[rB + cc]     = o[nj][2] * inv1;
        out[rB + cc + 1] = o[nj][3] * inv1;
    }
}

// ---------------- driver ----------------------------------------------------
extern "C" void kernel_launch(void* const* d_in, const int* in_sizes, int n_in,
                              void* d_out, int out_size) {
    const float* wte    = (const float*)d_in[0];
    const float* wpe    = (const float*)d_in[1];
    const float* ln1_w  = (const float*)d_in[2];
    const float* ln1_b  = (const float*)d_in[3];
    const float* attn_w = (const float*)d_in[4];
    const float* attn_b = (const float*)d_in[5];
    const float* proj_w = (const float*)d_in[6];
    const float* proj_b = (const float*)d_in[7];
    const float* ln2_w  = (const float*)d_in[8];
    const float* ln2_b  = (const float*)d_in[9];
    const float* fc_w   = (const float*)d_in[10];
    const float* fc_b   = (const float*)d_in[11];
    const float* fc2_w  = (const float*)d_in[12];
    const float* fc2_b  = (const float*)d_in[13];
    const float* lnf_w  = (const float*)d_in[14];
    const float* lnf_b  = (const float*)d_in[15];
    const int*   idx    = (const int*)d_in[16];
    float* out = (float*)d_out;

    void *px, *ph, *pqkv, *patt, *pfc;
    cudaGetSymbolAddress(&px, g_x);
    cudaGetSymbolAddress(&ph, g_h);
    cudaGetSymbolAddress(&pqkv, g_qkv);
    cudaGetSymbolAddress(&patt, g_att);
    cudaGetSymbolAddress(&pfc, g_fc);
    float* x   = (float*)px;
    float* h   = (float*)ph;
    float* qkv = (float*)pqkv;
    float* att = (float*)patt;
    float* fcb = (float*)pfc;

    cudaFuncSetAttribute(attn_tc_kernel,
                         cudaFuncAttributeMaxDynamicSharedMemorySize, ATTN_SMEM_TC);

    embed_kernel<<<MROWS, 256>>>(wte, wpe, idx, x);

    for (int l = 0; l < NLAYER; l++) {
        const float* aw  = attn_w + (size_t)l * DMODEL * 3 * DMODEL;
        const float* ab  = attn_b + (size_t)l * 3 * DMODEL;
        const float* pw  = proj_w + (size_t)l * DMODEL * DMODEL;
        const float* pb  = proj_b + (size_t)l * DMODEL;
        const float* fw  = fc_w   + (size_t)l * DMODEL * 4 * DMODEL;
        const float* fb  = fc_b   + (size_t)l * 4 * DMODEL;
        const float* f2w = fc2_w  + (size_t)l * 4 * DMODEL * DMODEL;
        const float* f2b = fc2_b  + (size_t)l * DMODEL;

        ln_kernel<<<MROWS, 256>>>(x, ln1_w + l * DMODEL, ln1_b + l * DMODEL, h);
        gemm_tf32<false><<<dim3(3 * DMODEL / 128, MROWS / 128), 256>>>(
            h, aw, ab, nullptr, qkv, MROWS, 3 * DMODEL, DMODEL, 0);
        attn_tc_kernel<<<dim3(TLEN / 128, BATCH * NHEAD), 256, ATTN_SMEM_TC>>>(qkv, att);
        gemm_tf32<false><<<dim3(DMODEL / 128, MROWS / 128), 256>>>(
            att, pw, pb, x, x, MROWS, DMODEL, DMODEL, 0);
        ln_kernel<<<MROWS, 256>>>(x, ln2_w + l * DMODEL, ln2_b + l * DMODEL, h);
        gemm_tf32<false><<<dim3(4 * DMODEL / 128, MROWS / 128), 256>>>(
            h, fw, fb, nullptr, fcb, MROWS, 4 * DMODEL, DMODEL, 1);
        gemm_tf32<false><<<dim3(DMODEL / 128, MROWS / 128), 256>>>(
            fcb, f2w, f2b, x, x, MROWS, DMODEL, 4 * DMODEL, 0);
    }

    ln_kernel<<<MROWS, 256>>>(x, lnf_w, lnf_b, h);
    gemm_tf32<true><<<dim3(MROWS / 128, VOCAB / 128), 256>>>(
        h, wte, nullptr, nullptr, out, MROWS, VOCAB, DMODEL, 0);
}

// round 8
// speedup vs baseline: 1.5973x; 1.5973x over previous
#include <cuda_runtime.h>
#include <math.h>
#include <stdint.h>

// ---------------- problem constants ----------------
#define NLAYER 4
#define NHEAD  8
#define DMODEL 512
#define TLEN   2048
#define BATCH  2
#define VOCAB  32000
#define HDIM   64
#define MROWS  (BATCH * TLEN)   // 4096
#define EPS    1e-5f

// ---------------- scratch (static device globals; no allocs allowed) -------
__device__ float g_x  [MROWS * DMODEL];
__device__ float g_qkv[MROWS * 3 * DMODEL];
__device__ float g_att[MROWS * DMODEL];
__device__ float g_fc [MROWS * 4 * DMODEL];
__device__ float g_mu [MROWS];
__device__ float g_rs [MROWS];

// ---------------- embedding ----------------
__global__ void embed_kernel(const float* __restrict__ wte,
                             const float* __restrict__ wpe,
                             const int*   __restrict__ idx,
                             float* __restrict__ x) {
    int m = blockIdx.x;
    int t = m % TLEN;
    int tok = idx[m];
    const float* we = wte + (size_t)tok * DMODEL;
    const float* pe = wpe + (size_t)t * DMODEL;
    float* xr = x + (size_t)m * DMODEL;
    for (int d = threadIdx.x; d < DMODEL; d += blockDim.x)
        xr[d] = we[d] + pe[d];
}

// ---------------- LN stats: one warp per row, two-pass in registers ----------
__global__ __launch_bounds__(256)
void ln_stats_kernel(const float* __restrict__ x,
                     float* __restrict__ mu, float* __restrict__ rs) {
    int row  = blockIdx.x * 8 + (threadIdx.x >> 5);
    int lane = threadIdx.x & 31;
    const float* xr = x + (size_t)row * DMODEL;
    float v[16];
    float s = 0.f;
    #pragma unroll
    for (int i = 0; i < 16; i++) { v[i] = xr[lane + i * 32]; s += v[i]; }
    #pragma unroll
    for (int o = 16; o; o >>= 1) s += __shfl_xor_sync(0xffffffffu, s, o);
    float m = s * (1.f / DMODEL);
    float s2 = 0.f;
    #pragma unroll
    for (int i = 0; i < 16; i++) { float d = v[i] - m; s2 += d * d; }
    #pragma unroll
    for (int o = 16; o; o >>= 1) s2 += __shfl_xor_sync(0xffffffffu, s2, o);
    if (lane == 0) {
        mu[row] = m;
        rs[row] = rsqrtf(s2 * (1.f / DMODEL) + EPS);
    }
}

// ---------------- tf32 helpers ----------------------------------------------
__device__ __forceinline__ uint32_t f2tf32(float v) {
    uint32_t r;
    asm("cvt.rna.tf32.f32 %0, %1;" : "=r"(r) : "f"(v));
    return r;
}

__device__ __forceinline__ void mma_tf32(float* d, const uint32_t* a, const uint32_t* b) {
    asm volatile(
        "mma.sync.aligned.m16n8k8.row.col.f32.tf32.tf32.f32 "
        "{%0,%1,%2,%3},{%4,%5,%6,%7},{%8,%9},{%0,%1,%2,%3};\n"
        : "+f"(d[0]), "+f"(d[1]), "+f"(d[2]), "+f"(d[3])
        : "r"(a[0]), "r"(a[1]), "r"(a[2]), "r"(a[3]), "r"(b[0]), "r"(b[1]));
}

// ---------------- pipelined tf32 tensor-core GEMM ----------------------------
// C[M,N] = A'[M,K] @ B (+bias) (+resid) (opt gelu), where A' = A or
// (LNF) layernorm(A) applied on the fly via precomputed mu/rs + w/b.
// Double-buffered smem; one __syncthreads per k-iter.
#define AP 20
#define BP 136
template<bool BTRANS, bool LNF>
__global__ __launch_bounds__(256)
void gemm_tf32(const float* __restrict__ A, const float* __restrict__ Bm,
               const float* __restrict__ bias, const float* __restrict__ resid,
               float* __restrict__ Cm, int M, int N, int K, int gelu_flag,
               const float* __restrict__ ln_mu, const float* __restrict__ ln_rs,
               const float* __restrict__ lnw,  const float* __restrict__ lnb) {
    __shared__ uint32_t As[2][128 * AP];
    __shared__ uint32_t Bs[2][16 * BP];

    int tid  = threadIdx.x;
    int lane = tid & 31;
    int w    = tid >> 5;
    int g    = lane >> 2;
    int tig  = lane & 3;
    int wm   = (w >> 2) * 64;
    int wn   = (w & 3) * 32;
    int m0 = (BTRANS ? blockIdx.x : blockIdx.y) * 128;
    int n0 = (BTRANS ? blockIdx.y : blockIdx.x) * 128;

    int aR0 = tid >> 2,            aC0 = (tid & 3) * 4;
    int aR1 = (tid + 256) >> 2;    // aC1 == aC0 (256 % 4 == 0)
    int bKr0, bNc0, bKr1, bNc1;
    if (!BTRANS) { bKr0 = tid >> 5; bNc0 = (tid & 31) * 4;
                   bKr1 = (tid + 256) >> 5; bNc1 = bNc0; }
    else         { bKr0 = (tid & 3) * 4; bNc0 = tid >> 2;
                   bKr1 = bKr0; bNc1 = (tid + 256) >> 2; }

    float muA0 = 0.f, rsA0 = 1.f, muA1 = 0.f, rsA1 = 1.f;
    if (LNF) {
        muA0 = ln_mu[m0 + aR0]; rsA0 = ln_rs[m0 + aR0];
        muA1 = ln_mu[m0 + aR1]; rsA1 = ln_rs[m0 + aR1];
    }

    float4 arg0, arg1, brg0, brg1, w4, b4;

    auto load_tile = [&](int k0) {
        arg0 = *(const float4*)&A[(size_t)(m0 + aR0) * K + k0 + aC0];
        arg1 = *(const float4*)&A[(size_t)(m0 + aR1) * K + k0 + aC0];
        if (LNF) {
            w4 = *(const float4*)&lnw[k0 + aC0];
            b4 = *(const float4*)&lnb[k0 + aC0];
        }
        if (!BTRANS) {
            brg0 = *(const float4*)&Bm[(size_t)(k0 + bKr0) * N + n0 + bNc0];
            brg1 = *(const float4*)&Bm[(size_t)(k0 + bKr1) * N + n0 + bNc1];
        } else {
            brg0 = *(const float4*)&Bm[(size_t)(n0 + bNc0) * K + k0 + bKr0];
            brg1 = *(const float4*)&Bm[(size_t)(n0 + bNc1) * K + k0 + bKr1];
        }
    };
    auto store_tile = [&](int buf) {
        float4 a0 = arg0, a1 = arg1;
        if (LNF) {
            a0.x = (a0.x - muA0) * rsA0 * w4.x + b4.x;
            a0.y = (a0.y - muA0) * rsA0 * w4.y + b4.y;
            a0.z = (a0.z - muA0) * rsA0 * w4.z + b4.z;
            a0.w = (a0.w - muA0) * rsA0 * w4.w + b4.w;
            a1.x = (a1.x - muA1) * rsA1 * w4.x + b4.x;
            a1.y = (a1.y - muA1) * rsA1 * w4.y + b4.y;
            a1.z = (a1.z - muA1) * rsA1 * w4.z + b4.z;
            a1.w = (a1.w - muA1) * rsA1 * w4.w + b4.w;
        }
        uint32_t* ap = &As[buf][aR0 * AP + aC0];
        ap[0] = f2tf32(a0.x); ap[1] = f2tf32(a0.y);
        ap[2] = f2tf32(a0.z); ap[3] = f2tf32(a0.w);
        ap = &As[buf][aR1 * AP + aC0];
        ap[0] = f2tf32(a1.x); ap[1] = f2tf32(a1.y);
        ap[2] = f2tf32(a1.z); ap[3] = f2tf32(a1.w);
        if (!BTRANS) {
            uint32_t* bp = &Bs[buf][bKr0 * BP + bNc0];
            bp[0] = f2tf32(brg0.x); bp[1] = f2tf32(brg0.y);
            bp[2] = f2tf32(brg0.z); bp[3] = f2tf32(brg0.w);
            bp = &Bs[buf][bKr1 * BP + bNc1];
            bp[0] = f2tf32(brg1.x); bp[1] = f2tf32(brg1.y);
            bp[2] = f2tf32(brg1.z); bp[3] = f2tf32(brg1.w);
        } else {
            Bs[buf][(bKr0 + 0) * BP + bNc0] = f2tf32(brg0.x);
            Bs[buf][(bKr0 + 1) * BP + bNc0] = f2tf32(brg0.y);
            Bs[buf][(bKr0 + 2) * BP + bNc0] = f2tf32(brg0.z);
            Bs[buf][(bKr0 + 3) * BP + bNc0] = f2tf32(brg0.w);
            Bs[buf][(bKr1 + 0) * BP + bNc1] = f2tf32(brg1.x);
            Bs[buf][(bKr1 + 1) * BP + bNc1] = f2tf32(brg1.y);
            Bs[buf][(bKr1 + 2) * BP + bNc1] = f2tf32(brg1.z);
            Bs[buf][(bKr1 + 3) * BP + bNc1] = f2tf32(brg1.w);
        }
    };

    float d[4][4][4];
    #pragma unroll
    for (int i = 0; i < 4; i++)
        #pragma unroll
        for (int j = 0; j < 4; j++)
            #pragma unroll
            for (int r = 0; r < 4; r++) d[i][j][r] = 0.f;

    load_tile(0);
    store_tile(0);
    __syncthreads();

    int buf = 0;
    for (int k0 = 0; k0 < K; k0 += 16) {
        int nk = k0 + 16;
        if (nk < K) load_tile(nk);

        const uint32_t* Ac = As[buf];
        const uint32_t* Bc = Bs[buf];
        #pragma unroll
        for (int kk = 0; kk < 16; kk += 8) {
            uint32_t af[4][4];
            #pragma unroll
            for (int mi = 0; mi < 4; mi++) {
                int rb = wm + mi * 16;
                af[mi][0] = Ac[(rb + g    ) * AP + kk + tig    ];
                af[mi][1] = Ac[(rb + g + 8) * AP + kk + tig    ];
                af[mi][2] = Ac[(rb + g    ) * AP + kk + tig + 4];
                af[mi][3] = Ac[(rb + g + 8) * AP + kk + tig + 4];
            }
            uint32_t bf[4][2];
            #pragma unroll
            for (int nj = 0; nj < 4; nj++) {
                int cb = wn + nj * 8;
                bf[nj][0] = Bc[(kk + tig    ) * BP + cb + g];
                bf[nj][1] = Bc[(kk + tig + 4) * BP + cb + g];
            }
            #pragma unroll
            for (int mi = 0; mi < 4; mi++)
                #pragma unroll
                for (int nj = 0; nj < 4; nj++)
                    mma_tf32(d[mi][nj], af[mi], bf[nj]);
        }

        if (nk < K) store_tile(buf ^ 1);
        __syncthreads();
        buf ^= 1;
    }

    #pragma unroll
    for (int mi = 0; mi < 4; mi++) {
        #pragma unroll
        for (int rr = 0; rr < 2; rr++) {
            int m = m0 + wm + mi * 16 + g + rr * 8;
            float* crow = Cm + (size_t)m * N;
            const float* rrow = resid ? resid + (size_t)m * N : nullptr;
            #pragma unroll
            for (int nj = 0; nj < 4; nj++) {
                int n = n0 + wn + nj * 8 + tig * 2;
                #pragma unroll
                for (int cc = 0; cc < 2; cc++) {
                    float c = d[mi][nj][rr * 2 + cc];
                    if (bias) c += bias[n + cc];
                    if (rrow) c += rrow[n + cc];
                    if (gelu_flag)
                        c = 0.5f * c * (1.f + erff(c * 0.70710678118654752f));
                    crow[n + cc] = c;
                }
            }
        }
    }
}

// ---------------- tensor-core causal flash attention -------------------------
// Round-4 structure (64 q-rows, 128 threads, 4 warps), with all smem fills
// vectorized: Kh/Kl/Vt/Qh/Ql rows written as STS.128, Ps as STS.64.
// Split-tf32 QK^T, tf32 PV, register softmax. Ps aliases Kl.
#define AT_P 72
#define ATTN_SMEM_TC (5 * 64 * AT_P * (int)sizeof(uint32_t))

__global__ __launch_bounds__(128)
void attn_tc_kernel(const float* __restrict__ qkv, float* __restrict__ out) {
    extern __shared__ uint32_t smu[];
    uint32_t* Qh = smu;
    uint32_t* Ql = Qh + 64 * AT_P;
    uint32_t* Kh = Ql + 64 * AT_P;
    uint32_t* Kl = Kh + 64 * AT_P;
    uint32_t* Vt = Kl + 64 * AT_P;
    uint32_t* Ps = Kl;                      // alias: Kl dead after QK^T

    int tid  = threadIdx.x;
    int lane = tid & 31;
    int wid  = tid >> 5;
    int g    = lane >> 2;
    int tig  = lane & 3;
    int b = blockIdx.y >> 3, h = blockIdx.y & 7;
    int q0 = blockIdx.x * 64;
    const int RS = 3 * DMODEL;
    const float* qbase = qkv + (size_t)b * TLEN * RS + h * HDIM;
    const float* kbase = qbase + DMODEL;
    const float* vbase = qbase + 2 * DMODEL;

    // Q tile: scale + split hi/lo, STS.128 rows
    for (int i = tid; i < 64 * 16; i += 128) {
        int r = i >> 4, d4 = (i & 15) * 4;
        float4 v = *(const float4*)&qbase[(size_t)(q0 + r) * RS + d4];
        float q4[4] = {v.x, v.y, v.z, v.w};
        uint4 uh, ul;
        uint32_t* ph = (uint32_t*)&uh;
        uint32_t* pl = (uint32_t*)&ul;
        #pragma unroll
        for (int c = 0; c < 4; c++) {
            float qs = q4[c] * 0.125f;
            uint32_t hi = f2tf32(qs);
            ph[c] = hi;
            pl[c] = f2tf32(qs - __uint_as_float(hi));
        }
        *(uint4*)&Qh[r * AT_P + d4] = uh;
        *(uint4*)&Ql[r * AT_P + d4] = ul;
    }

    float o[8][4];
    #pragma unroll
    for (int nj = 0; nj < 8; nj++)
        #pragma unroll
        for (int c = 0; c < 4; c++) o[nj][c] = 0.f;
    float m0 = -1e30f, m1 = -1e30f, l0 = 0.f, l1 = 0.f;
    int wrow = wid * 16;
    int rowA = wrow + g, rowB = wrow + g + 8;

    for (int j0 = 0; j0 <= q0; j0 += 64) {
        __syncthreads();   // prev iter's PV reads (Ps=Kl, Vt) done before refill
        for (int i = tid; i < 64 * 16; i += 128) {
            int r = i >> 4, d4 = (i & 15) * 4;
            float4 kv = *(const float4*)&kbase[(size_t)(j0 + r) * RS + d4];
            float4 vv = *(const float4*)&vbase[(size_t)(j0 + r) * RS + d4];
            float k4[4] = {kv.x, kv.y, kv.z, kv.w};
            float v4[4] = {vv.x, vv.y, vv.z, vv.w};
            uint4 uh, ul, uv;
            uint32_t* ph = (uint32_t*)&uh;
            uint32_t* pl = (uint32_t*)&ul;
            uint32_t* pv = (uint32_t*)&uv;
            #pragma unroll
            for (int c = 0; c < 4; c++) {
                uint32_t hi = f2tf32(k4[c]);
                ph[c] = hi;
                pl[c] = f2tf32(k4[c] - __uint_as_float(hi));
                pv[c] = f2tf32(v4[c]);
            }
            *(uint4*)&Kh[r * AT_P + d4] = uh;
            *(uint4*)&Kl[r * AT_P + d4] = ul;
            *(uint4*)&Vt[r * AT_P + d4] = uv;
        }
        __syncthreads();

        // ---- S = Q K^T (split-tf32) ----
        float s[8][4];
        #pragma unroll
        for (int nj = 0; nj < 8; nj++)
            #pragma unroll
            for (int c = 0; c < 4; c++) s[nj][c] = 0.f;

        #pragma unroll
        for (int k8 = 0; k8 < 64; k8 += 8) {
            uint32_t ah[4], al[4];
            ah[0] = Qh[rowA * AT_P + k8 + tig];
            ah[1] = Qh[rowB * AT_P + k8 + tig];
            ah[2] = Qh[rowA * AT_P + k8 + tig + 4];
            ah[3] = Qh[rowB * AT_P + k8 + tig + 4];
            al[0] = Ql[rowA * AT_P + k8 + tig];
            al[1] = Ql[rowB * AT_P + k8 + tig];
            al[2] = Ql[rowA * AT_P + k8 + tig + 4];
            al[3] = Ql[rowB * AT_P + k8 + tig + 4];
            #pragma unroll
            for (int nj = 0; nj < 8; nj++) {
                int kr = nj * 8 + g;
                uint32_t bh2[2] = {Kh[kr * AT_P + k8 + tig], Kh[kr * AT_P + k8 + tig + 4]};
                uint32_t bl2[2] = {Kl[kr * AT_P + k8 + tig], Kl[kr * AT_P + k8 + tig + 4]};
                mma_tf32(s[nj], ah, bh2);
                mma_tf32(s[nj], al, bh2);
                mma_tf32(s[nj], ah, bl2);
            }
        }

        if (j0 == q0) {
            #pragma unroll
            for (int nj = 0; nj < 8; nj++) {
                int k0c = nj * 8 + 2 * tig;
                if (k0c     > rowA) s[nj][0] = -1e30f;
                if (k0c + 1 > rowA) s[nj][1] = -1e30f;
                if (k0c     > rowB) s[nj][2] = -1e30f;
                if (k0c + 1 > rowB) s[nj][3] = -1e30f;
            }
        }

        // ---- online softmax in registers ----
        float mx0 = m0, mx1 = m1;
        #pragma unroll
        for (int nj = 0; nj < 8; nj++) {
            mx0 = fmaxf(mx0, fmaxf(s[nj][0], s[nj][1]));
            mx1 = fmaxf(mx1, fmaxf(s[nj][2], s[nj][3]));
        }
        mx0 = fmaxf(mx0, __shfl_xor_sync(0xffffffffu, mx0, 1));
        mx0 = fmaxf(mx0, __shfl_xor_sync(0xffffffffu, mx0, 2));
        mx1 = fmaxf(mx1, __shfl_xor_sync(0xffffffffu, mx1, 1));
        mx1 = fmaxf(mx1, __shfl_xor_sync(0xffffffffu, mx1, 2));

        float fac0 = __expf(m0 - mx0), fac1 = __expf(m1 - mx1);
        float sum0 = 0.f, sum1 = 0.f;
        #pragma unroll
        for (int nj = 0; nj < 8; nj++) {
            s[nj][0] = __expf(s[nj][0] - mx0);
            s[nj][1] = __expf(s[nj][1] - mx0);
            s[nj][2] = __expf(s[nj][2] - mx1);
            s[nj][3] = __expf(s[nj][3] - mx1);
            sum0 += s[nj][0] + s[nj][1];
            sum1 += s[nj][2] + s[nj][3];
        }
        sum0 += __shfl_xor_sync(0xffffffffu, sum0, 1);
        sum0 += __shfl_xor_sync(0xffffffffu, sum0, 2);
        sum1 += __shfl_xor_sync(0xffffffffu, sum1, 1);
        sum1 += __shfl_xor_sync(0xffffffffu, sum1, 2);
        l0 = l0 * fac0 + sum0;
        l1 = l1 * fac1 + sum1;
        m0 = mx0; m1 = mx1;
        #pragma unroll
        for (int nj = 0; nj < 8; nj++) {
            o[nj][0] *= fac0; o[nj][1] *= fac0;
            o[nj][2] *= fac1; o[nj][3] *= fac1;
        }

        __syncthreads();   // all warps' QK^T reads of Kl done before Ps writes
        #pragma unroll
        for (int nj = 0; nj < 8; nj++) {
            int cc = nj * 8 + 2 * tig;
            uint2 pa = {f2tf32(s[nj][0]), f2tf32(s[nj][1])};
            uint2 pb = {f2tf32(s[nj][2]), f2tf32(s[nj][3])};
            *(uint2*)&Ps[rowA * AT_P + cc] = pa;
            *(uint2*)&Ps[rowB * AT_P + cc] = pb;
        }
        __syncwarp();      // Ps rows are warp-private

        // ---- O += P V (single tf32) ----
        #pragma unroll
        for (int k8 = 0; k8 < 64; k8 += 8) {
            uint32_t a[4];
            a[0] = Ps[rowA * AT_P + k8 + tig];
            a[1] = Ps[rowB * AT_P + k8 + tig];
            a[2] = Ps[rowA * AT_P + k8 + tig + 4];
            a[3] = Ps[rowB * AT_P + k8 + tig + 4];
            #pragma unroll
            for (int nj = 0; nj < 8; nj++) {
                uint32_t bv[2] = {Vt[(k8 + tig) * AT_P + nj * 8 + g],
                                  Vt[(k8 + tig + 4) * AT_P + nj * 8 + g]};
                mma_tf32(o[nj], a, bv);
            }
        }
    }

    float inv0 = 1.f / l0, inv1 = 1.f / l1;
    size_t rA = (size_t)(b * TLEN + q0 + rowA) * DMODEL + h * HDIM;
    size_t rB = (size_t)(b * TLEN + q0 + rowB) * DMODEL + h * HDIM;
    #pragma unroll
    for (int nj = 0; nj < 8; nj++) {
        int cc = nj * 8 + 2 * tig;
        out[rA + cc]     = o[nj][0] * inv0;
        out[rA + cc + 1] = o[nj][1] * inv0;
        out[rB + cc]     = o[nj][2] * inv1;
        out[rB + cc + 1] = o[nj][3] * inv1;
    }
}

// ---------------- driver ----------------------------------------------------
extern "C" void kernel_launch(void* const* d_in, const int* in_sizes, int n_in,
                              void* d_out, int out_size) {
    const float* wte    = (const float*)d_in[0];
    const float* wpe    = (const float*)d_in[1];
    const float* ln1_w  = (const float*)d_in[2];
    const float* ln1_b  = (const float*)d_in[3];
    const float* attn_w = (const float*)d_in[4];
    const float* attn_b = (const float*)d_in[5];
    const float* proj_w = (const float*)d_in[6];
    const float* proj_b = (const float*)d_in[7];
    const float* ln2_w  = (const float*)d_in[8];
    const float* ln2_b  = (const float*)d_in[9];
    const float* fc_w   = (const float*)d_in[10];
    const float* fc_b   = (const float*)d_in[11];
    const float* fc2_w  = (const float*)d_in[12];
    const float* fc2_b  = (const float*)d_in[13];
    const float* lnf_w  = (const float*)d_in[14];
    const float* lnf_b  = (const float*)d_in[15];
    const int*   idx    = (const int*)d_in[16];
    float* out = (float*)d_out;

    void *px, *pqkv, *patt, *pfc, *pmu, *prs;
    cudaGetSymbolAddress(&px, g_x);
    cudaGetSymbolAddress(&pqkv, g_qkv);
    cudaGetSymbolAddress(&patt, g_att);
    cudaGetSymbolAddress(&pfc, g_fc);
    cudaGetSymbolAddress(&pmu, g_mu);
    cudaGetSymbolAddress(&prs, g_rs);
    float* x   = (float*)px;
    float* qkv = (float*)pqkv;
    float* att = (float*)patt;
    float* fcb = (float*)pfc;
    float* mu  = (float*)pmu;
    float* rs  = (float*)prs;

    cudaFuncSetAttribute(attn_tc_kernel,
                         cudaFuncAttributeMaxDynamicSharedMemorySize, ATTN_SMEM_TC);

    embed_kernel<<<MROWS, 256>>>(wte, wpe, idx, x);

    for (int l = 0; l < NLAYER; l++) {
        const float* aw  = attn_w + (size_t)l * DMODEL * 3 * DMODEL;
        const float* ab  = attn_b + (size_t)l * 3 * DMODEL;
        const float* pw  = proj_w + (size_t)l * DMODEL * DMODEL;
        const float* pb  = proj_b + (size_t)l * DMODEL;
        const float* fw  = fc_w   + (size_t)l * DMODEL * 4 * DMODEL;
        const float* fb  = fc_b   + (size_t)l * 4 * DMODEL;
        const float* f2w = fc2_w  + (size_t)l * 4 * DMODEL * DMODEL;
        const float* f2b = fc2_b  + (size_t)l * DMODEL;

        // qkv = LN1(x) @ attn_w + attn_b  (LN fused into A-load)
        ln_stats_kernel<<<MROWS / 8, 256>>>(x, mu, rs);
        gemm_tf32<false, true><<<dim3(3 * DMODEL / 128, MROWS / 128), 256>>>(
            x, aw, ab, nullptr, qkv, MROWS, 3 * DMODEL, DMODEL, 0,
            mu, rs, ln1_w + l * DMODEL, ln1_b + l * DMODEL);
        attn_tc_kernel<<<dim3(TLEN / 64, BATCH * NHEAD), 128, ATTN_SMEM_TC>>>(qkv, att);
        gemm_tf32<false, false><<<dim3(DMODEL / 128, MROWS / 128), 256>>>(
            att, pw, pb, x, x, MROWS, DMODEL, DMODEL, 0,
            nullptr, nullptr, nullptr, nullptr);
        // fcb = gelu(LN2(x) @ fc_w + fc_b)
        ln_stats_kernel<<<MROWS / 8, 256>>>(x, mu, rs);
        gemm_tf32<false, true><<<dim3(4 * DMODEL / 128, MROWS / 128), 256>>>(
            x, fw, fb, nullptr, fcb, MROWS, 4 * DMODEL, DMODEL, 1,
            mu, rs, ln2_w + l * DMODEL, ln2_b + l * DMODEL);
        gemm_tf32<false, false><<<dim3(DMODEL / 128, MROWS / 128), 256>>>(
            fcb, f2w, f2b, x, x, MROWS, DMODEL, 4 * DMODEL, 0,
            nullptr, nullptr, nullptr, nullptr);
    }

    // out = LNf(x) @ wte^T  (LN fused; grid swapped for wte L2 reuse)
    ln_stats_kernel<<<MROWS / 8, 256>>>(x, mu, rs);
    gemm_tf32<true, true><<<dim3(MROWS / 128, VOCAB / 128), 256>>>(
        x, wte, nullptr, nullptr, out, MROWS, VOCAB, DMODEL, 0,
        mu, rs, lnf_w, lnf_b);
}

// round 9
// speedup vs baseline: 1.6101x; 1.0080x over previous
#include <cuda_runtime.h>
#include <math.h>
#include <stdint.h>

// ---------------- problem constants ----------------
#define NLAYER 4
#define NHEAD  8
#define DMODEL 512
#define TLEN   2048
#define BATCH  2
#define VOCAB  32000
#define HDIM   64
#define MROWS  (BATCH * TLEN)   // 4096
#define EPS    1e-5f

// ---------------- scratch (static device globals; no allocs allowed) -------
__device__ float g_x  [MROWS * DMODEL];
__device__ float g_h  [MROWS * DMODEL];
__device__ float g_qkv[MROWS * 3 * DMODEL];
__device__ float g_att[MROWS * DMODEL];
__device__ float g_fc [MROWS * 4 * DMODEL];

// ---------------- embedding ----------------
__global__ void embed_kernel(const float* __restrict__ wte,
                             const float* __restrict__ wpe,
                             const int*   __restrict__ idx,
                             float* __restrict__ x) {
    int m = blockIdx.x;
    int t = m % TLEN;
    int tok = idx[m];
    const float* we = wte + (size_t)tok * DMODEL;
    const float* pe = wpe + (size_t)t * DMODEL;
    float* xr = x + (size_t)m * DMODEL;
    for (int d = threadIdx.x; d < DMODEL; d += blockDim.x)
        xr[d] = we[d] + pe[d];
}

// ---------------- layernorm (round-4 proven) ----------------
__global__ __launch_bounds__(256)
void ln_kernel(const float* __restrict__ x, const float* __restrict__ w,
               const float* __restrict__ b, float* __restrict__ y) {
    int row = blockIdx.x;
    int tid = threadIdx.x;
    const float* xr = x + (size_t)row * DMODEL;
    float v0 = xr[tid];
    float v1 = xr[tid + 256];

    __shared__ float red[8];
    __shared__ float bc;

    float s = v0 + v1;
    #pragma unroll
    for (int o = 16; o; o >>= 1) s += __shfl_xor_sync(0xffffffffu, s, o);
    if ((tid & 31) == 0) red[tid >> 5] = s;
    __syncthreads();
    if (tid == 0) {
        float t = 0.f;
        #pragma unroll
        for (int i = 0; i < 8; i++) t += red[i];
        bc = t;
    }
    __syncthreads();
    float mu = bc * (1.f / DMODEL);
    float d0 = v0 - mu, d1 = v1 - mu;

    float s2 = d0 * d0 + d1 * d1;
    #pragma unroll
    for (int o = 16; o; o >>= 1) s2 += __shfl_xor_sync(0xffffffffu, s2, o);
    __syncthreads();
    if ((tid & 31) == 0) red[tid >> 5] = s2;
    __syncthreads();
    if (tid == 0) {
        float t = 0.f;
        #pragma unroll
        for (int i = 0; i < 8; i++) t += red[i];
        bc = t;
    }
    __syncthreads();
    float inv = rsqrtf(bc * (1.f / DMODEL) + EPS);

    float* yr = y + (size_t)row * DMODEL;
    yr[tid]       = d0 * inv * w[tid]       + b[tid];
    yr[tid + 256] = d1 * inv * w[tid + 256] + b[tid + 256];
}

// ---------------- tf32 helpers ----------------------------------------------
__device__ __forceinline__ uint32_t f2tf32(float v) {
    uint32_t r;
    asm("cvt.rna.tf32.f32 %0, %1;" : "=r"(r) : "f"(v));
    return r;
}

__device__ __forceinline__ void mma_tf32(float* d, const uint32_t* a, const uint32_t* b) {
    asm volatile(
        "mma.sync.aligned.m16n8k8.row.col.f32.tf32.tf32.f32 "
        "{%0,%1,%2,%3},{%4,%5,%6,%7},{%8,%9},{%0,%1,%2,%3};\n"
        : "+f"(d[0]), "+f"(d[1]), "+f"(d[2]), "+f"(d[3])
        : "r"(a[0]), "r"(a[1]), "r"(a[2]), "r"(a[3]), "r"(b[0]), "r"(b[1]));
}

// ---------------- pipelined tf32 tensor-core GEMM ----------------------------
// C[M,N] = A[M,K] @ B (+bias) (+resid) (opt gelu).
// Double-buffered smem in MMA-FRAGMENT ORDER:
//   A word: (kb*8+m16)*128 + (lane^(3*kb))*4 + cslot       (cslot=half+2*khalf)
//     -> a-fragment = ONE LDS.128, conflict-free.
//   B word: (kb*16+n8)*64 + ((g*4+tig)^(n8&15))*2 + khalf
//     -> b-fragment pair = ONE LDS.64, conflict-free phases.
// Mainloop frag loads: 48 LDS.32 -> 8 LDS.128 + 8 LDS.64 per warp per k16.
#define ASZ 2048
#define BSZ 2048
template<bool BTRANS>
__global__ __launch_bounds__(256)
void gemm_tf32(const float* __restrict__ A, const float* __restrict__ Bm,
               const float* __restrict__ bias, const float* __restrict__ resid,
               float* __restrict__ Cm, int M, int N, int K, int gelu_flag) {
    __shared__ uint32_t As[2][ASZ];
    __shared__ uint32_t Bs[2][BSZ];

    int tid  = threadIdx.x;
    int lane = tid & 31;
    int w    = tid >> 5;
    int g    = lane >> 2;
    int tig  = lane & 3;
    int wm   = (w >> 2) * 64;
    int wn   = (w & 3) * 32;
    int m0 = (BTRANS ? blockIdx.x : blockIdx.y) * 128;
    int n0 = (BTRANS ? blockIdx.y : blockIdx.x) * 128;

    // global-load coordinates (fixed)
    int aR0 = tid >> 2,          aC0 = (tid & 3) * 4;
    int aR1 = aR0 + 64;
    int bKr0, bNc0, bKr1, bNc1;
    if (!BTRANS) { bKr0 = tid >> 5; bNc0 = (tid & 31) * 4;
                   bKr1 = bKr0 + 8; bNc1 = bNc0; }
    else         { bKr0 = (tid & 3) * 4; bNc0 = tid >> 2;
                   bKr1 = bKr0; bNc1 = bNc0 + 64; }

    // ---- precomputed store addresses (word indices) ----
    // A row 0: element (aR0, aC0+c) -> base + c-dependent slot
    int a_kb  = aC0 >> 3, a_kh = (aC0 >> 2) & 1;
    int a_g0  = aR0 & 7,  a_h0 = (aR0 >> 3) & 1, a_m0 = aR0 >> 4;
    int a_g1  = aR1 & 7,  a_h1 = (aR1 >> 3) & 1, a_m1 = aR1 >> 4;
    int a_cs0 = a_h0 + 2 * a_kh, a_cs1 = a_h1 + 2 * a_kh;
    int aSl0  = a_g0 * 4, aSl1 = a_g1 * 4;   // + tig(=c) then ^3*kb
    int aB0   = (a_kb * 8 + a_m0) * 128 + a_cs0;
    int aB1   = (a_kb * 8 + a_m1) * 128 + a_cs1;
    int aX    = 3 * a_kb;

    int bB0, bB1, bSl0, bSl1, bX0, bX1, bStride; // bStride: slot step per element
    if (!BTRANS) {
        int kb0 = bKr0 >> 3, t0 = bKr0 & 3, kh0 = (bKr0 >> 2) & 1;
        int kb1 = bKr1 >> 3, t1 = bKr1 & 3, kh1 = (bKr1 >> 2) & 1;
        int n8 = bNc0 >> 3, g0 = bNc0 & 7;
        bX0 = n8 & 15; bX1 = bX0;
        bSl0 = g0 * 4 + t0; bSl1 = g0 * 4 + t1;
        bB0 = (kb0 * 16 + n8) * 64 + kh0;
        bB1 = (kb1 * 16 + n8) * 64 + kh1;
        bStride = 4;          // element c -> n+c -> g+c -> slot + 4*c
    } else {
        int kb = bKr0 >> 3, kh = (bKr0 >> 2) & 1;
        int n80 = bNc0 >> 3, g0 = bNc0 & 7;
        int n81 = bNc1 >> 3, g1 = bNc1 & 7;
        bX0 = n80 & 15; bX1 = n81 & 15;
        bSl0 = g0 * 4; bSl1 = g1 * 4;
        bB0 = (kb * 16 + n80) * 64 + kh;
        bB1 = (kb * 16 + n81) * 64 + kh;
        bStride = 1;          // element c -> krow+c -> tig+c -> slot + c
    }

    float4 arg0, arg1, brg0, brg1;

    auto load_tile = [&](int k0) {
        arg0 = *(const float4*)&A[(size_t)(m0 + aR0) * K + k0 + aC0];
        arg1 = *(const float4*)&A[(size_t)(m0 + aR1) * K + k0 + aC0];
        if (!BTRANS) {
            brg0 = *(const float4*)&Bm[(size_t)(k0 + bKr0) * N + n0 + bNc0];
            brg1 = *(const float4*)&Bm[(size_t)(k0 + bKr1) * N + n0 + bNc1];
        } else {
            brg0 = *(const float4*)&Bm[(size_t)(n0 + bNc0) * K + k0 + bKr0];
            brg1 = *(const float4*)&Bm[(size_t)(n0 + bNc1) * K + k0 + bKr1];
        }
    };
    auto store_tile = [&](int buf) {
        uint32_t* ab = As[buf];
        ab[aB0 + ((aSl0 + 0) ^ aX) * 4] = f2tf32(arg0.x);
        ab[aB0 + ((aSl0 + 1) ^ aX) * 4] = f2tf32(arg0.y);
        ab[aB0 + ((aSl0 + 2) ^ aX) * 4] = f2tf32(arg0.z);
        ab[aB0 + ((aSl0 + 3) ^ aX) * 4] = f2tf32(arg0.w);
        ab[aB1 + ((aSl1 + 0) ^ aX) * 4] = f2tf32(arg1.x);
        ab[aB1 + ((aSl1 + 1) ^ aX) * 4] = f2tf32(arg1.y);
        ab[aB1 + ((aSl1 + 2) ^ aX) * 4] = f2tf32(arg1.z);
        ab[aB1 + ((aSl1 + 3) ^ aX) * 4] = f2tf32(arg1.w);
        uint32_t* bb = Bs[buf];
        bb[bB0 + ((bSl0 + 0 * bStride) ^ bX0) * 2] = f2tf32(brg0.x);
        bb[bB0 + ((bSl0 + 1 * bStride) ^ bX0) * 2] = f2tf32(brg0.y);
        bb[bB0 + ((bSl0 + 2 * bStride) ^ bX0) * 2] = f2tf32(brg0.z);
        bb[bB0 + ((bSl0 + 3 * bStride) ^ bX0) * 2] = f2tf32(brg0.w);
        bb[bB1 + ((bSl1 + 0 * bStride) ^ bX1) * 2] = f2tf32(brg1.x);
        bb[bB1 + ((bSl1 + 1 * bStride) ^ bX1) * 2] = f2tf32(brg1.y);
        bb[bB1 + ((bSl1 + 2 * bStride) ^ bX1) * 2] = f2tf32(brg1.z);
        bb[bB1 + ((bSl1 + 3 * bStride) ^ bX1) * 2] = f2tf32(brg1.w);
    };

    float d[4][4][4];
    #pragma unroll
    for (int i = 0; i < 4; i++)
        #pragma unroll
        for (int j = 0; j < 4; j++)
            #pragma unroll
            for (int r = 0; r < 4; r++) d[i][j][r] = 0.f;

    load_tile(0);
    store_tile(0);
    __syncthreads();

    int buf = 0;
    for (int k0 = 0; k0 < K; k0 += 16) {
        int nk = k0 + 16;
        if (nk < K) load_tile(nk);

        const uint32_t* Ac = As[buf];
        const uint32_t* Bc = Bs[buf];
        #pragma unroll
        for (int kb = 0; kb < 2; kb++) {
            uint32_t af[4][4];
            #pragma unroll
            for (int mi = 0; mi < 4; mi++) {
                int m16 = (w >> 2) * 4 + mi;
                uint4 av = *(const uint4*)&Ac[(kb * 8 + m16) * 128 + (lane ^ (3 * kb)) * 4];
                af[mi][0] = av.x; af[mi][1] = av.y;
                af[mi][2] = av.z; af[mi][3] = av.w;
            }
            uint32_t bf[4][2];
            #pragma unroll
            for (int nj = 0; nj < 4; nj++) {
                int n8 = (w & 3) * 4 + nj;
                uint2 bv = *(const uint2*)&Bc[(kb * 16 + n8) * 64 + (lane ^ (n8 & 15)) * 2];
                bf[nj][0] = bv.x; bf[nj][1] = bv.y;
            }
            #pragma unroll
            for (int mi = 0; mi < 4; mi++)
                #pragma unroll
                for (int nj = 0; nj < 4; nj++)
                    mma_tf32(d[mi][nj], af[mi], bf[nj]);
        }

        if (nk < K) store_tile(buf ^ 1);
        __syncthreads();
        buf ^= 1;
    }

    #pragma unroll
    for (int mi = 0; mi < 4; mi++) {
        #pragma unroll
        for (int rr = 0; rr < 2; rr++) {
            int m = m0 + wm + mi * 16 + g + rr * 8;
            float* crow = Cm + (size_t)m * N;
            const float* rrow = resid ? resid + (size_t)m * N : nullptr;
            #pragma unroll
            for (int nj = 0; nj < 4; nj++) {
                int n = n0 + wn + nj * 8 + tig * 2;
                #pragma unroll
                for (int cc = 0; cc < 2; cc++) {
                    float c = d[mi][nj][rr * 2 + cc];
                    if (bias) c += bias[n + cc];
                    if (rrow) c += rrow[n + cc];
                    if (gelu_flag)
                        c = 0.5f * c * (1.f + erff(c * 0.70710678118654752f));
                    crow[n + cc] = c;
                }
            }
        }
    }
}

// ---------------- tensor-core causal flash attention (round-8 proven) --------
#define AT_P 72
#define ATTN_SMEM_TC (5 * 64 * AT_P * (int)sizeof(uint32_t))

__global__ __launch_bounds__(128)
void attn_tc_kernel(const float* __restrict__ qkv, float* __restrict__ out) {
    extern __shared__ uint32_t smu[];
    uint32_t* Qh = smu;
    uint32_t* Ql = Qh + 64 * AT_P;
    uint32_t* Kh = Ql + 64 * AT_P;
    uint32_t* Kl = Kh + 64 * AT_P;
    uint32_t* Vt = Kl + 64 * AT_P;
    uint32_t* Ps = Kl;                      // alias: Kl dead after QK^T

    int tid  = threadIdx.x;
    int lane = tid & 31;
    int wid  = tid >> 5;
    int g    = lane >> 2;
    int tig  = lane & 3;
    int b = blockIdx.y >> 3, h = blockIdx.y & 7;
    int q0 = blockIdx.x * 64;
    const int RS = 3 * DMODEL;
    const float* qbase = qkv + (size_t)b * TLEN * RS + h * HDIM;
    const float* kbase = qbase + DMODEL;
    const float* vbase = qbase + 2 * DMODEL;

    for (int i = tid; i < 64 * 16; i += 128) {
        int r = i >> 4, d4 = (i & 15) * 4;
        float4 v = *(const float4*)&qbase[(size_t)(q0 + r) * RS + d4];
        float q4[4] = {v.x, v.y, v.z, v.w};
        uint4 uh, ul;
        uint32_t* ph = (uint32_t*)&uh;
        uint32_t* pl = (uint32_t*)&ul;
        #pragma unroll
        for (int c = 0; c < 4; c++) {
            float qs = q4[c] * 0.125f;
            uint32_t hi = f2tf32(qs);
            ph[c] = hi;
            pl[c] = f2tf32(qs - __uint_as_float(hi));
        }
        *(uint4*)&Qh[r * AT_P + d4] = uh;
        *(uint4*)&Ql[r * AT_P + d4] = ul;
    }

    float o[8][4];
    #pragma unroll
    for (int nj = 0; nj < 8; nj++)
        #pragma unroll
        for (int c = 0; c < 4; c++) o[nj][c] = 0.f;
    float m0 = -1e30f, m1 = -1e30f, l0 = 0.f, l1 = 0.f;
    int wrow = wid * 16;
    int rowA = wrow + g, rowB = wrow + g + 8;

    for (int j0 = 0; j0 <= q0; j0 += 64) {
        __syncthreads();
        for (int i = tid; i < 64 * 16; i += 128) {
            int r = i >> 4, d4 = (i & 15) * 4;
            float4 kv = *(const float4*)&kbase[(size_t)(j0 + r) * RS + d4];
            float4 vv = *(const float4*)&vbase[(size_t)(j0 + r) * RS + d4];
            float k4[4] = {kv.x, kv.y, kv.z, kv.w};
            float v4[4] = {vv.x, vv.y, vv.z, vv.w};
            uint4 uh, ul, uv;
            uint32_t* ph = (uint32_t*)&uh;
            uint32_t* pl = (uint32_t*)&ul;
            uint32_t* pv = (uint32_t*)&uv;
            #pragma unroll
            for (int c = 0; c < 4; c++) {
                uint32_t hi = f2tf32(k4[c]);
                ph[c] = hi;
                pl[c] = f2tf32(k4[c] - __uint_as_float(hi));
                pv[c] = f2tf32(v4[c]);
            }
            *(uint4*)&Kh[r * AT_P + d4] = uh;
            *(uint4*)&Kl[r * AT_P + d4] = ul;
            *(uint4*)&Vt[r * AT_P + d4] = uv;
        }
        __syncthreads();

        float s[8][4];
        #pragma unroll
        for (int nj = 0; nj < 8; nj++)
            #pragma unroll
            for (int c = 0; c < 4; c++) s[nj][c] = 0.f;

        #pragma unroll
        for (int k8 = 0; k8 < 64; k8 += 8) {
            uint32_t ah[4], al[4];
            ah[0] = Qh[rowA * AT_P + k8 + tig];
            ah[1] = Qh[rowB * AT_P + k8 + tig];
            ah[2] = Qh[rowA * AT_P + k8 + tig + 4];
            ah[3] = Qh[rowB * AT_P + k8 + tig + 4];
            al[0] = Ql[rowA * AT_P + k8 + tig];
            al[1] = Ql[rowB * AT_P + k8 + tig];
            al[2] = Ql[rowA * AT_P + k8 + tig + 4];
            al[3] = Ql[rowB * AT_P + k8 + tig + 4];
            #pragma unroll
            for (int nj = 0; nj < 8; nj++) {
                int kr = nj * 8 + g;
                uint32_t bh2[2] = {Kh[kr * AT_P + k8 + tig], Kh[kr * AT_P + k8 + tig + 4]};
                uint32_t bl2[2] = {Kl[kr * AT_P + k8 + tig], Kl[kr * AT_P + k8 + tig + 4]};
                mma_tf32(s[nj], ah, bh2);
                mma_tf32(s[nj], al, bh2);
                mma_tf32(s[nj], ah, bl2);
            }
        }

        if (j0 == q0) {
            #pragma unroll
            for (int nj = 0; nj < 8; nj++) {
                int k0c = nj * 8 + 2 * tig;
                if (k0c     > rowA) s[nj][0] = -1e30f;
                if (k0c + 1 > rowA) s[nj][1] = -1e30f;
                if (k0c     > rowB) s[nj][2] = -1e30f;
                if (k0c + 1 > rowB) s[nj][3] = -1e30f;
            }
        }

        float mx0 = m0, mx1 = m1;
        #pragma unroll
        for (int nj = 0; nj < 8; nj++) {
            mx0 = fmaxf(mx0, fmaxf(s[nj][0], s[nj][1]));
            mx1 = fmaxf(mx1, fmaxf(s[nj][2], s[nj][3]));
        }
        mx0 = fmaxf(mx0, __shfl_xor_sync(0xffffffffu, mx0, 1));
        mx0 = fmaxf(mx0, __shfl_xor_sync(0xffffffffu, mx0, 2));
        mx1 = fmaxf(mx1, __shfl_xor_sync(0xffffffffu, mx1, 1));
        mx1 = fmaxf(mx1, __shfl_xor_sync(0xffffffffu, mx1, 2));

        float fac0 = __expf(m0 - mx0), fac1 = __expf(m1 - mx1);
        float sum0 = 0.f, sum1 = 0.f;
        #pragma unroll
        for (int nj = 0; nj < 8; nj++) {
            s[nj][0] = __expf(s[nj][0] - mx0);
            s[nj][1] = __expf(s[nj][1] - mx0);
            s[nj][2] = __expf(s[nj][2] - mx1);
            s[nj][3] = __expf(s[nj][3] - mx1);
            sum0 += s[nj][0] + s[nj][1];
            sum1 += s[nj][2] + s[nj][3];
        }
        sum0 += __shfl_xor_sync(0xffffffffu, sum0, 1);
        sum0 += __shfl_xor_sync(0xffffffffu, sum0, 2);
        sum1 += __shfl_xor_sync(0xffffffffu, sum1, 1);
        sum1 += __shfl_xor_sync(0xffffffffu, sum1, 2);
        l0 = l0 * fac0 + sum0;
        l1 = l1 * fac1 + sum1;
        m0 = mx0; m1 = mx1;
        #pragma unroll
        for (int nj = 0; nj < 8; nj++) {
            o[nj][0] *= fac0; o[nj][1] *= fac0;
            o[nj][2] *= fac1; o[nj][3] *= fac1;
        }

        __syncthreads();
        #pragma unroll
        for (int nj = 0; nj < 8; nj++) {
            int cc = nj * 8 + 2 * tig;
            uint2 pa = {f2tf32(s[nj][0]), f2tf32(s[nj][1])};
            uint2 pb = {f2tf32(s[nj][2]), f2tf32(s[nj][3])};
            *(uint2*)&Ps[rowA * AT_P + cc] = pa;
            *(uint2*)&Ps[rowB * AT_P + cc] = pb;
        }
        __syncwarp();

        #pragma unroll
        for (int k8 = 0; k8 < 64; k8 += 8) {
            uint32_t a[4];
            a[0] = Ps[rowA * AT_P + k8 + tig];
            a[1] = Ps[rowB * AT_P + k8 + tig];
            a[2] = Ps[rowA * AT_P + k8 + tig + 4];
            a[3] = Ps[rowB * AT_P + k8 + tig + 4];
            #pragma unroll
            for (int nj = 0; nj < 8; nj++) {
                uint32_t bv[2] = {Vt[(k8 + tig) * AT_P + nj * 8 + g],
                                  Vt[(k8 + tig + 4) * AT_P + nj * 8 + g]};
                mma_tf32(o[nj], a, bv);
            }
        }
    }

    float inv0 = 1.f / l0, inv1 = 1.f / l1;
    size_t rA = (size_t)(b * TLEN + q0 + rowA) * DMODEL + h * HDIM;
    size_t rB = (size_t)(b * TLEN + q0 + rowB) * DMODEL + h * HDIM;
    #pragma unroll
    for (int nj = 0; nj < 8; nj++) {
        int cc = nj * 8 + 2 * tig;
        out[rA + cc]     = o[nj][0] * inv0;
        out[rA + cc + 1] = o[nj][1] * inv0;
        out[rB + cc]     = o[nj][2] * inv1;
        out[rB + cc + 1] = o[nj][3] * inv1;
    }
}

// ---------------- driver ----------------------------------------------------
extern "C" void kernel_launch(void* const* d_in, const int* in_sizes, int n_in,
                              void* d_out, int out_size) {
    const float* wte    = (const float*)d_in[0];
    const float* wpe    = (const float*)d_in[1];
    const float* ln1_w  = (const float*)d_in[2];
    const float* ln1_b  = (const float*)d_in[3];
    const float* attn_w = (const float*)d_in[4];
    const float* attn_b = (const float*)d_in[5];
    const float* proj_w = (const float*)d_in[6];
    const float* proj_b = (const float*)d_in[7];
    const float* ln2_w  = (const float*)d_in[8];
    const float* ln2_b  = (const float*)d_in[9];
    const float* fc_w   = (const float*)d_in[10];
    const float* fc_b   = (const float*)d_in[11];
    const float* fc2_w  = (const float*)d_in[12];
    const float* fc2_b  = (const float*)d_in[13];
    const float* lnf_w  = (const float*)d_in[14];
    const float* lnf_b  = (const float*)d_in[15];
    const int*   idx    = (const int*)d_in[16];
    float* out = (float*)d_out;

    void *px, *ph, *pqkv, *patt, *pfc;
    cudaGetSymbolAddress(&px, g_x);
    cudaGetSymbolAddress(&ph, g_h);
    cudaGetSymbolAddress(&pqkv, g_qkv);
    cudaGetSymbolAddress(&patt, g_att);
    cudaGetSymbolAddress(&pfc, g_fc);
    float* x   = (float*)px;
    float* h   = (float*)ph;
    float* qkv = (float*)pqkv;
    float* att = (float*)patt;
    float* fcb = (float*)pfc;

    cudaFuncSetAttribute(attn_tc_kernel,
                         cudaFuncAttributeMaxDynamicSharedMemorySize, ATTN_SMEM_TC);

    embed_kernel<<<MROWS, 256>>>(wte, wpe, idx, x);

    for (int l = 0; l < NLAYER; l++) {
        const float* aw  = attn_w + (size_t)l * DMODEL * 3 * DMODEL;
        const float* ab  = attn_b + (size_t)l * 3 * DMODEL;
        const float* pw  = proj_w + (size_t)l * DMODEL * DMODEL;
        const float* pb  = proj_b + (size_t)l * DMODEL;
        const float* fw  = fc_w   + (size_t)l * DMODEL * 4 * DMODEL;
        const float* fb  = fc_b   + (size_t)l * 4 * DMODEL;
        const float* f2w = fc2_w  + (size_t)l * 4 * DMODEL * DMODEL;
        const float* f2b = fc2_b  + (size_t)l * DMODEL;

        ln_kernel<<<MROWS, 256>>>(x, ln1_w + l * DMODEL, ln1_b + l * DMODEL, h);
        gemm_tf32<false><<<dim3(3 * DMODEL / 128, MROWS / 128), 256>>>(
            h, aw, ab, nullptr, qkv, MROWS, 3 * DMODEL, DMODEL, 0);
        attn_tc_kernel<<<dim3(TLEN / 64, BATCH * NHEAD), 128, ATTN_SMEM_TC>>>(qkv, att);
        gemm_tf32<false><<<dim3(DMODEL / 128, MROWS / 128), 256>>>(
            att, pw, pb, x, x, MROWS, DMODEL, DMODEL, 0);
        ln_kernel<<<MROWS, 256>>>(x, ln2_w + l * DMODEL, ln2_b + l * DMODEL, h);
        gemm_tf32<false><<<dim3(4 * DMODEL / 128, MROWS / 128), 256>>>(
            h, fw, fb, nullptr, fcb, MROWS, 4 * DMODEL, DMODEL, 1);
        gemm_tf32<false><<<dim3(DMODEL / 128, MROWS / 128), 256>>>(
            fcb, f2w, f2b, x, x, MROWS, DMODEL, 4 * DMODEL, 0);
    }

    ln_kernel<<<MROWS, 256>>>(x, lnf_w, lnf_b, h);
    gemm_tf32<true><<<dim3(MROWS / 128, VOCAB / 128), 256>>>(
        h, wte, nullptr, nullptr, out, MROWS, VOCAB, DMODEL, 0);
}

// round 11
// speedup vs baseline: 1.8496x; 1.1487x over previous
#include <cuda_runtime.h>
#include <cuda_bf16.h>
#include <math.h>
#include <stdint.h>

// ---------------- problem constants ----------------
#define NLAYER 4
#define NHEAD  8
#define DMODEL 512
#define TLEN   2048
#define BATCH  2
#define VOCAB  32000
#define HDIM   64
#define MROWS  (BATCH * TLEN)   // 4096
#define EPS    1e-5f

// ---------------- scratch (static device globals; no allocs allowed) -------
__device__ float g_x  [MROWS * DMODEL];
__device__ float g_h  [MROWS * DMODEL];
__device__ float g_qkv[MROWS * 3 * DMODEL];
__device__ float g_att[MROWS * DMODEL];
__device__ float g_fc [MROWS * 4 * DMODEL];

// ---------------- embedding ----------------
__global__ void embed_kernel(const float* __restrict__ wte,
                             const float* __restrict__ wpe,
                             const int*   __restrict__ idx,
                             float* __restrict__ x) {
    int m = blockIdx.x;
    int t = m % TLEN;
    int tok = idx[m];
    const float* we = wte + (size_t)tok * DMODEL;
    const float* pe = wpe + (size_t)t * DMODEL;
    float* xr = x + (size_t)m * DMODEL;
    for (int d = threadIdx.x; d < DMODEL; d += blockDim.x)
        xr[d] = we[d] + pe[d];
}

// ---------------- layernorm (round-4 proven) ----------------
__global__ __launch_bounds__(256)
void ln_kernel(const float* __restrict__ x, const float* __restrict__ w,
               const float* __restrict__ b, float* __restrict__ y) {
    int row = blockIdx.x;
    int tid = threadIdx.x;
    const float* xr = x + (size_t)row * DMODEL;
    float v0 = xr[tid];
    float v1 = xr[tid + 256];

    __shared__ float red[8];
    __shared__ float bc;

    float s = v0 + v1;
    #pragma unroll
    for (int o = 16; o; o >>= 1) s += __shfl_xor_sync(0xffffffffu, s, o);
    if ((tid & 31) == 0) red[tid >> 5] = s;
    __syncthreads();
    if (tid == 0) {
        float t = 0.f;
        #pragma unroll
        for (int i = 0; i < 8; i++) t += red[i];
        bc = t;
    }
    __syncthreads();
    float mu = bc * (1.f / DMODEL);
    float d0 = v0 - mu, d1 = v1 - mu;

    float s2 = d0 * d0 + d1 * d1;
    #pragma unroll
    for (int o = 16; o; o >>= 1) s2 += __shfl_xor_sync(0xffffffffu, s2, o);
    __syncthreads();
    if ((tid & 31) == 0) red[tid >> 5] = s2;
    __syncthreads();
    if (tid == 0) {
        float t = 0.f;
        #pragma unroll
        for (int i = 0; i < 8; i++) t += red[i];
        bc = t;
    }
    __syncthreads();
    float inv = rsqrtf(bc * (1.f / DMODEL) + EPS);

    float* yr = y + (size_t)row * DMODEL;
    yr[tid]       = d0 * inv * w[tid]       + b[tid];
    yr[tid + 256] = d1 * inv * w[tid + 256] + b[tid + 256];
}

// ---------------- mma helpers ----------------------------------------------
__device__ __forceinline__ uint32_t f2tf32(float v) {
    uint32_t r;
    asm("cvt.rna.tf32.f32 %0, %1;" : "=r"(r) : "f"(v));
    return r;
}
// pack (lo, hi) floats -> bf16x2 word (lo in lower 16 bits)
__device__ __forceinline__ uint32_t bf2(float lo, float hi) {
    uint32_t r;
    asm("cvt.rn.bf16x2.f32 %0, %1, %2;" : "=r"(r) : "f"(hi), "f"(lo));
    return r;
}

__device__ __forceinline__ void mma_tf32(float* d, const uint32_t* a, const uint32_t* b) {
    asm volatile(
        "mma.sync.aligned.m16n8k8.row.col.f32.tf32.tf32.f32 "
        "{%0,%1,%2,%3},{%4,%5,%6,%7},{%8,%9},{%0,%1,%2,%3};\n"
        : "+f"(d[0]), "+f"(d[1]), "+f"(d[2]), "+f"(d[3])
        : "r"(a[0]), "r"(a[1]), "r"(a[2]), "r"(a[3]), "r"(b[0]), "r"(b[1]));
}
__device__ __forceinline__ void mma_bf16(float* d, const uint32_t* a, const uint32_t* b) {
    asm volatile(
        "mma.sync.aligned.m16n8k16.row.col.f32.bf16.bf16.f32 "
        "{%0,%1,%2,%3},{%4,%5,%6,%7},{%8,%9},{%0,%1,%2,%3};\n"
        : "+f"(d[0]), "+f"(d[1]), "+f"(d[2]), "+f"(d[3])
        : "r"(a[0]), "r"(a[1]), "r"(a[2]), "r"(a[3]), "r"(b[0]), "r"(b[1]));
}

// ---------------- pipelined tf32 tensor-core GEMM (round-4, best measured) ---
#define AP 20
#define BP 136
template<bool BTRANS>
__global__ __launch_bounds__(256)
void gemm_tf32(const float* __restrict__ A, const float* __restrict__ Bm,
               const float* __restrict__ bias, const float* __restrict__ resid,
               float* __restrict__ Cm, int M, int N, int K, int gelu_flag) {
    __shared__ uint32_t As[2][128 * AP];
    __shared__ uint32_t Bs[2][16 * BP];

    int tid  = threadIdx.x;
    int lane = tid & 31;
    int w    = tid >> 5;
    int g    = lane >> 2;
    int tig  = lane & 3;
    int wm   = (w >> 2) * 64;
    int wn   = (w & 3) * 32;
    int m0 = (BTRANS ? blockIdx.x : blockIdx.y) * 128;
    int n0 = (BTRANS ? blockIdx.y : blockIdx.x) * 128;

    int aR0 = tid >> 2,            aC0 = (tid & 3) * 4;
    int aR1 = (tid + 256) >> 2;
    int bKr0, bNc0, bKr1, bNc1;
    if (!BTRANS) { bKr0 = tid >> 5; bNc0 = (tid & 31) * 4;
                   bKr1 = (tid + 256) >> 5; bNc1 = bNc0; }
    else         { bKr0 = (tid & 3) * 4; bNc0 = tid >> 2;
                   bKr1 = bKr0; bNc1 = (tid + 256) >> 2; }

    float4 arg0, arg1, brg0, brg1;

    auto load_tile = [&](int k0) {
        arg0 = *(const float4*)&A[(size_t)(m0 + aR0) * K + k0 + aC0];
        arg1 = *(const float4*)&A[(size_t)(m0 + aR1) * K + k0 + aC0];
        if (!BTRANS) {
            brg0 = *(const float4*)&Bm[(size_t)(k0 + bKr0) * N + n0 + bNc0];
            brg1 = *(const float4*)&Bm[(size_t)(k0 + bKr1) * N + n0 + bNc1];
        } else {
            brg0 = *(const float4*)&Bm[(size_t)(n0 + bNc0) * K + k0 + bKr0];
            brg1 = *(const float4*)&Bm[(size_t)(n0 + bNc1) * K + k0 + bKr1];
        }
    };
    auto store_tile = [&](int buf) {
        uint32_t* ap = &As[buf][aR0 * AP + aC0];
        ap[0] = f2tf32(arg0.x); ap[1] = f2tf32(arg0.y);
        ap[2] = f2tf32(arg0.z); ap[3] = f2tf32(arg0.w);
        ap = &As[buf][aR1 * AP + aC0];
        ap[0] = f2tf32(arg1.x); ap[1] = f2tf32(arg1.y);
        ap[2] = f2tf32(arg1.z); ap[3] = f2tf32(arg1.w);
        if (!BTRANS) {
            uint32_t* bp = &Bs[buf][bKr0 * BP + bNc0];
            bp[0] = f2tf32(brg0.x); bp[1] = f2tf32(brg0.y);
            bp[2] = f2tf32(brg0.z); bp[3] = f2tf32(brg0.w);
            bp = &Bs[buf][bKr1 * BP + bNc1];
            bp[0] = f2tf32(brg1.x); bp[1] = f2tf32(brg1.y);
            bp[2] = f2tf32(brg1.z); bp[3] = f2tf32(brg1.w);
        } else {
            Bs[buf][(bKr0 + 0) * BP + bNc0] = f2tf32(brg0.x);
            Bs[buf][(bKr0 + 1) * BP + bNc0] = f2tf32(brg0.y);
            Bs[buf][(bKr0 + 2) * BP + bNc0] = f2tf32(brg0.z);
            Bs[buf][(bKr0 + 3) * BP + bNc0] = f2tf32(brg0.w);
            Bs[buf][(bKr1 + 0) * BP + bNc1] = f2tf32(brg1.x);
            Bs[buf][(bKr1 + 1) * BP + bNc1] = f2tf32(brg1.y);
            Bs[buf][(bKr1 + 2) * BP + bNc1] = f2tf32(brg1.z);
            Bs[buf][(bKr1 + 3) * BP + bNc1] = f2tf32(brg1.w);
        }
    };

    float d[4][4][4];
    #pragma unroll
    for (int i = 0; i < 4; i++)
        #pragma unroll
        for (int j = 0; j < 4; j++)
            #pragma unroll
            for (int r = 0; r < 4; r++) d[i][j][r] = 0.f;

    load_tile(0);
    store_tile(0);
    __syncthreads();

    int buf = 0;
    for (int k0 = 0; k0 < K; k0 += 16) {
        int nk = k0 + 16;
        if (nk < K) load_tile(nk);

        const uint32_t* Ac = As[buf];
        const uint32_t* Bc = Bs[buf];
        #pragma unroll
        for (int kk = 0; kk < 16; kk += 8) {
            uint32_t af[4][4];
            #pragma unroll
            for (int mi = 0; mi < 4; mi++) {
                int rb = wm + mi * 16;
                af[mi][0] = Ac[(rb + g    ) * AP + kk + tig    ];
                af[mi][1] = Ac[(rb + g + 8) * AP + kk + tig    ];
                af[mi][2] = Ac[(rb + g    ) * AP + kk + tig + 4];
                af[mi][3] = Ac[(rb + g + 8) * AP + kk + tig + 4];
            }
            uint32_t bf[4][2];
            #pragma unroll
            for (int nj = 0; nj < 4; nj++) {
                int cb = wn + nj * 8;
                bf[nj][0] = Bc[(kk + tig    ) * BP + cb + g];
                bf[nj][1] = Bc[(kk + tig + 4) * BP + cb + g];
            }
            #pragma unroll
            for (int mi = 0; mi < 4; mi++)
                #pragma unroll
                for (int nj = 0; nj < 4; nj++)
                    mma_tf32(d[mi][nj], af[mi], bf[nj]);
        }

        if (nk < K) store_tile(buf ^ 1);
        __syncthreads();
        buf ^= 1;
    }

    #pragma unroll
    for (int mi = 0; mi < 4; mi++) {
        #pragma unroll
        for (int rr = 0; rr < 2; rr++) {
            int m = m0 + wm + mi * 16 + g + rr * 8;
            float* crow = Cm + (size_t)m * N;
            const float* rrow = resid ? resid + (size_t)m * N : nullptr;
            #pragma unroll
            for (int nj = 0; nj < 4; nj++) {
                int n = n0 + wn + nj * 8 + tig * 2;
                #pragma unroll
                for (int cc = 0; cc < 2; cc++) {
                    float c = d[mi][nj][rr * 2 + cc];
                    if (bias) c += bias[n + cc];
                    if (rrow) c += rrow[n + cc];
                    if (gelu_flag)
                        c = 0.5f * c * (1.f + erff(c * 0.70710678118654752f));
                    crow[n + cc] = c;
                }
            }
        }
    }
}

// ---------------- tensor-core causal flash attention -------------------------
// QK^T: split-bf16 3-term (hi*hi + lo*hi + hi*lo) with m16n8k16 — covers K=16
// per MMA, halving QK tensor instructions vs tf32-k8 split while keeping
// ~fp32-accurate scores (dropped term ~2^-18). PV: single tf32 (unchanged).
// Q/K stored as packed bf16x2 words, 32 words/row, pitch 36 (banks 4g+t).
// V tf32, pitch 72. Ps (tf32, pitch 72) aliases the contiguous Kh+Kl block
// (64*36 + 64*36 = 64*72 words), dead after QK^T; barrier separates phases.
#define P2B 36
#define PVP 72
#define ATTN_SMEM_TC ((4 * 64 * P2B + 64 * PVP) * (int)sizeof(uint32_t)) // 55296

__global__ __launch_bounds__(128)
void attn_tc_kernel(const float* __restrict__ qkv, float* __restrict__ out) {
    extern __shared__ uint32_t smu[];
    uint32_t* Qh = smu;                    // [64][36] bf16x2
    uint32_t* Ql = Qh + 64 * P2B;          // [64][36] bf16x2
    uint32_t* Kh = Ql + 64 * P2B;          // [64][36] bf16x2
    uint32_t* Kl = Kh + 64 * P2B;          // [64][36] bf16x2
    uint32_t* Vt = Kl + 64 * P2B;          // [64][72] tf32
    uint32_t* Ps = Kh;                     // [64][72] tf32, aliases Kh+Kl

    int tid  = threadIdx.x;
    int lane = tid & 31;
    int wid  = tid >> 5;
    int g    = lane >> 2;
    int tig  = lane & 3;
    int b = blockIdx.y >> 3, h = blockIdx.y & 7;
    int q0 = blockIdx.x * 64;
    const int RS = 3 * DMODEL;
    const float* qbase = qkv + (size_t)b * TLEN * RS + h * HDIM;
    const float* kbase = qbase + DMODEL;
    const float* vbase = qbase + 2 * DMODEL;

    // Q tile: scale by 1/8, split bf16 hi/lo, packed pairs (STS.64)
    for (int i = tid; i < 64 * 16; i += 128) {
        int r = i >> 4, j = i & 15;        // j-th float4; word offset 2j
        float4 v = *(const float4*)&qbase[(size_t)(q0 + r) * RS + j * 4];
        float q4[4] = {v.x * 0.125f, v.y * 0.125f, v.z * 0.125f, v.w * 0.125f};
        float hi[4], lo[4];
        #pragma unroll
        for (int c = 0; c < 4; c++) {
            __nv_bfloat16 hb = __float2bfloat16(q4[c]);
            hi[c] = __bfloat162float(hb);
            lo[c] = q4[c] - hi[c];
        }
        uint2 uh = {bf2(hi[0], hi[1]), bf2(hi[2], hi[3])};
        uint2 ul = {bf2(lo[0], lo[1]), bf2(lo[2], lo[3])};
        *(uint2*)&Qh[r * P2B + 2 * j] = uh;
        *(uint2*)&Ql[r * P2B + 2 * j] = ul;
    }

    float o[8][4];
    #pragma unroll
    for (int nj = 0; nj < 8; nj++)
        #pragma unroll
        for (int c = 0; c < 4; c++) o[nj][c] = 0.f;
    float m0 = -1e30f, m1 = -1e30f, l0 = 0.f, l1 = 0.f;
    int wrow = wid * 16;
    int rowA = wrow + g, rowB = wrow + g + 8;

    for (int j0 = 0; j0 <= q0; j0 += 64) {
        __syncthreads();   // prev iter's PV reads (Ps, Vt) done before refill
        for (int i = tid; i < 64 * 16; i += 128) {
            int r = i >> 4, j = i & 15;
            float4 kv = *(const float4*)&kbase[(size_t)(j0 + r) * RS + j * 4];
            float4 vv = *(const float4*)&vbase[(size_t)(j0 + r) * RS + j * 4];
            float k4[4] = {kv.x, kv.y, kv.z, kv.w};
            float hi[4], lo[4];
            #pragma unroll
            for (int c = 0; c < 4; c++) {
                __nv_bfloat16 hb = __float2bfloat16(k4[c]);
                hi[c] = __bfloat162float(hb);
                lo[c] = k4[c] - hi[c];
            }
            uint2 uh = {bf2(hi[0], hi[1]), bf2(hi[2], hi[3])};
            uint2 ul = {bf2(lo[0], lo[1]), bf2(lo[2], lo[3])};
            *(uint2*)&Kh[r * P2B + 2 * j] = uh;
            *(uint2*)&Kl[r * P2B + 2 * j] = ul;
            uint4 uv = {f2tf32(vv.x), f2tf32(vv.y), f2tf32(vv.z), f2tf32(vv.w)};
            *(uint4*)&Vt[r * PVP + 4 * j] = uv;
        }
        __syncthreads();

        // ---- S = Q K^T (split-bf16, m16n8k16; 4 k-blocks of 16) ----
        float s[8][4];
        #pragma unroll
        for (int nj = 0; nj < 8; nj++)
            #pragma unroll
            for (int c = 0; c < 4; c++) s[nj][c] = 0.f;

        #pragma unroll
        for (int kw = 0; kw < 32; kw += 8) {   // word offset per k16 block
            uint32_t ah[4], al[4];
            ah[0] = Qh[rowA * P2B + kw + tig];
            ah[1] = Qh[rowB * P2B + kw + tig];
            ah[2] = Qh[rowA * P2B + kw + tig + 4];
            ah[3] = Qh[rowB * P2B + kw + tig + 4];
            al[0] = Ql[rowA * P2B + kw + tig];
            al[1] = Ql[rowB * P2B + kw + tig];
            al[2] = Ql[rowA * P2B + kw + tig + 4];
            al[3] = Ql[rowB * P2B + kw + tig + 4];
            #pragma unroll
            for (int nj = 0; nj < 8; nj++) {
                int kr = nj * 8 + g;
                uint32_t bh2[2] = {Kh[kr * P2B + kw + tig], Kh[kr * P2B + kw + tig + 4]};
                uint32_t bl2[2] = {Kl[kr * P2B + kw + tig], Kl[kr * P2B + kw + tig + 4]};
                mma_bf16(s[nj], ah, bh2);
                mma_bf16(s[nj], al, bh2);
                mma_bf16(s[nj], ah, bl2);
            }
        }

        if (j0 == q0) {
            #pragma unroll
            for (int nj = 0; nj < 8; nj++) {
                int k0c = nj * 8 + 2 * tig;
                if (k0c     > rowA) s[nj][0] = -1e30f;
                if (k0c + 1 > rowA) s[nj][1] = -1e30f;
                if (k0c     > rowB) s[nj][2] = -1e30f;
                if (k0c + 1 > rowB) s[nj][3] = -1e30f;
            }
        }

        // ---- online softmax in registers ----
        float mx0 = m0, mx1 = m1;
        #pragma unroll
        for (int nj = 0; nj < 8; nj++) {
            mx0 = fmaxf(mx0, fmaxf(s[nj][0], s[nj][1]));
            mx1 = fmaxf(mx1, fmaxf(s[nj][2], s[nj][3]));
        }
        mx0 = fmaxf(mx0, __shfl_xor_sync(0xffffffffu, mx0, 1));
        mx0 = fmaxf(mx0, __shfl_xor_sync(0xffffffffu, mx0, 2));
        mx1 = fmaxf(mx1, __shfl_xor_sync(0xffffffffu, mx1, 1));
        mx1 = fmaxf(mx1, __shfl_xor_sync(0xffffffffu, mx1, 2));

        float fac0 = __expf(m0 - mx0), fac1 = __expf(m1 - mx1);
        float sum0 = 0.f, sum1 = 0.f;
        #pragma unroll
        for (int nj = 0; nj < 8; nj++) {
            s[nj][0] = __expf(s[nj][0] - mx0);
            s[nj][1] = __expf(s[nj][1] - mx0);
            s[nj][2] = __expf(s[nj][2] - mx1);
            s[nj][3] = __expf(s[nj][3] - mx1);
            sum0 += s[nj][0] + s[nj][1];
            sum1 += s[nj][2] + s[nj][3];
        }
        sum0 += __shfl_xor_sync(0xffffffffu, sum0, 1);
        sum0 += __shfl_xor_sync(0xffffffffu, sum0, 2);
        sum1 += __shfl_xor_sync(0xffffffffu, sum1, 1);
        sum1 += __shfl_xor_sync(0xffffffffu, sum1, 2);
        l0 = l0 * fac0 + sum0;
        l1 = l1 * fac1 + sum1;
        m0 = mx0; m1 = mx1;
        #pragma unroll
        for (int nj = 0; nj < 8; nj++) {
            o[nj][0] *= fac0; o[nj][1] *= fac0;
            o[nj][2] *= fac1; o[nj][3] *= fac1;
        }

        __syncthreads();   // all warps' QK^T reads of Kh/Kl done before Ps writes
        #pragma unroll
        for (int nj = 0; nj < 8; nj++) {
            int cc = nj * 8 + 2 * tig;
            uint2 pa = {f2tf32(s[nj][0]), f2tf32(s[nj][1])};
            uint2 pb = {f2tf32(s[nj][2]), f2tf32(s[nj][3])};
            *(uint2*)&Ps[rowA * PVP + cc] = pa;
            *(uint2*)&Ps[rowB * PVP + cc] = pb;
        }
        __syncwarp();      // Ps rows are warp-private

        // ---- O += P V (single tf32, m16n8k8) ----
        #pragma unroll
        for (int k8 = 0; k8 < 64; k8 += 8) {
            uint32_t a[4];
            a[0] = Ps[rowA * PVP + k8 + tig];
            a[1] = Ps[rowB * PVP + k8 + tig];
            a[2] = Ps[rowA * PVP + k8 + tig + 4];
            a[3] = Ps[rowB * PVP + k8 + tig + 4];
            #pragma unroll
            for (int nj = 0; nj < 8; nj++) {
                uint32_t bv[2] = {Vt[(k8 + tig) * PVP + nj * 8 + g],
                                  Vt[(k8 + tig + 4) * PVP + nj * 8 + g]};
                mma_tf32(o[nj], a, bv);
            }
        }
    }

    float inv0 = 1.f / l0, inv1 = 1.f / l1;
    size_t rA = (size_t)(b * TLEN + q0 + rowA) * DMODEL + h * HDIM;
    size_t rB = (size_t)(b * TLEN + q0 + rowB) * DMODEL + h * HDIM;
    #pragma unroll
    for (int nj = 0; nj < 8; nj++) {
        int cc = nj * 8 + 2 * tig;
        out[rA + cc]     = o[nj][0] * inv0;
        out[rA + cc + 1] = o[nj][1] * inv0;
        out[rB + cc]     = o[nj][2] * inv1;
        out[rB + cc + 1] = o[nj][3] * inv1;
    }
}

// ---------------- driver ----------------------------------------------------
extern "C" void kernel_launch(void* const* d_in, const int* in_sizes, int n_in,
                              void* d_out, int out_size) {
    const float* wte    = (const float*)d_in[0];
    const float* wpe    = (const float*)d_in[1];
    const float* ln1_w  = (const float*)d_in[2];
    const float* ln1_b  = (const float*)d_in[3];
    const float* attn_w = (const float*)d_in[4];
    const float* attn_b = (const float*)d_in[5];
    const float* proj_w = (const float*)d_in[6];
    const float* proj_b = (const float*)d_in[7];
    const float* ln2_w  = (const float*)d_in[8];
    const float* ln2_b  = (const float*)d_in[9];
    const float* fc_w   = (const float*)d_in[10];
    const float* fc_b   = (const float*)d_in[11];
    const float* fc2_w  = (const float*)d_in[12];
    const float* fc2_b  = (const float*)d_in[13];
    const float* lnf_w  = (const float*)d_in[14];
    const float* lnf_b  = (const float*)d_in[15];
    const int*   idx    = (const int*)d_in[16];
    float* out = (float*)d_out;

    void *px, *ph, *pqkv, *patt, *pfc;
    cudaGetSymbolAddress(&px, g_x);
    cudaGetSymbolAddress(&ph, g_h);
    cudaGetSymbolAddress(&pqkv, g_qkv);
    cudaGetSymbolAddress(&patt, g_att);
    cudaGetSymbolAddress(&pfc, g_fc);
    float* x   = (float*)px;
    float* h   = (float*)ph;
    float* qkv = (float*)pqkv;
    float* att = (float*)patt;
    float* fcb = (float*)pfc;

    cudaFuncSetAttribute(attn_tc_kernel,
                         cudaFuncAttributeMaxDynamicSharedMemorySize, ATTN_SMEM_TC);

    embed_kernel<<<MROWS, 256>>>(wte, wpe, idx, x);

    for (int l = 0; l < NLAYER; l++) {
        const float* aw  = attn_w + (size_t)l * DMODEL * 3 * DMODEL;
        const float* ab  = attn_b + (size_t)l * 3 * DMODEL;
        const float* pw  = proj_w + (size_t)l * DMODEL * DMODEL;
        const float* pb  = proj_b + (size_t)l * DMODEL;
        const float* fw  = fc_w   + (size_t)l * DMODEL * 4 * DMODEL;
        const float* fb  = fc_b   + (size_t)l * 4 * DMODEL;
        const float* f2w = fc2_w  + (size_t)l * 4 * DMODEL * DMODEL;
        const float* f2b = fc2_b  + (size_t)l * DMODEL;

        ln_kernel<<<MROWS, 256>>>(x, ln1_w + l * DMODEL, ln1_b + l * DMODEL, h);
        gemm_tf32<false><<<dim3(3 * DMODEL / 128, MROWS / 128), 256>>>(
            h, aw, ab, nullptr, qkv, MROWS, 3 * DMODEL, DMODEL, 0);
        attn_tc_kernel<<<dim3(TLEN / 64, BATCH * NHEAD), 128, ATTN_SMEM_TC>>>(qkv, att);
        gemm_tf32<false><<<dim3(DMODEL / 128, MROWS / 128), 256>>>(
            att, pw, pb, x, x, MROWS, DMODEL, DMODEL, 0);
        ln_kernel<<<MROWS, 256>>>(x, ln2_w + l * DMODEL, ln2_b + l * DMODEL, h);
        gemm_tf32<false><<<dim3(4 * DMODEL / 128, MROWS / 128), 256>>>(
            h, fw, fb, nullptr, fcb, MROWS, 4 * DMODEL, DMODEL, 1);
        gemm_tf32<false><<<dim3(DMODEL / 128, MROWS / 128), 256>>>(
            fcb, f2w, f2b, x, x, MROWS, DMODEL, 4 * DMODEL, 0);
    }

    ln_kernel<<<MROWS, 256>>>(x, lnf_w, lnf_b, h);
    gemm_tf32<true><<<dim3(MROWS / 128, VOCAB / 128), 256>>>(
        h, wte, nullptr, nullptr, out, MROWS, VOCAB, DMODEL, 0);
}

// round 12
// speedup vs baseline: 1.8689x; 1.0104x over previous
#include <cuda_runtime.h>
#include <cuda_bf16.h>
#include <math.h>
#include <stdint.h>

// ---------------- problem constants ----------------
#define NLAYER 4
#define NHEAD  8
#define DMODEL 512
#define TLEN   2048
#define BATCH  2
#define VOCAB  32000
#define HDIM   64
#define MROWS  (BATCH * TLEN)   // 4096
#define EPS    1e-5f

// ---------------- scratch (static device globals; no allocs allowed) -------
__device__ float g_x  [MROWS * DMODEL];
__device__ float g_h  [MROWS * DMODEL];
__device__ float g_qkv[MROWS * 3 * DMODEL];
__device__ float g_att[MROWS * DMODEL];
__device__ float g_fc [MROWS * 4 * DMODEL];

// ---------------- embedding ----------------
__global__ void embed_kernel(const float* __restrict__ wte,
                             const float* __restrict__ wpe,
                             const int*   __restrict__ idx,
                             float* __restrict__ x) {
    int m = blockIdx.x;
    int t = m % TLEN;
    int tok = idx[m];
    const float* we = wte + (size_t)tok * DMODEL;
    const float* pe = wpe + (size_t)t * DMODEL;
    float* xr = x + (size_t)m * DMODEL;
    for (int d = threadIdx.x; d < DMODEL; d += blockDim.x)
        xr[d] = we[d] + pe[d];
}

// ---------------- layernorm ----------------
__global__ __launch_bounds__(256)
void ln_kernel(const float* __restrict__ x, const float* __restrict__ w,
               const float* __restrict__ b, float* __restrict__ y) {
    int row = blockIdx.x;
    int tid = threadIdx.x;
    const float* xr = x + (size_t)row * DMODEL;
    float v0 = xr[tid];
    float v1 = xr[tid + 256];

    __shared__ float red[8];
    __shared__ float bc;

    float s = v0 + v1;
    #pragma unroll
    for (int o = 16; o; o >>= 1) s += __shfl_xor_sync(0xffffffffu, s, o);
    if ((tid & 31) == 0) red[tid >> 5] = s;
    __syncthreads();
    if (tid == 0) {
        float t = 0.f;
        #pragma unroll
        for (int i = 0; i < 8; i++) t += red[i];
        bc = t;
    }
    __syncthreads();
    float mu = bc * (1.f / DMODEL);
    float d0 = v0 - mu, d1 = v1 - mu;

    float s2 = d0 * d0 + d1 * d1;
    #pragma unroll
    for (int o = 16; o; o >>= 1) s2 += __shfl_xor_sync(0xffffffffu, s2, o);
    __syncthreads();
    if ((tid & 31) == 0) red[tid >> 5] = s2;
    __syncthreads();
    if (tid == 0) {
        float t = 0.f;
        #pragma unroll
        for (int i = 0; i < 8; i++) t += red[i];
        bc = t;
    }
    __syncthreads();
    float inv = rsqrtf(bc * (1.f / DMODEL) + EPS);

    float* yr = y + (size_t)row * DMODEL;
    yr[tid]       = d0 * inv * w[tid]       + b[tid];
    yr[tid + 256] = d1 * inv * w[tid + 256] + b[tid + 256];
}

// ---------------- mma helpers ----------------------------------------------
__device__ __forceinline__ uint32_t f2tf32(float v) {
    uint32_t r;
    asm("cvt.rna.tf32.f32 %0, %1;" : "=r"(r) : "f"(v));
    return r;
}
__device__ __forceinline__ uint32_t bf2(float lo, float hi) {
    uint32_t r;
    asm("cvt.rn.bf16x2.f32 %0, %1, %2;" : "=r"(r) : "f"(hi), "f"(lo));
    return r;
}

__device__ __forceinline__ void mma_tf32(float* d, const uint32_t* a, const uint32_t* b) {
    asm volatile(
        "mma.sync.aligned.m16n8k8.row.col.f32.tf32.tf32.f32 "
        "{%0,%1,%2,%3},{%4,%5,%6,%7},{%8,%9},{%0,%1,%2,%3};\n"
        : "+f"(d[0]), "+f"(d[1]), "+f"(d[2]), "+f"(d[3])
        : "r"(a[0]), "r"(a[1]), "r"(a[2]), "r"(a[3]), "r"(b[0]), "r"(b[1]));
}
__device__ __forceinline__ void mma_bf16(float* d, const uint32_t* a, const uint32_t* b) {
    asm volatile(
        "mma.sync.aligned.m16n8k16.row.col.f32.bf16.bf16.f32 "
        "{%0,%1,%2,%3},{%4,%5,%6,%7},{%8,%9},{%0,%1,%2,%3};\n"
        : "+f"(d[0]), "+f"(d[1]), "+f"(d[2]), "+f"(d[3])
        : "r"(a[0]), "r"(a[1]), "r"(a[2]), "r"(a[3]), "r"(b[0]), "r"(b[1]));
}

// ---------------- pipelined tf32 GEMM, 128x128 tile (round-4 proven) ---------
#define AP 20
#define BP 136
template<bool BTRANS>
__global__ __launch_bounds__(256)
void gemm_tf32(const float* __restrict__ A, const float* __restrict__ Bm,
               const float* __restrict__ bias, const float* __restrict__ resid,
               float* __restrict__ Cm, int M, int N, int K, int gelu_flag) {
    __shared__ uint32_t As[2][128 * AP];
    __shared__ uint32_t Bs[2][16 * BP];

    int tid  = threadIdx.x;
    int lane = tid & 31;
    int w    = tid >> 5;
    int g    = lane >> 2;
    int tig  = lane & 3;
    int wm   = (w >> 2) * 64;
    int wn   = (w & 3) * 32;
    int m0 = (BTRANS ? blockIdx.x : blockIdx.y) * 128;
    int n0 = (BTRANS ? blockIdx.y : blockIdx.x) * 128;

    int aR0 = tid >> 2,            aC0 = (tid & 3) * 4;
    int aR1 = (tid + 256) >> 2;
    int bKr0, bNc0, bKr1, bNc1;
    if (!BTRANS) { bKr0 = tid >> 5; bNc0 = (tid & 31) * 4;
                   bKr1 = (tid + 256) >> 5; bNc1 = bNc0; }
    else         { bKr0 = (tid & 3) * 4; bNc0 = tid >> 2;
                   bKr1 = bKr0; bNc1 = (tid + 256) >> 2; }

    float4 arg0, arg1, brg0, brg1;

    auto load_tile = [&](int k0) {
        arg0 = *(const float4*)&A[(size_t)(m0 + aR0) * K + k0 + aC0];
        arg1 = *(const float4*)&A[(size_t)(m0 + aR1) * K + k0 + aC0];
        if (!BTRANS) {
            brg0 = *(const float4*)&Bm[(size_t)(k0 + bKr0) * N + n0 + bNc0];
            brg1 = *(const float4*)&Bm[(size_t)(k0 + bKr1) * N + n0 + bNc1];
        } else {
            brg0 = *(const float4*)&Bm[(size_t)(n0 + bNc0) * K + k0 + bKr0];
            brg1 = *(const float4*)&Bm[(size_t)(n0 + bNc1) * K + k0 + bKr1];
        }
    };
    auto store_tile = [&](int buf) {
        uint32_t* ap = &As[buf][aR0 * AP + aC0];
        ap[0] = f2tf32(arg0.x); ap[1] = f2tf32(arg0.y);
        ap[2] = f2tf32(arg0.z); ap[3] = f2tf32(arg0.w);
        ap = &As[buf][aR1 * AP + aC0];
        ap[0] = f2tf32(arg1.x); ap[1] = f2tf32(arg1.y);
        ap[2] = f2tf32(arg1.z); ap[3] = f2tf32(arg1.w);
        if (!BTRANS) {
            uint32_t* bp = &Bs[buf][bKr0 * BP + bNc0];
            bp[0] = f2tf32(brg0.x); bp[1] = f2tf32(brg0.y);
            bp[2] = f2tf32(brg0.z); bp[3] = f2tf32(brg0.w);
            bp = &Bs[buf][bKr1 * BP + bNc1];
            bp[0] = f2tf32(brg1.x); bp[1] = f2tf32(brg1.y);
            bp[2] = f2tf32(brg1.z); bp[3] = f2tf32(brg1.w);
        } else {
            Bs[buf][(bKr0 + 0) * BP + bNc0] = f2tf32(brg0.x);
            Bs[buf][(bKr0 + 1) * BP + bNc0] = f2tf32(brg0.y);
            Bs[buf][(bKr0 + 2) * BP + bNc0] = f2tf32(brg0.z);
            Bs[buf][(bKr0 + 3) * BP + bNc0] = f2tf32(brg0.w);
            Bs[buf][(bKr1 + 0) * BP + bNc1] = f2tf32(brg1.x);
            Bs[buf][(bKr1 + 1) * BP + bNc1] = f2tf32(brg1.y);
            Bs[buf][(bKr1 + 2) * BP + bNc1] = f2tf32(brg1.z);
            Bs[buf][(bKr1 + 3) * BP + bNc1] = f2tf32(brg1.w);
        }
    };

    float d[4][4][4];
    #pragma unroll
    for (int i = 0; i < 4; i++)
        #pragma unroll
        for (int j = 0; j < 4; j++)
            #pragma unroll
            for (int r = 0; r < 4; r++) d[i][j][r] = 0.f;

    load_tile(0);
    store_tile(0);
    __syncthreads();

    int buf = 0;
    for (int k0 = 0; k0 < K; k0 += 16) {
        int nk = k0 + 16;
        if (nk < K) load_tile(nk);

        const uint32_t* Ac = As[buf];
        const uint32_t* Bc = Bs[buf];
        #pragma unroll
        for (int kk = 0; kk < 16; kk += 8) {
            uint32_t af[4][4];
            #pragma unroll
            for (int mi = 0; mi < 4; mi++) {
                int rb = wm + mi * 16;
                af[mi][0] = Ac[(rb + g    ) * AP + kk + tig    ];
                af[mi][1] = Ac[(rb + g + 8) * AP + kk + tig    ];
                af[mi][2] = Ac[(rb + g    ) * AP + kk + tig + 4];
                af[mi][3] = Ac[(rb + g + 8) * AP + kk + tig + 4];
            }
            uint32_t bf[4][2];
            #pragma unroll
            for (int nj = 0; nj < 4; nj++) {
                int cb = wn + nj * 8;
                bf[nj][0] = Bc[(kk + tig    ) * BP + cb + g];
                bf[nj][1] = Bc[(kk + tig + 4) * BP + cb + g];
            }
            #pragma unroll
            for (int mi = 0; mi < 4; mi++)
                #pragma unroll
                for (int nj = 0; nj < 4; nj++)
                    mma_tf32(d[mi][nj], af[mi], bf[nj]);
        }

        if (nk < K) store_tile(buf ^ 1);
        __syncthreads();
        buf ^= 1;
    }

    #pragma unroll
    for (int mi = 0; mi < 4; mi++) {
        #pragma unroll
        for (int rr = 0; rr < 2; rr++) {
            int m = m0 + wm + mi * 16 + g + rr * 8;
            float* crow = Cm + (size_t)m * N;
            const float* rrow = resid ? resid + (size_t)m * N : nullptr;
            #pragma unroll
            for (int nj = 0; nj < 4; nj++) {
                int n = n0 + wn + nj * 8 + tig * 2;
                #pragma unroll
                for (int cc = 0; cc < 2; cc++) {
                    float c = d[mi][nj][rr * 2 + cc];
                    if (bias) c += bias[n + cc];
                    if (rrow) c += rrow[n + cc];
                    if (gelu_flag)
                        c = 0.5f * c * (1.f + erff(c * 0.70710678118654752f));
                    crow[n + cc] = c;
                }
            }
        }
    }
}

// ---------------- pipelined tf32 GEMM, 64x128 tile (for N=512 shapes) --------
// proj/fc2 launch only 128 CTAs with the 128-tile — one under-filled wave.
// 64 M-rows per CTA doubles the grid (256 CTAs) and halves per-CTA smem/regs
// (8 warps = 1x8 over N, warp tile 64x16, acc 4x2). Non-trans B only.
__global__ __launch_bounds__(256)
void gemm_tf32_m64(const float* __restrict__ A, const float* __restrict__ Bm,
                   const float* __restrict__ bias, const float* __restrict__ resid,
                   float* __restrict__ Cm, int M, int N, int K, int gelu_flag) {
    __shared__ uint32_t As[2][64 * AP];
    __shared__ uint32_t Bs[2][16 * BP];

    int tid  = threadIdx.x;
    int lane = tid & 31;
    int w    = tid >> 5;
    int g    = lane >> 2;
    int tig  = lane & 3;
    int wn   = w * 16;                 // 8 warps across N
    int m0 = blockIdx.y * 64;
    int n0 = blockIdx.x * 128;

    int aR0 = tid >> 2,  aC0 = (tid & 3) * 4;           // 64x16 A tile: 1 f4/thread
    int bKr0 = tid >> 5, bNc0 = (tid & 31) * 4;         // B tile: 2 f4/thread
    int bKr1 = bKr0 + 8;

    float4 arg0, brg0, brg1;

    auto load_tile = [&](int k0) {
        arg0 = *(const float4*)&A[(size_t)(m0 + aR0) * K + k0 + aC0];
        brg0 = *(const float4*)&Bm[(size_t)(k0 + bKr0) * N + n0 + bNc0];
        brg1 = *(const float4*)&Bm[(size_t)(k0 + bKr1) * N + n0 + bNc0];
    };
    auto store_tile = [&](int buf) {
        uint32_t* ap = &As[buf][aR0 * AP + aC0];
        ap[0] = f2tf32(arg0.x); ap[1] = f2tf32(arg0.y);
        ap[2] = f2tf32(arg0.z); ap[3] = f2tf32(arg0.w);
        uint32_t* bp = &Bs[buf][bKr0 * BP + bNc0];
        bp[0] = f2tf32(brg0.x); bp[1] = f2tf32(brg0.y);
        bp[2] = f2tf32(brg0.z); bp[3] = f2tf32(brg0.w);
        bp = &Bs[buf][bKr1 * BP + bNc0];
        bp[0] = f2tf32(brg1.x); bp[1] = f2tf32(brg1.y);
        bp[2] = f2tf32(brg1.z); bp[3] = f2tf32(brg1.w);
    };

    float d[4][2][4];
    #pragma unroll
    for (int i = 0; i < 4; i++)
        #pragma unroll
        for (int j = 0; j < 2; j++)
            #pragma unroll
            for (int r = 0; r < 4; r++) d[i][j][r] = 0.f;

    load_tile(0);
    store_tile(0);
    __syncthreads();

    int buf = 0;
    for (int k0 = 0; k0 < K; k0 += 16) {
        int nk = k0 + 16;
        if (nk < K) load_tile(nk);

        const uint32_t* Ac = As[buf];
        const uint32_t* Bc = Bs[buf];
        #pragma unroll
        for (int kk = 0; kk < 16; kk += 8) {
            uint32_t af[4][4];
            #pragma unroll
            for (int mi = 0; mi < 4; mi++) {
                int rb = mi * 16;
                af[mi][0] = Ac[(rb + g    ) * AP + kk + tig    ];
                af[mi][1] = Ac[(rb + g + 8) * AP + kk + tig    ];
                af[mi][2] = Ac[(rb + g    ) * AP + kk + tig + 4];
                af[mi][3] = Ac[(rb + g + 8) * AP + kk + tig + 4];
            }
            uint32_t bf[2][2];
            #pragma unroll
            for (int nj = 0; nj < 2; nj++) {
                int cb = wn + nj * 8;
                bf[nj][0] = Bc[(kk + tig    ) * BP + cb + g];
                bf[nj][1] = Bc[(kk + tig + 4) * BP + cb + g];
            }
            #pragma unroll
            for (int mi = 0; mi < 4; mi++)
                #pragma unroll
                for (int nj = 0; nj < 2; nj++)
                    mma_tf32(d[mi][nj], af[mi], bf[nj]);
        }

        if (nk < K) store_tile(buf ^ 1);
        __syncthreads();
        buf ^= 1;
    }

    #pragma unroll
    for (int mi = 0; mi < 4; mi++) {
        #pragma unroll
        for (int rr = 0; rr < 2; rr++) {
            int m = m0 + mi * 16 + g + rr * 8;
            float* crow = Cm + (size_t)m * N;
            const float* rrow = resid ? resid + (size_t)m * N : nullptr;
            #pragma unroll
            for (int nj = 0; nj < 2; nj++) {
                int n = n0 + wn + nj * 8 + tig * 2;
                #pragma unroll
                for (int cc = 0; cc < 2; cc++) {
                    float c = d[mi][nj][rr * 2 + cc];
                    if (bias) c += bias[n + cc];
                    if (rrow) c += rrow[n + cc];
                    if (gelu_flag)
                        c = 0.5f * c * (1.f + erff(c * 0.70710678118654752f));
                    crow[n + cc] = c;
                }
            }
        }
    }
}

// ---------------- tensor-core causal flash attention -------------------------
// Round-11 proven (split-bf16 k16 QK, tf32 PV), with Ps in a DEDICATED buffer:
// the softmax->Ps->PV path now needs only __syncwarp (Ps rows warp-private),
// deleting one of three __syncthreads per K-tile.
#define P2B 36
#define PVP 72
#define ATTN_SMEM_TC ((4 * 64 * P2B + 2 * 64 * PVP) * (int)sizeof(uint32_t)) // 73728

__global__ __launch_bounds__(128)
void attn_tc_kernel(const float* __restrict__ qkv, float* __restrict__ out) {
    extern __shared__ uint32_t smu[];
    uint32_t* Qh = smu;                    // [64][36] bf16x2
    uint32_t* Ql = Qh + 64 * P2B;          // [64][36] bf16x2
    uint32_t* Kh = Ql + 64 * P2B;          // [64][36] bf16x2
    uint32_t* Kl = Kh + 64 * P2B;          // [64][36] bf16x2
    uint32_t* Vt = Kl + 64 * P2B;          // [64][72] tf32
    uint32_t* Ps = Vt + 64 * PVP;          // [64][72] tf32 (dedicated)

    int tid  = threadIdx.x;
    int lane = tid & 31;
    int wid  = tid >> 5;
    int g    = lane >> 2;
    int tig  = lane & 3;
    int b = blockIdx.y >> 3, h = blockIdx.y & 7;
    int q0 = blockIdx.x * 64;
    const int RS = 3 * DMODEL;
    const float* qbase = qkv + (size_t)b * TLEN * RS + h * HDIM;
    const float* kbase = qbase + DMODEL;
    const float* vbase = qbase + 2 * DMODEL;

    for (int i = tid; i < 64 * 16; i += 128) {
        int r = i >> 4, j = i & 15;
        float4 v = *(const float4*)&qbase[(size_t)(q0 + r) * RS + j * 4];
        float q4[4] = {v.x * 0.125f, v.y * 0.125f, v.z * 0.125f, v.w * 0.125f};
        float hi[4], lo[4];
        #pragma unroll
        for (int c = 0; c < 4; c++) {
            __nv_bfloat16 hb = __float2bfloat16(q4[c]);
            hi[c] = __bfloat162float(hb);
            lo[c] = q4[c] - hi[c];
        }
        uint2 uh = {bf2(hi[0], hi[1]), bf2(hi[2], hi[3])};
        uint2 ul = {bf2(lo[0], lo[1]), bf2(lo[2], lo[3])};
        *(uint2*)&Qh[r * P2B + 2 * j] = uh;
        *(uint2*)&Ql[r * P2B + 2 * j] = ul;
    }

    float o[8][4];
    #pragma unroll
    for (int nj = 0; nj < 8; nj++)
        #pragma unroll
        for (int c = 0; c < 4; c++) o[nj][c] = 0.f;
    float m0 = -1e30f, m1 = -1e30f, l0 = 0.f, l1 = 0.f;
    int wrow = wid * 16;
    int rowA = wrow + g, rowB = wrow + g + 8;

    for (int j0 = 0; j0 <= q0; j0 += 64) {
        __syncthreads();   // prev iter's PV reads of Vt done before refill
        for (int i = tid; i < 64 * 16; i += 128) {
            int r = i >> 4, j = i & 15;
            float4 kv = *(const float4*)&kbase[(size_t)(j0 + r) * RS + j * 4];
            float4 vv = *(const float4*)&vbase[(size_t)(j0 + r) * RS + j * 4];
            float k4[4] = {kv.x, kv.y, kv.z, kv.w};
            float hi[4], lo[4];
            #pragma unroll
            for (int c = 0; c < 4; c++) {
                __nv_bfloat16 hb = __float2bfloat16(k4[c]);
                hi[c] = __bfloat162float(hb);
                lo[c] = k4[c] - hi[c];
            }
            uint2 uh = {bf2(hi[0], hi[1]), bf2(hi[2], hi[3])};
            uint2 ul = {bf2(lo[0], lo[1]), bf2(lo[2], lo[3])};
            *(uint2*)&Kh[r * P2B + 2 * j] = uh;
            *(uint2*)&Kl[r * P2B + 2 * j] = ul;
            uint4 uv = {f2tf32(vv.x), f2tf32(vv.y), f2tf32(vv.z), f2tf32(vv.w)};
            *(uint4*)&Vt[r * PVP + 4 * j] = uv;
        }
        __syncthreads();

        // ---- S = Q K^T (split-bf16, m16n8k16) ----
        float s[8][4];
        #pragma unroll
        for (int nj = 0; nj < 8; nj++)
            #pragma unroll
            for (int c = 0; c < 4; c++) s[nj][c] = 0.f;

        #pragma unroll
        for (int kw = 0; kw < 32; kw += 8) {
            uint32_t ah[4], al[4];
            ah[0] = Qh[rowA * P2B + kw + tig];
            ah[1] = Qh[rowB * P2B + kw + tig];
            ah[2] = Qh[rowA * P2B + kw + tig + 4];
            ah[3] = Qh[rowB * P2B + kw + tig + 4];
            al[0] = Ql[rowA * P2B + kw + tig];
            al[1] = Ql[rowB * P2B + kw + tig];
            al[2] = Ql[rowA * P2B + kw + tig + 4];
            al[3] = Ql[rowB * P2B + kw + tig + 4];
            #pragma unroll
            for (int nj = 0; nj < 8; nj++) {
                int kr = nj * 8 + g;
                uint32_t bh2[2] = {Kh[kr * P2B + kw + tig], Kh[kr * P2B + kw + tig + 4]};
                uint32_t bl2[2] = {Kl[kr * P2B + kw + tig], Kl[kr * P2B + kw + tig + 4]};
                mma_bf16(s[nj], ah, bh2);
                mma_bf16(s[nj], al, bh2);
                mma_bf16(s[nj], ah, bl2);
            }
        }

        if (j0 == q0) {
            #pragma unroll
            for (int nj = 0; nj < 8; nj++) {
                int k0c = nj * 8 + 2 * tig;
                if (k0c     > rowA) s[nj][0] = -1e30f;
                if (k0c + 1 > rowA) s[nj][1] = -1e30f;
                if (k0c     > rowB) s[nj][2] = -1e30f;
                if (k0c + 1 > rowB) s[nj][3] = -1e30f;
            }
        }

        // ---- online softmax in registers ----
        float mx0 = m0, mx1 = m1;
        #pragma unroll
        for (int nj = 0; nj < 8; nj++) {
            mx0 = fmaxf(mx0, fmaxf(s[nj][0], s[nj][1]));
            mx1 = fmaxf(mx1, fmaxf(s[nj][2], s[nj][3]));
        }
        mx0 = fmaxf(mx0, __shfl_xor_sync(0xffffffffu, mx0, 1));
        mx0 = fmaxf(mx0, __shfl_xor_sync(0xffffffffu, mx0, 2));
        mx1 = fmaxf(mx1, __shfl_xor_sync(0xffffffffu, mx1, 1));
        mx1 = fmaxf(mx1, __shfl_xor_sync(0xffffffffu, mx1, 2));

        float fac0 = __expf(m0 - mx0), fac1 = __expf(m1 - mx1);
        float sum0 = 0.f, sum1 = 0.f;
        #pragma unroll
        for (int nj = 0; nj < 8; nj++) {
            s[nj][0] = __expf(s[nj][0] - mx0);
            s[nj][1] = __expf(s[nj][1] - mx0);
            s[nj][2] = __expf(s[nj][2] - mx1);
            s[nj][3] = __expf(s[nj][3] - mx1);
            sum0 += s[nj][0] + s[nj][1];
            sum1 += s[nj][2] + s[nj][3];
        }
        sum0 += __shfl_xor_sync(0xffffffffu, sum0, 1);
        sum0 += __shfl_xor_sync(0xffffffffu, sum0, 2);
        sum1 += __shfl_xor_sync(0xffffffffu, sum1, 1);
        sum1 += __shfl_xor_sync(0xffffffffu, sum1, 2);
        l0 = l0 * fac0 + sum0;
        l1 = l1 * fac1 + sum1;
        m0 = mx0; m1 = mx1;
        #pragma unroll
        for (int nj = 0; nj < 8; nj++) {
            o[nj][0] *= fac0; o[nj][1] *= fac0;
            o[nj][2] *= fac1; o[nj][3] *= fac1;
        }

        // Ps is dedicated + rows warp-private: no block barrier needed
        #pragma unroll
        for (int nj = 0; nj < 8; nj++) {
            int cc = nj * 8 + 2 * tig;
            uint2 pa = {f2tf32(s[nj][0]), f2tf32(s[nj][1])};
            uint2 pb = {f2tf32(s[nj][2]), f2tf32(s[nj][3])};
            *(uint2*)&Ps[rowA * PVP + cc] = pa;
            *(uint2*)&Ps[rowB * PVP + cc] = pb;
        }
        __syncwarp();

        // ---- O += P V (single tf32, m16n8k8) ----
        #pragma unroll
        for (int k8 = 0; k8 < 64; k8 += 8) {
            uint32_t a[4];
            a[0] = Ps[rowA * PVP + k8 + tig];
            a[1] = Ps[rowB * PVP + k8 + tig];
            a[2] = Ps[rowA * PVP + k8 + tig + 4];
            a[3] = Ps[rowB * PVP + k8 + tig + 4];
            #pragma unroll
            for (int nj = 0; nj < 8; nj++) {
                uint32_t bv[2] = {Vt[(k8 + tig) * PVP + nj * 8 + g],
                                  Vt[(k8 + tig + 4) * PVP + nj * 8 + g]};
                mma_tf32(o[nj], a, bv);
            }
        }
    }

    float inv0 = 1.f / l0, inv1 = 1.f / l1;
    size_t rA = (size_t)(b * TLEN + q0 + rowA) * DMODEL + h * HDIM;
    size_t rB = (size_t)(b * TLEN + q0 + rowB) * DMODEL + h * HDIM;
    #pragma unroll
    for (int nj = 0; nj < 8; nj++) {
        int cc = nj * 8 + 2 * tig;
        out[rA + cc]     = o[nj][0] * inv0;
        out[rA + cc + 1] = o[nj][1] * inv0;
        out[rB + cc]     = o[nj][2] * inv1;
        out[rB + cc + 1] = o[nj][3] * inv1;
    }
}

// ---------------- driver ----------------------------------------------------
extern "C" void kernel_launch(void* const* d_in, const int* in_sizes, int n_in,
                              void* d_out, int out_size) {
    const float* wte    = (const float*)d_in[0];
    const float* wpe    = (const float*)d_in[1];
    const float* ln1_w  = (const float*)d_in[2];
    const float* ln1_b  = (const float*)d_in[3];
    const float* attn_w = (const float*)d_in[4];
    const float* attn_b = (const float*)d_in[5];
    const float* proj_w = (const float*)d_in[6];
    const float* proj_b = (const float*)d_in[7];
    const float* ln2_w  = (const float*)d_in[8];
    const float* ln2_b  = (const float*)d_in[9];
    const float* fc_w   = (const float*)d_in[10];
    const float* fc_b   = (const float*)d_in[11];
    const float* fc2_w  = (const float*)d_in[12];
    const float* fc2_b  = (const float*)d_in[13];
    const float* lnf_w  = (const float*)d_in[14];
    const float* lnf_b  = (const float*)d_in[15];
    const int*   idx    = (const int*)d_in[16];
    float* out = (float*)d_out;

    void *px, *ph, *pqkv, *patt, *pfc;
    cudaGetSymbolAddress(&px, g_x);
    cudaGetSymbolAddress(&ph, g_h);
    cudaGetSymbolAddress(&pqkv, g_qkv);
    cudaGetSymbolAddress(&patt, g_att);
    cudaGetSymbolAddress(&pfc, g_fc);
    float* x   = (float*)px;
    float* h   = (float*)ph;
    float* qkv = (float*)pqkv;
    float* att = (float*)patt;
    float* fcb = (float*)pfc;

    cudaFuncSetAttribute(attn_tc_kernel,
                         cudaFuncAttributeMaxDynamicSharedMemorySize, ATTN_SMEM_TC);

    embed_kernel<<<MROWS, 256>>>(wte, wpe, idx, x);

    for (int l = 0; l < NLAYER; l++) {
        const float* aw  = attn_w + (size_t)l * DMODEL * 3 * DMODEL;
        const float* ab  = attn_b + (size_t)l * 3 * DMODEL;
        const float* pw  = proj_w + (size_t)l * DMODEL * DMODEL;
        const float* pb  = proj_b + (size_t)l * DMODEL;
        const float* fw  = fc_w   + (size_t)l * DMODEL * 4 * DMODEL;
        const float* fb  = fc_b   + (size_t)l * 4 * DMODEL;
        const float* f2w = fc2_w  + (size_t)l * 4 * DMODEL * DMODEL;
        const float* f2b = fc2_b  + (size_t)l * DMODEL;

        ln_kernel<<<MROWS, 256>>>(x, ln1_w + l * DMODEL, ln1_b + l * DMODEL, h);
        gemm_tf32<false><<<dim3(3 * DMODEL / 128, MROWS / 128), 256>>>(
            h, aw, ab, nullptr, qkv, MROWS, 3 * DMODEL, DMODEL, 0);
        attn_tc_kernel<<<dim3(TLEN / 64, BATCH * NHEAD), 128, ATTN_SMEM_TC>>>(qkv, att);
        // proj: N=512 -> 64-row tiles, 256 CTAs (vs 128)
        gemm_tf32_m64<<<dim3(DMODEL / 128, MROWS / 64), 256>>>(
            att, pw, pb, x, x, MROWS, DMODEL, DMODEL, 0);
        ln_kernel<<<MROWS, 256>>>(x, ln2_w + l * DMODEL, ln2_b + l * DMODEL, h);
        gemm_tf32<false><<<dim3(4 * DMODEL / 128, MROWS / 128), 256>>>(
            h, fw, fb, nullptr, fcb, MROWS, 4 * DMODEL, DMODEL, 1);
        // fc2: N=512 -> 64-row tiles
        gemm_tf32_m64<<<dim3(DMODEL / 128, MROWS / 64), 256>>>(
            fcb, f2w, f2b, x, x, MROWS, DMODEL, 4 * DMODEL, 0);
    }

    ln_kernel<<<MROWS, 256>>>(x, lnf_w, lnf_b, h);
    gemm_tf32<true><<<dim3(MROWS / 128, VOCAB / 128), 256>>>(
        h, wte, nullptr, nullptr, out, MROWS, VOCAB, DMODEL, 0);
}

// round 13
// speedup vs baseline: 2.3516x; 1.2583x over previous
#include <cuda_runtime.h>
#include <cuda_bf16.h>
#include <math.h>
#include <stdint.h>

// ---------------- problem constants ----------------
#define NLAYER 4
#define NHEAD  8
#define DMODEL 512
#define TLEN   2048
#define BATCH  2
#define VOCAB  32000
#define HDIM   64
#define MROWS  (BATCH * TLEN)   // 4096
#define EPS    1e-5f

// ---------------- scratch (static device globals; no allocs allowed) -------
__device__ float g_x  [MROWS * DMODEL];
__device__ float g_h  [MROWS * DMODEL];
__device__ float g_qkv[MROWS * 3 * DMODEL];
__device__ float g_att[MROWS * DMODEL];
__device__ float g_fc [MROWS * 4 * DMODEL];

// ---------------- embedding ----------------
__global__ void embed_kernel(const float* __restrict__ wte,
                             const float* __restrict__ wpe,
                             const int*   __restrict__ idx,
                             float* __restrict__ x) {
    int m = blockIdx.x;
    int t = m % TLEN;
    int tok = idx[m];
    const float* we = wte + (size_t)tok * DMODEL;
    const float* pe = wpe + (size_t)t * DMODEL;
    float* xr = x + (size_t)m * DMODEL;
    for (int d = threadIdx.x; d < DMODEL; d += blockDim.x)
        xr[d] = we[d] + pe[d];
}

// ---------------- layernorm ----------------
__global__ __launch_bounds__(256)
void ln_kernel(const float* __restrict__ x, const float* __restrict__ w,
               const float* __restrict__ b, float* __restrict__ y) {
    int row = blockIdx.x;
    int tid = threadIdx.x;
    const float* xr = x + (size_t)row * DMODEL;
    float v0 = xr[tid];
    float v1 = xr[tid + 256];

    __shared__ float red[8];
    __shared__ float bc;

    float s = v0 + v1;
    #pragma unroll
    for (int o = 16; o; o >>= 1) s += __shfl_xor_sync(0xffffffffu, s, o);
    if ((tid & 31) == 0) red[tid >> 5] = s;
    __syncthreads();
    if (tid == 0) {
        float t = 0.f;
        #pragma unroll
        for (int i = 0; i < 8; i++) t += red[i];
        bc = t;
    }
    __syncthreads();
    float mu = bc * (1.f / DMODEL);
    float d0 = v0 - mu, d1 = v1 - mu;

    float s2 = d0 * d0 + d1 * d1;
    #pragma unroll
    for (int o = 16; o; o >>= 1) s2 += __shfl_xor_sync(0xffffffffu, s2, o);
    __syncthreads();
    if ((tid & 31) == 0) red[tid >> 5] = s2;
    __syncthreads();
    if (tid == 0) {
        float t = 0.f;
        #pragma unroll
        for (int i = 0; i < 8; i++) t += red[i];
        bc = t;
    }
    __syncthreads();
    float inv = rsqrtf(bc * (1.f / DMODEL) + EPS);

    float* yr = y + (size_t)row * DMODEL;
    yr[tid]       = d0 * inv * w[tid]       + b[tid];
    yr[tid + 256] = d1 * inv * w[tid + 256] + b[tid + 256];
}

// ---------------- mma helpers ----------------------------------------------
__device__ __forceinline__ uint32_t f2tf32(float v) {
    uint32_t r;
    asm("cvt.rna.tf32.f32 %0, %1;" : "=r"(r) : "f"(v));
    return r;
}
// pack (lo, hi) floats -> bf16x2 / f16x2 word (lo in lower 16 bits)
__device__ __forceinline__ uint32_t bf2(float lo, float hi) {
    uint32_t r;
    asm("cvt.rn.bf16x2.f32 %0, %1, %2;" : "=r"(r) : "f"(hi), "f"(lo));
    return r;
}
__device__ __forceinline__ uint32_t h2(float lo, float hi) {
    uint32_t r;
    asm("cvt.rn.f16x2.f32 %0, %1, %2;" : "=r"(r) : "f"(hi), "f"(lo));
    return r;
}

__device__ __forceinline__ void mma_tf32(float* d, const uint32_t* a, const uint32_t* b) {
    asm volatile(
        "mma.sync.aligned.m16n8k8.row.col.f32.tf32.tf32.f32 "
        "{%0,%1,%2,%3},{%4,%5,%6,%7},{%8,%9},{%0,%1,%2,%3};\n"
        : "+f"(d[0]), "+f"(d[1]), "+f"(d[2]), "+f"(d[3])
        : "r"(a[0]), "r"(a[1]), "r"(a[2]), "r"(a[3]), "r"(b[0]), "r"(b[1]));
}
__device__ __forceinline__ void mma_bf16(float* d, const uint32_t* a, const uint32_t* b) {
    asm volatile(
        "mma.sync.aligned.m16n8k16.row.col.f32.bf16.bf16.f32 "
        "{%0,%1,%2,%3},{%4,%5,%6,%7},{%8,%9},{%0,%1,%2,%3};\n"
        : "+f"(d[0]), "+f"(d[1]), "+f"(d[2]), "+f"(d[3])
        : "r"(a[0]), "r"(a[1]), "r"(a[2]), "r"(a[3]), "r"(b[0]), "r"(b[1]));
}
__device__ __forceinline__ void mma_fp16(float* d, const uint32_t* a, const uint32_t* b) {
    asm volatile(
        "mma.sync.aligned.m16n8k16.row.col.f32.f16.f16.f32 "
        "{%0,%1,%2,%3},{%4,%5,%6,%7},{%8,%9},{%0,%1,%2,%3};\n"
        : "+f"(d[0]), "+f"(d[1]), "+f"(d[2]), "+f"(d[3])
        : "r"(a[0]), "r"(a[1]), "r"(a[2]), "r"(a[3]), "r"(b[0]), "r"(b[1]));
}

// ---------------- pipelined fp16-k16 tensor-core GEMM ------------------------
// C[M,N] = A[M,K] @ B (+bias) (+resid) (opt gelu).  fp16 inputs (10+1-bit
// mantissa == tf32 precision; all operands O(1) so range is safe), fp32 acc.
// m16n8k16 => HALF the MMA instructions + packed-pair fragments vs tf32-k8.
// Smem (packed f16x2 words):
//   A: [row 0..127][word 0..7] pitch 12 -> frag addr 12g+tig hits all 32 banks
//   B: [kpair 0..7][n 0..127] pitch 136 -> frag addr 8*tig+g hits all 32 banks
#define APH 12
#define BPH 136
template<bool BTRANS>
__global__ __launch_bounds__(256)
void gemm_fp16(const float* __restrict__ A, const float* __restrict__ Bm,
               const float* __restrict__ bias, const float* __restrict__ resid,
               float* __restrict__ Cm, int M, int N, int K, int gelu_flag) {
    __shared__ uint32_t As[2][128 * APH];
    __shared__ uint32_t Bs[2][8 * BPH];

    int tid  = threadIdx.x;
    int lane = tid & 31;
    int w    = tid >> 5;
    int g    = lane >> 2;
    int tig  = lane & 3;
    int wm   = (w >> 2) * 64;
    int wn   = (w & 3) * 32;
    int m0 = (BTRANS ? blockIdx.x : blockIdx.y) * 128;
    int n0 = (BTRANS ? blockIdx.y : blockIdx.x) * 128;

    // A: thread -> rows aR0, aR0+64; k-quad aC0 (words 2c, 2c+1)
    int aR0 = tid >> 2, aR1 = aR0 + 64;
    int aC  = tid & 3;                      // k-quad index; k offset 4*aC
    // B (!BT): kp = tid>>5 (k-pair), nq = tid&31 (n-quad)
    int bKp = tid >> 5, bNq = tid & 31;
    // B (BT): n rows bN0, bN0+64; k-quad bKq
    int bN0 = tid >> 2, bKq = tid & 3;

    float4 arg0, arg1, brg0, brg1;

    auto load_tile = [&](int k0) {
        arg0 = *(const float4*)&A[(size_t)(m0 + aR0) * K + k0 + aC * 4];
        arg1 = *(const float4*)&A[(size_t)(m0 + aR1) * K + k0 + aC * 4];
        if (!BTRANS) {
            brg0 = *(const float4*)&Bm[(size_t)(k0 + 2 * bKp)     * N + n0 + bNq * 4];
            brg1 = *(const float4*)&Bm[(size_t)(k0 + 2 * bKp + 1) * N + n0 + bNq * 4];
        } else {
            brg0 = *(const float4*)&Bm[(size_t)(n0 + bN0)      * K + k0 + bKq * 4];
            brg1 = *(const float4*)&Bm[(size_t)(n0 + bN0 + 64) * K + k0 + bKq * 4];
        }
    };
    auto store_tile = [&](int buf) {
        // A: float4 = k 4c..4c+3 -> words 2c (x,y), 2c+1 (z,w); STS.64
        uint2 a0 = {h2(arg0.x, arg0.y), h2(arg0.z, arg0.w)};
        uint2 a1 = {h2(arg1.x, arg1.y), h2(arg1.z, arg1.w)};
        *(uint2*)&As[buf][aR0 * APH + aC * 2] = a0;
        *(uint2*)&As[buf][aR1 * APH + aC * 2] = a1;
        if (!BTRANS) {
            // pack across the two k rows for 4 consecutive n; STS.128
            uint4 bv = {h2(brg0.x, brg1.x), h2(brg0.y, brg1.y),
                        h2(brg0.z, brg1.z), h2(brg0.w, brg1.w)};
            *(uint4*)&Bs[buf][bKp * BPH + bNq * 4] = bv;
        } else {
            // float4 along K at an n row -> words 2q,2q+1 in k-pair rows
            Bs[buf][(bKq * 2    ) * BPH + bN0]      = h2(brg0.x, brg0.y);
            Bs[buf][(bKq * 2 + 1) * BPH + bN0]      = h2(brg0.z, brg0.w);
            Bs[buf][(bKq * 2    ) * BPH + bN0 + 64] = h2(brg1.x, brg1.y);
            Bs[buf][(bKq * 2 + 1) * BPH + bN0 + 64] = h2(brg1.z, brg1.w);
        }
    };

    float d[4][4][4];
    #pragma unroll
    for (int i = 0; i < 4; i++)
        #pragma unroll
        for (int j = 0; j < 4; j++)
            #pragma unroll
            for (int r = 0; r < 4; r++) d[i][j][r] = 0.f;

    load_tile(0);
    store_tile(0);
    __syncthreads();

    int buf = 0;
    for (int k0 = 0; k0 < K; k0 += 16) {
        int nk = k0 + 16;
        if (nk < K) load_tile(nk);

        const uint32_t* Ac = As[buf];
        const uint32_t* Bc = Bs[buf];
        uint32_t af[4][4];
        #pragma unroll
        for (int mi = 0; mi < 4; mi++) {
            int rb = wm + mi * 16;
            af[mi][0] = Ac[(rb + g    ) * APH + tig    ];
            af[mi][1] = Ac[(rb + g + 8) * APH + tig    ];
            af[mi][2] = Ac[(rb + g    ) * APH + tig + 4];
            af[mi][3] = Ac[(rb + g + 8) * APH + tig + 4];
        }
        uint32_t bf[4][2];
        #pragma unroll
        for (int nj = 0; nj < 4; nj++) {
            int cb = wn + nj * 8;
            bf[nj][0] = Bc[(tig    ) * BPH + cb + g];
            bf[nj][1] = Bc[(tig + 4) * BPH + cb + g];
        }
        #pragma unroll
        for (int mi = 0; mi < 4; mi++)
            #pragma unroll
            for (int nj = 0; nj < 4; nj++)
                mma_fp16(d[mi][nj], af[mi], bf[nj]);

        if (nk < K) store_tile(buf ^ 1);
        __syncthreads();
        buf ^= 1;
    }

    #pragma unroll
    for (int mi = 0; mi < 4; mi++) {
        #pragma unroll
        for (int rr = 0; rr < 2; rr++) {
            int m = m0 + wm + mi * 16 + g + rr * 8;
            float* crow = Cm + (size_t)m * N;
            const float* rrow = resid ? resid + (size_t)m * N : nullptr;
            #pragma unroll
            for (int nj = 0; nj < 4; nj++) {
                int n = n0 + wn + nj * 8 + tig * 2;
                #pragma unroll
                for (int cc = 0; cc < 2; cc++) {
                    float c = d[mi][nj][rr * 2 + cc];
                    if (bias) c += bias[n + cc];
                    if (rrow) c += rrow[n + cc];
                    if (gelu_flag)
                        c = 0.5f * c * (1.f + erff(c * 0.70710678118654752f));
                    crow[n + cc] = c;
                }
            }
        }
    }
}

// ---------------- fp16-k16 GEMM, 64x128 tile (N=512 shapes) ------------------
__global__ __launch_bounds__(256)
void gemm_fp16_m64(const float* __restrict__ A, const float* __restrict__ Bm,
                   const float* __restrict__ bias, const float* __restrict__ resid,
                   float* __restrict__ Cm, int M, int N, int K, int gelu_flag) {
    __shared__ uint32_t As[2][64 * APH];
    __shared__ uint32_t Bs[2][8 * BPH];

    int tid  = threadIdx.x;
    int lane = tid & 31;
    int w    = tid >> 5;
    int g    = lane >> 2;
    int tig  = lane & 3;
    int wn   = w * 16;                 // 8 warps across N
    int m0 = blockIdx.y * 64;
    int n0 = blockIdx.x * 128;

    int aR0 = tid >> 2, aC = tid & 3;  // 64 rows: exactly 1 float4/thread
    int bKp = tid >> 5, bNq = tid & 31;

    float4 arg0, brg0, brg1;

    auto load_tile = [&](int k0) {
        arg0 = *(const float4*)&A[(size_t)(m0 + aR0) * K + k0 + aC * 4];
        brg0 = *(const float4*)&Bm[(size_t)(k0 + 2 * bKp)     * N + n0 + bNq * 4];
        brg1 = *(const float4*)&Bm[(size_t)(k0 + 2 * bKp + 1) * N + n0 + bNq * 4];
    };
    auto store_tile = [&](int buf) {
        uint2 a0 = {h2(arg0.x, arg0.y), h2(arg0.z, arg0.w)};
        *(uint2*)&As[buf][aR0 * APH + aC * 2] = a0;
        uint4 bv = {h2(brg0.x, brg1.x), h2(brg0.y, brg1.y),
                    h2(brg0.z, brg1.z), h2(brg0.w, brg1.w)};
        *(uint4*)&Bs[buf][bKp * BPH + bNq * 4] = bv;
    };

    float d[4][2][4];
    #pragma unroll
    for (int i = 0; i < 4; i++)
        #pragma unroll
        for (int j = 0; j < 2; j++)
            #pragma unroll
            for (int r = 0; r < 4; r++) d[i][j][r] = 0.f;

    load_tile(0);
    store_tile(0);
    __syncthreads();

    int buf = 0;
    for (int k0 = 0; k0 < K; k0 += 16) {
        int nk = k0 + 16;
        if (nk < K) load_tile(nk);

        const uint32_t* Ac = As[buf];
        const uint32_t* Bc = Bs[buf];
        uint32_t af[4][4];
        #pragma unroll
        for (int mi = 0; mi < 4; mi++) {
            int rb = mi * 16;
            af[mi][0] = Ac[(rb + g    ) * APH + tig    ];
            af[mi][1] = Ac[(rb + g + 8) * APH + tig    ];
            af[mi][2] = Ac[(rb + g    ) * APH + tig + 4];
            af[mi][3] = Ac[(rb + g + 8) * APH + tig + 4];
        }
        uint32_t bf[2][2];
        #pragma unroll
        for (int nj = 0; nj < 2; nj++) {
            int cb = wn + nj * 8;
            bf[nj][0] = Bc[(tig    ) * BPH + cb + g];
            bf[nj][1] = Bc[(tig + 4) * BPH + cb + g];
        }
        #pragma unroll
        for (int mi = 0; mi < 4; mi++)
            #pragma unroll
            for (int nj = 0; nj < 2; nj++)
                mma_fp16(d[mi][nj], af[mi], bf[nj]);

        if (nk < K) store_tile(buf ^ 1);
        __syncthreads();
        buf ^= 1;
    }

    #pragma unroll
    for (int mi = 0; mi < 4; mi++) {
        #pragma unroll
        for (int rr = 0; rr < 2; rr++) {
            int m = m0 + mi * 16 + g + rr * 8;
            float* crow = Cm + (size_t)m * N;
            const float* rrow = resid ? resid + (size_t)m * N : nullptr;
            #pragma unroll
            for (int nj = 0; nj < 2; nj++) {
                int n = n0 + wn + nj * 8 + tig * 2;
                #pragma unroll
                for (int cc = 0; cc < 2; cc++) {
                    float c = d[mi][nj][rr * 2 + cc];
                    if (bias) c += bias[n + cc];
                    if (rrow) c += rrow[n + cc];
                    if (gelu_flag)
                        c = 0.5f * c * (1.f + erff(c * 0.70710678118654752f));
                    crow[n + cc] = c;
                }
            }
        }
    }
}

// ---------------- tensor-core causal flash attention (round-12 proven) -------
#define P2B 36
#define PVP 72
#define ATTN_SMEM_TC ((4 * 64 * P2B + 2 * 64 * PVP) * (int)sizeof(uint32_t)) // 73728

__global__ __launch_bounds__(128)
void attn_tc_kernel(const float* __restrict__ qkv, float* __restrict__ out) {
    extern __shared__ uint32_t smu[];
    uint32_t* Qh = smu;
    uint32_t* Ql = Qh + 64 * P2B;
    uint32_t* Kh = Ql + 64 * P2B;
    uint32_t* Kl = Kh + 64 * P2B;
    uint32_t* Vt = Kl + 64 * P2B;
    uint32_t* Ps = Vt + 64 * PVP;

    int tid  = threadIdx.x;
    int lane = tid & 31;
    int wid  = tid >> 5;
    int g    = lane >> 2;
    int tig  = lane & 3;
    int b = blockIdx.y >> 3, h = blockIdx.y & 7;
    int q0 = blockIdx.x * 64;
    const int RS = 3 * DMODEL;
    const float* qbase = qkv + (size_t)b * TLEN * RS + h * HDIM;
    const float* kbase = qbase + DMODEL;
    const float* vbase = qbase + 2 * DMODEL;

    for (int i = tid; i < 64 * 16; i += 128) {
        int r = i >> 4, j = i & 15;
        float4 v = *(const float4*)&qbase[(size_t)(q0 + r) * RS + j * 4];
        float q4[4] = {v.x * 0.125f, v.y * 0.125f, v.z * 0.125f, v.w * 0.125f};
        float hi[4], lo[4];
        #pragma unroll
        for (int c = 0; c < 4; c++) {
            __nv_bfloat16 hb = __float2bfloat16(q4[c]);
            hi[c] = __bfloat162float(hb);
            lo[c] = q4[c] - hi[c];
        }
        uint2 uh = {bf2(hi[0], hi[1]), bf2(hi[2], hi[3])};
        uint2 ul = {bf2(lo[0], lo[1]), bf2(lo[2], lo[3])};
        *(uint2*)&Qh[r * P2B + 2 * j] = uh;
        *(uint2*)&Ql[r * P2B + 2 * j] = ul;
    }

    float o[8][4];
    #pragma unroll
    for (int nj = 0; nj < 8; nj++)
        #pragma unroll
        for (int c = 0; c < 4; c++) o[nj][c] = 0.f;
    float m0 = -1e30f, m1 = -1e30f, l0 = 0.f, l1 = 0.f;
    int wrow = wid * 16;
    int rowA = wrow + g, rowB = wrow + g + 8;

    for (int j0 = 0; j0 <= q0; j0 += 64) {
        __syncthreads();
        for (int i = tid; i < 64 * 16; i += 128) {
            int r = i >> 4, j = i & 15;
            float4 kv = *(const float4*)&kbase[(size_t)(j0 + r) * RS + j * 4];
            float4 vv = *(const float4*)&vbase[(size_t)(j0 + r) * RS + j * 4];
            float k4[4] = {kv.x, kv.y, kv.z, kv.w};
            float hi[4], lo[4];
            #pragma unroll
            for (int c = 0; c < 4; c++) {
                __nv_bfloat16 hb = __float2bfloat16(k4[c]);
                hi[c] = __bfloat162float(hb);
                lo[c] = k4[c] - hi[c];
            }
            uint2 uh = {bf2(hi[0], hi[1]), bf2(hi[2], hi[3])};
            uint2 ul = {bf2(lo[0], lo[1]), bf2(lo[2], lo[3])};
            *(uint2*)&Kh[r * P2B + 2 * j] = uh;
            *(uint2*)&Kl[r * P2B + 2 * j] = ul;
            uint4 uv = {f2tf32(vv.x), f2tf32(vv.y), f2tf32(vv.z), f2tf32(vv.w)};
            *(uint4*)&Vt[r * PVP + 4 * j] = uv;
        }
        __syncthreads();

        float s[8][4];
        #pragma unroll
        for (int nj = 0; nj < 8; nj++)
            #pragma unroll
            for (int c = 0; c < 4; c++) s[nj][c] = 0.f;

        #pragma unroll
        for (int kw = 0; kw < 32; kw += 8) {
            uint32_t ah[4], al[4];
            ah[0] = Qh[rowA * P2B + kw + tig];
            ah[1] = Qh[rowB * P2B + kw + tig];
            ah[2] = Qh[rowA * P2B + kw + tig + 4];
            ah[3] = Qh[rowB * P2B + kw + tig + 4];
            al[0] = Ql[rowA * P2B + kw + tig];
            al[1] = Ql[rowB * P2B + kw + tig];
            al[2] = Ql[rowA * P2B + kw + tig + 4];
            al[3] = Ql[rowB * P2B + kw + tig + 4];
            #pragma unroll
            for (int nj = 0; nj < 8; nj++) {
                int kr = nj * 8 + g;
                uint32_t bh2[2] = {Kh[kr * P2B + kw + tig], Kh[kr * P2B + kw + tig + 4]};
                uint32_t bl2[2] = {Kl[kr * P2B + kw + tig], Kl[kr * P2B + kw + tig + 4]};
                mma_bf16(s[nj], ah, bh2);
                mma_bf16(s[nj], al, bh2);
                mma_bf16(s[nj], ah, bl2);
            }
        }

        if (j0 == q0) {
            #pragma unroll
            for (int nj = 0; nj < 8; nj++) {
                int k0c = nj * 8 + 2 * tig;
                if (k0c     > rowA) s[nj][0] = -1e30f;
                if (k0c + 1 > rowA) s[nj][1] = -1e30f;
                if (k0c     > rowB) s[nj][2] = -1e30f;
                if (k0c + 1 > rowB) s[nj][3] = -1e30f;
            }
        }

        float mx0 = m0, mx1 = m1;
        #pragma unroll
        for (int nj = 0; nj < 8; nj++) {
            mx0 = fmaxf(mx0, fmaxf(s[nj][0], s[nj][1]));
            mx1 = fmaxf(mx1, fmaxf(s[nj][2], s[nj][3]));
        }
        mx0 = fmaxf(mx0, __shfl_xor_sync(0xffffffffu, mx0, 1));
        mx0 = fmaxf(mx0, __shfl_xor_sync(0xffffffffu, mx0, 2));
        mx1 = fmaxf(mx1, __shfl_xor_sync(0xffffffffu, mx1, 1));
        mx1 = fmaxf(mx1, __shfl_xor_sync(0xffffffffu, mx1, 2));

        float fac0 = __expf(m0 - mx0), fac1 = __expf(m1 - mx1);
        float sum0 = 0.f, sum1 = 0.f;
        #pragma unroll
        for (int nj = 0; nj < 8; nj++) {
            s[nj][0] = __expf(s[nj][0] - mx0);
            s[nj][1] = __expf(s[nj][1] - mx0);
            s[nj][2] = __expf(s[nj][2] - mx1);
            s[nj][3] = __expf(s[nj][3] - mx1);
            sum0 += s[nj][0] + s[nj][1];
            sum1 += s[nj][2] + s[nj][3];
        }
        sum0 += __shfl_xor_sync(0xffffffffu, sum0, 1);
        sum0 += __shfl_xor_sync(0xffffffffu, sum0, 2);
        sum1 += __shfl_xor_sync(0xffffffffu, sum1, 1);
        sum1 += __shfl_xor_sync(0xffffffffu, sum1, 2);
        l0 = l0 * fac0 + sum0;
        l1 = l1 * fac1 + sum1;
        m0 = mx0; m1 = mx1;
        #pragma unroll
        for (int nj = 0; nj < 8; nj++) {
            o[nj][0] *= fac0; o[nj][1] *= fac0;
            o[nj][2] *= fac1; o[nj][3] *= fac1;
        }

        #pragma unroll
        for (int nj = 0; nj < 8; nj++) {
            int cc = nj * 8 + 2 * tig;
            uint2 pa = {f2tf32(s[nj][0]), f2tf32(s[nj][1])};
            uint2 pb = {f2tf32(s[nj][2]), f2tf32(s[nj][3])};
            *(uint2*)&Ps[rowA * PVP + cc] = pa;
            *(uint2*)&Ps[rowB * PVP + cc] = pb;
        }
        __syncwarp();

        #pragma unroll
        for (int k8 = 0; k8 < 64; k8 += 8) {
            uint32_t a[4];
            a[0] = Ps[rowA * PVP + k8 + tig];
            a[1] = Ps[rowB * PVP + k8 + tig];
            a[2] = Ps[rowA * PVP + k8 + tig + 4];
            a[3] = Ps[rowB * PVP + k8 + tig + 4];
            #pragma unroll
            for (int nj = 0; nj < 8; nj++) {
                uint32_t bv[2] = {Vt[(k8 + tig) * PVP + nj * 8 + g],
                                  Vt[(k8 + tig + 4) * PVP + nj * 8 + g]};
                mma_tf32(o[nj], a, bv);
            }
        }
    }

    float inv0 = 1.f / l0, inv1 = 1.f / l1;
    size_t rA = (size_t)(b * TLEN + q0 + rowA) * DMODEL + h * HDIM;
    size_t rB = (size_t)(b * TLEN + q0 + rowB) * DMODEL + h * HDIM;
    #pragma unroll
    for (int nj = 0; nj < 8; nj++) {
        int cc = nj * 8 + 2 * tig;
        out[rA + cc]     = o[nj][0] * inv0;
        out[rA + cc + 1] = o[nj][1] * inv0;
        out[rB + cc]     = o[nj][2] * inv1;
        out[rB + cc + 1] = o[nj][3] * inv1;
    }
}

// ---------------- driver ----------------------------------------------------
extern "C" void kernel_launch(void* const* d_in, const int* in_sizes, int n_in,
                              void* d_out, int out_size) {
    const float* wte    = (const float*)d_in[0];
    const float* wpe    = (const float*)d_in[1];
    const float* ln1_w  = (const float*)d_in[2];
    const float* ln1_b  = (const float*)d_in[3];
    const float* attn_w = (const float*)d_in[4];
    const float* attn_b = (const float*)d_in[5];
    const float* proj_w = (const float*)d_in[6];
    const float* proj_b = (const float*)d_in[7];
    const float* ln2_w  = (const float*)d_in[8];
    const float* ln2_b  = (const float*)d_in[9];
    const float* fc_w   = (const float*)d_in[10];
    const float* fc_b   = (const float*)d_in[11];
    const float* fc2_w  = (const float*)d_in[12];
    const float* fc2_b  = (const float*)d_in[13];
    const float* lnf_w  = (const float*)d_in[14];
    const float* lnf_b  = (const float*)d_in[15];
    const int*   idx    = (const int*)d_in[16];
    float* out = (float*)d_out;

    void *px, *ph, *pqkv, *patt, *pfc;
    cudaGetSymbolAddress(&px, g_x);
    cudaGetSymbolAddress(&ph, g_h);
    cudaGetSymbolAddress(&pqkv, g_qkv);
    cudaGetSymbolAddress(&patt, g_att);
    cudaGetSymbolAddress(&pfc, g_fc);
    float* x   = (float*)px;
    float* h   = (float*)ph;
    float* qkv = (float*)pqkv;
    float* att = (float*)patt;
    float* fcb = (float*)pfc;

    cudaFuncSetAttribute(attn_tc_kernel,
                         cudaFuncAttributeMaxDynamicSharedMemorySize, ATTN_SMEM_TC);

    embed_kernel<<<MROWS, 256>>>(wte, wpe, idx, x);

    for (int l = 0; l < NLAYER; l++) {
        const float* aw  = attn_w + (size_t)l * DMODEL * 3 * DMODEL;
        const float* ab  = attn_b + (size_t)l * 3 * DMODEL;
        const float* pw  = proj_w + (size_t)l * DMODEL * DMODEL;
        const float* pb  = proj_b + (size_t)l * DMODEL;
        const float* fw  = fc_w   + (size_t)l * DMODEL * 4 * DMODEL;
        const float* fb  = fc_b   + (size_t)l * 4 * DMODEL;
        const float* f2w = fc2_w  + (size_t)l * 4 * DMODEL * DMODEL;
        const float* f2b = fc2_b  + (size_t)l * DMODEL;

        ln_kernel<<<MROWS, 256>>>(x, ln1_w + l * DMODEL, ln1_b + l * DMODEL, h);
        gemm_fp16<false><<<dim3(3 * DMODEL / 128, MROWS / 128), 256>>>(
            h, aw, ab, nullptr, qkv, MROWS, 3 * DMODEL, DMODEL, 0);
        attn_tc_kernel<<<dim3(TLEN / 64, BATCH * NHEAD), 128, ATTN_SMEM_TC>>>(qkv, att);
        gemm_fp16_m64<<<dim3(DMODEL / 128, MROWS / 64), 256>>>(
            att, pw, pb, x, x, MROWS, DMODEL, DMODEL, 0);
        ln_kernel<<<MROWS, 256>>>(x, ln2_w + l * DMODEL, ln2_b + l * DMODEL, h);
        gemm_fp16<false><<<dim3(4 * DMODEL / 128, MROWS / 128), 256>>>(
            h, fw, fb, nullptr, fcb, MROWS, 4 * DMODEL, DMODEL, 1);
        gemm_fp16_m64<<<dim3(DMODEL / 128, MROWS / 64), 256>>>(
            fcb, f2w, f2b, x, x, MROWS, DMODEL, 4 * DMODEL, 0);
    }

    ln_kernel<<<MROWS, 256>>>(x, lnf_w, lnf_b, h);
    gemm_fp16<true><<<dim3(MROWS / 128, VOCAB / 128), 256>>>(
        h, wte, nullptr, nullptr, out, MROWS, VOCAB, DMODEL, 0);
}

// round 15
// speedup vs baseline: 2.5607x; 1.0889x over previous
#include <cuda_runtime.h>
#include <cuda_bf16.h>
#include <math.h>
#include <stdint.h>

// ---------------- problem constants ----------------
#define NLAYER 4
#define NHEAD  8
#define DMODEL 512
#define TLEN   2048
#define BATCH  2
#define VOCAB  32000
#define HDIM   64
#define MROWS  (BATCH * TLEN)   // 4096
#define EPS    1e-5f

// ---------------- scratch (static device globals; no allocs allowed) -------
__device__ float g_x  [MROWS * DMODEL];
__device__ float g_h  [MROWS * DMODEL];
__device__ float g_qkv[MROWS * 3 * DMODEL];
__device__ float g_att[MROWS * DMODEL];
__device__ float g_fc [MROWS * 4 * DMODEL];

// ---------------- embedding ----------------
__global__ void embed_kernel(const float* __restrict__ wte,
                             const float* __restrict__ wpe,
                             const int*   __restrict__ idx,
                             float* __restrict__ x) {
    int m = blockIdx.x;
    int t = m % TLEN;
    int tok = idx[m];
    const float* we = wte + (size_t)tok * DMODEL;
    const float* pe = wpe + (size_t)t * DMODEL;
    float* xr = x + (size_t)m * DMODEL;
    for (int d = threadIdx.x; d < DMODEL; d += blockDim.x)
        xr[d] = we[d] + pe[d];
}

// ---------------- layernorm ----------------
__global__ __launch_bounds__(256)
void ln_kernel(const float* __restrict__ x, const float* __restrict__ w,
               const float* __restrict__ b, float* __restrict__ y) {
    int row = blockIdx.x;
    int tid = threadIdx.x;
    const float* xr = x + (size_t)row * DMODEL;
    float v0 = xr[tid];
    float v1 = xr[tid + 256];

    __shared__ float red[8];
    __shared__ float bc;

    float s = v0 + v1;
    #pragma unroll
    for (int o = 16; o; o >>= 1) s += __shfl_xor_sync(0xffffffffu, s, o);
    if ((tid & 31) == 0) red[tid >> 5] = s;
    __syncthreads();
    if (tid == 0) {
        float t = 0.f;
        #pragma unroll
        for (int i = 0; i < 8; i++) t += red[i];
        bc = t;
    }
    __syncthreads();
    float mu = bc * (1.f / DMODEL);
    float d0 = v0 - mu, d1 = v1 - mu;

    float s2 = d0 * d0 + d1 * d1;
    #pragma unroll
    for (int o = 16; o; o >>= 1) s2 += __shfl_xor_sync(0xffffffffu, s2, o);
    __syncthreads();
    if ((tid & 31) == 0) red[tid >> 5] = s2;
    __syncthreads();
    if (tid == 0) {
        float t = 0.f;
        #pragma unroll
        for (int i = 0; i < 8; i++) t += red[i];
        bc = t;
    }
    __syncthreads();
    float inv = rsqrtf(bc * (1.f / DMODEL) + EPS);

    float* yr = y + (size_t)row * DMODEL;
    yr[tid]       = d0 * inv * w[tid]       + b[tid];
    yr[tid + 256] = d1 * inv * w[tid + 256] + b[tid + 256];
}

// ---------------- mma helpers ----------------------------------------------
__device__ __forceinline__ uint32_t f2tf32(float v) {
    uint32_t r;
    asm("cvt.rna.tf32.f32 %0, %1;" : "=r"(r) : "f"(v));
    return r;
}
__device__ __forceinline__ uint32_t bf2(float lo, float hi) {
    uint32_t r;
    asm("cvt.rn.bf16x2.f32 %0, %1, %2;" : "=r"(r) : "f"(hi), "f"(lo));
    return r;
}
__device__ __forceinline__ uint32_t h2(float lo, float hi) {
    uint32_t r;
    asm("cvt.rn.f16x2.f32 %0, %1, %2;" : "=r"(r) : "f"(hi), "f"(lo));
    return r;
}

__device__ __forceinline__ void mma_bf16(float* d, const uint32_t* a, const uint32_t* b) {
    asm volatile(
        "mma.sync.aligned.m16n8k16.row.col.f32.bf16.bf16.f32 "
        "{%0,%1,%2,%3},{%4,%5,%6,%7},{%8,%9},{%0,%1,%2,%3};\n"
        : "+f"(d[0]), "+f"(d[1]), "+f"(d[2]), "+f"(d[3])
        : "r"(a[0]), "r"(a[1]), "r"(a[2]), "r"(a[3]), "r"(b[0]), "r"(b[1]));
}
__device__ __forceinline__ void mma_fp16(float* d, const uint32_t* a, const uint32_t* b) {
    asm volatile(
        "mma.sync.aligned.m16n8k16.row.col.f32.f16.f16.f32 "
        "{%0,%1,%2,%3},{%4,%5,%6,%7},{%8,%9},{%0,%1,%2,%3};\n"
        : "+f"(d[0]), "+f"(d[1]), "+f"(d[2]), "+f"(d[3])
        : "r"(a[0]), "r"(a[1]), "r"(a[2]), "r"(a[3]), "r"(b[0]), "r"(b[1]));
}

// ---------------- pipelined fp16 GEMM, BK=32, 128x128 tile -------------------
// C[M,N] = A[M,K] @ B (+bias) (+resid) (opt gelu). fp16 inputs, fp32 acc.
// 32-deep k-slab per smem stage: 2 x k16 MMA blocks per __syncthreads
// (halves barrier count vs BK=16 and amortizes fragment loads).
// Smem (f16x2 words): A [row][16 words] pitch 20; B [kpair 0..15][n] pitch 136.
#define APH 20
#define BPH 136
template<bool BTRANS>
__global__ __launch_bounds__(256)
void gemm_fp16(const float* __restrict__ A, const float* __restrict__ Bm,
               const float* __restrict__ bias, const float* __restrict__ resid,
               float* __restrict__ Cm, int M, int N, int K, int gelu_flag) {
    __shared__ uint32_t As[2][128 * APH];
    __shared__ uint32_t Bs[2][16 * BPH];

    int tid  = threadIdx.x;
    int lane = tid & 31;
    int w    = tid >> 5;
    int g    = lane >> 2;
    int tig  = lane & 3;
    int wm   = (w >> 2) * 64;
    int wn   = (w & 3) * 32;
    int m0 = (BTRANS ? blockIdx.x : blockIdx.y) * 128;
    int n0 = (BTRANS ? blockIdx.y : blockIdx.x) * 128;

    // A: 4 float4/thread: idx = tid + s*256 -> r = idx>>3 (0..127), q = idx&7
    int aR[4], aQ[4];
    #pragma unroll
    for (int s = 0; s < 4; s++) { int idx = tid + s * 256; aR[s] = idx >> 3; aQ[s] = idx & 7; }
    // B (!BT): 2 kpairs/thread: kp = tid>>5 + s*8, nq = tid&31 (2 loads each)
    int bKp0 = tid >> 5, bNq = tid & 31;
    // B (BT): 4 float4/thread: n = idx>>3 (0..127), q = idx&7
    int bN[4], bQ[4];
    #pragma unroll
    for (int s = 0; s < 4; s++) { int idx = tid + s * 256; bN[s] = idx >> 3; bQ[s] = idx & 7; }

    float4 arg[4], brg[4];

    auto load_tile = [&](int k0) {
        #pragma unroll
        for (int s = 0; s < 4; s++)
            arg[s] = *(const float4*)&A[(size_t)(m0 + aR[s]) * K + k0 + aQ[s] * 4];
        if (!BTRANS) {
            #pragma unroll
            for (int s = 0; s < 2; s++) {
                int kp = bKp0 + s * 8;
                brg[2 * s]     = *(const float4*)&Bm[(size_t)(k0 + 2 * kp)     * N + n0 + bNq * 4];
                brg[2 * s + 1] = *(const float4*)&Bm[(size_t)(k0 + 2 * kp + 1) * N + n0 + bNq * 4];
            }
        } else {
            #pragma unroll
            for (int s = 0; s < 4; s++)
                brg[s] = *(const float4*)&Bm[(size_t)(n0 + bN[s]) * K + k0 + bQ[s] * 4];
        }
    };
    auto store_tile = [&](int buf) {
        #pragma unroll
        for (int s = 0; s < 4; s++) {
            uint2 a2 = {h2(arg[s].x, arg[s].y), h2(arg[s].z, arg[s].w)};
            *(uint2*)&As[buf][aR[s] * APH + aQ[s] * 2] = a2;
        }
        if (!BTRANS) {
            #pragma unroll
            for (int s = 0; s < 2; s++) {
                int kp = bKp0 + s * 8;
                float4 b0 = brg[2 * s], b1 = brg[2 * s + 1];
                uint4 bv = {h2(b0.x, b1.x), h2(b0.y, b1.y),
                            h2(b0.z, b1.z), h2(b0.w, b1.w)};
                *(uint4*)&Bs[buf][kp * BPH + bNq * 4] = bv;
            }
        } else {
            #pragma unroll
            for (int s = 0; s < 4; s++) {
                Bs[buf][(bQ[s] * 2    ) * BPH + bN[s]] = h2(brg[s].x, brg[s].y);
                Bs[buf][(bQ[s] * 2 + 1) * BPH + bN[s]] = h2(brg[s].z, brg[s].w);
            }
        }
    };

    float d[4][4][4];
    #pragma unroll
    for (int i = 0; i < 4; i++)
        #pragma unroll
        for (int j = 0; j < 4; j++)
            #pragma unroll
            for (int r = 0; r < 4; r++) d[i][j][r] = 0.f;

    load_tile(0);
    store_tile(0);
    __syncthreads();

    int buf = 0;
    for (int k0 = 0; k0 < K; k0 += 32) {
        int nk = k0 + 32;
        if (nk < K) load_tile(nk);

        const uint32_t* Ac = As[buf];
        const uint32_t* Bc = Bs[buf];
        #pragma unroll
        for (int kb = 0; kb < 2; kb++) {
            uint32_t af[4][4];
            #pragma unroll
            for (int mi = 0; mi < 4; mi++) {
                int rb = wm + mi * 16;
                af[mi][0] = Ac[(rb + g    ) * APH + kb * 8 + tig    ];
                af[mi][1] = Ac[(rb + g + 8) * APH + kb * 8 + tig    ];
                af[mi][2] = Ac[(rb + g    ) * APH + kb * 8 + tig + 4];
                af[mi][3] = Ac[(rb + g + 8) * APH + kb * 8 + tig + 4];
            }
            uint32_t bf[4][2];
            #pragma unroll
            for (int nj = 0; nj < 4; nj++) {
                int cb = wn + nj * 8;
                bf[nj][0] = Bc[(kb * 8 + tig    ) * BPH + cb + g];
                bf[nj][1] = Bc[(kb * 8 + tig + 4) * BPH + cb + g];
            }
            #pragma unroll
            for (int mi = 0; mi < 4; mi++)
                #pragma unroll
                for (int nj = 0; nj < 4; nj++)
                    mma_fp16(d[mi][nj], af[mi], bf[nj]);
        }

        if (nk < K) store_tile(buf ^ 1);
        __syncthreads();
        buf ^= 1;
    }

    #pragma unroll
    for (int mi = 0; mi < 4; mi++) {
        #pragma unroll
        for (int rr = 0; rr < 2; rr++) {
            int m = m0 + wm + mi * 16 + g + rr * 8;
            float* crow = Cm + (size_t)m * N;
            const float* rrow = resid ? resid + (size_t)m * N : nullptr;
            #pragma unroll
            for (int nj = 0; nj < 4; nj++) {
                int n = n0 + wn + nj * 8 + tig * 2;
                #pragma unroll
                for (int cc = 0; cc < 2; cc++) {
                    float c = d[mi][nj][rr * 2 + cc];
                    if (bias) c += bias[n + cc];
                    if (rrow) c += rrow[n + cc];
                    if (gelu_flag)
                        c = 0.5f * c * (1.f + erff(c * 0.70710678118654752f));
                    crow[n + cc] = c;
                }
            }
        }
    }
}

// ---------------- fp16 GEMM, BK=32, 64x128 tile (N=512 shapes) ---------------
__global__ __launch_bounds__(256)
void gemm_fp16_m64(const float* __restrict__ A, const float* __restrict__ Bm,
                   const float* __restrict__ bias, const float* __restrict__ resid,
                   float* __restrict__ Cm, int M, int N, int K, int gelu_flag) {
    __shared__ uint32_t As[2][64 * APH];
    __shared__ uint32_t Bs[2][16 * BPH];

    int tid  = threadIdx.x;
    int lane = tid & 31;
    int w    = tid >> 5;
    int g    = lane >> 2;
    int tig  = lane & 3;
    int wn   = w * 16;
    int m0 = blockIdx.y * 64;
    int n0 = blockIdx.x * 128;

    int aR[2], aQ[2];
    #pragma unroll
    for (int s = 0; s < 2; s++) { int idx = tid + s * 256; aR[s] = idx >> 3; aQ[s] = idx & 7; }
    int bKp0 = tid >> 5, bNq = tid & 31;

    float4 arg[2], brg[4];

    auto load_tile = [&](int k0) {
        #pragma unroll
        for (int s = 0; s < 2; s++)
            arg[s] = *(const float4*)&A[(size_t)(m0 + aR[s]) * K + k0 + aQ[s] * 4];
        #pragma unroll
        for (int s = 0; s < 2; s++) {
            int kp = bKp0 + s * 8;
            brg[2 * s]     = *(const float4*)&Bm[(size_t)(k0 + 2 * kp)     * N + n0 + bNq * 4];
            brg[2 * s + 1] = *(const float4*)&Bm[(size_t)(k0 + 2 * kp + 1) * N + n0 + bNq * 4];
        }
    };
    auto store_tile = [&](int buf) {
        #pragma unroll
        for (int s = 0; s < 2; s++) {
            uint2 a2 = {h2(arg[s].x, arg[s].y), h2(arg[s].z, arg[s].w)};
            *(uint2*)&As[buf][aR[s] * APH + aQ[s] * 2] = a2;
        }
        #pragma unroll
        for (int s = 0; s < 2; s++) {
            int kp = bKp0 + s * 8;
            float4 b0 = brg[2 * s], b1 = brg[2 * s + 1];
            uint4 bv = {h2(b0.x, b1.x), h2(b0.y, b1.y),
                        h2(b0.z, b1.z), h2(b0.w, b1.w)};
            *(uint4*)&Bs[buf][kp * BPH + bNq * 4] = bv;
        }
    };

    float d[4][2][4];
    #pragma unroll
    for (int i = 0; i < 4; i++)
        #pragma unroll
        for (int j = 0; j < 2; j++)
            #pragma unroll
            for (int r = 0; r < 4; r++) d[i][j][r] = 0.f;

    load_tile(0);
    store_tile(0);
    __syncthreads();

    int buf = 0;
    for (int k0 = 0; k0 < K; k0 += 32) {
        int nk = k0 + 32;
        if (nk < K) load_tile(nk);

        const uint32_t* Ac = As[buf];
        const uint32_t* Bc = Bs[buf];
        #pragma unroll
        for (int kb = 0; kb < 2; kb++) {
            uint32_t af[4][4];
            #pragma unroll
            for (int mi = 0; mi < 4; mi++) {
                int rb = mi * 16;
                af[mi][0] = Ac[(rb + g    ) * APH + kb * 8 + tig    ];
                af[mi][1] = Ac[(rb + g + 8) * APH + kb * 8 + tig    ];
                af[mi][2] = Ac[(rb + g    ) * APH + kb * 8 + tig + 4];
                af[mi][3] = Ac[(rb + g + 8) * APH + kb * 8 + tig + 4];
            }
            uint32_t bf[2][2];
            #pragma unroll
            for (int nj = 0; nj < 2; nj++) {
                int cb = wn + nj * 8;
                bf[nj][0] = Bc[(kb * 8 + tig    ) * BPH + cb + g];
                bf[nj][1] = Bc[(kb * 8 + tig + 4) * BPH + cb + g];
            }
            #pragma unroll
            for (int mi = 0; mi < 4; mi++)
                #pragma unroll
                for (int nj = 0; nj < 2; nj++)
                    mma_fp16(d[mi][nj], af[mi], bf[nj]);
        }

        if (nk < K) store_tile(buf ^ 1);
        __syncthreads();
        buf ^= 1;
    }

    #pragma unroll
    for (int mi = 0; mi < 4; mi++) {
        #pragma unroll
        for (int rr = 0; rr < 2; rr++) {
            int m = m0 + mi * 16 + g + rr * 8;
            float* crow = Cm + (size_t)m * N;
            const float* rrow = resid ? resid + (size_t)m * N : nullptr;
            #pragma unroll
            for (int nj = 0; nj < 2; nj++) {
                int n = n0 + wn + nj * 8 + tig * 2;
                #pragma unroll
                for (int cc = 0; cc < 2; cc++) {
                    float c = d[mi][nj][rr * 2 + cc];
                    if (bias) c += bias[n + cc];
                    if (rrow) c += rrow[n + cc];
                    if (gelu_flag)
                        c = 0.5f * c * (1.f + erff(c * 0.70710678118654752f));
                    crow[n + cc] = c;
                }
            }
        }
    }
}

// ---------------- tensor-core causal flash attention -------------------------
// QK^T: split-bf16 3-term m16n8k16 (proven). PV: NOW fp16 m16n8k16 —
// halves PV MMAs (64->32 per tile per warp); P in [0,1] and V are O(1),
// fp16 rounding == tf32 rounding, so accuracy is unchanged.
// Ps: packed f16x2 k-pairs, pitch 36. V: [kpair 0..31][n 0..63], pitch 72.
#define P2B 36
#define PVP 72
#define PSP 36
#define ATTN_SMEM_TC ((4 * 64 * P2B + 32 * PVP + 64 * PSP) * (int)sizeof(uint32_t)) // 55296

__global__ __launch_bounds__(128)
void attn_tc_kernel(const float* __restrict__ qkv, float* __restrict__ out) {
    extern __shared__ uint32_t smu[];
    uint32_t* Qh = smu;                    // [64][36] bf16x2
    uint32_t* Ql = Qh + 64 * P2B;          // [64][36] bf16x2
    uint32_t* Kh = Ql + 64 * P2B;          // [64][36] bf16x2
    uint32_t* Kl = Kh + 64 * P2B;          // [64][36] bf16x2
    uint32_t* Vt = Kl + 64 * P2B;          // [32 kpairs][72] f16x2
    uint32_t* Ps = Vt + 32 * PVP;          // [64][36] f16x2

    int tid  = threadIdx.x;
    int lane = tid & 31;
    int wid  = tid >> 5;
    int g    = lane >> 2;
    int tig  = lane & 3;
    int b = blockIdx.y >> 3, h = blockIdx.y & 7;
    int q0 = blockIdx.x * 64;
    const int RS = 3 * DMODEL;
    const float* qbase = qkv + (size_t)b * TLEN * RS + h * HDIM;
    const float* kbase = qbase + DMODEL;
    const float* vbase = qbase + 2 * DMODEL;

    for (int i = tid; i < 64 * 16; i += 128) {
        int r = i >> 4, j = i & 15;
        float4 v = *(const float4*)&qbase[(size_t)(q0 + r) * RS + j * 4];
        float q4[4] = {v.x * 0.125f, v.y * 0.125f, v.z * 0.125f, v.w * 0.125f};
        float hi[4], lo[4];
        #pragma unroll
        for (int c = 0; c < 4; c++) {
            __nv_bfloat16 hb = __float2bfloat16(q4[c]);
            hi[c] = __bfloat162float(hb);
            lo[c] = q4[c] - hi[c];
        }
        uint2 uh = {bf2(hi[0], hi[1]), bf2(hi[2], hi[3])};
        uint2 ul = {bf2(lo[0], lo[1]), bf2(lo[2], lo[3])};
        *(uint2*)&Qh[r * P2B + 2 * j] = uh;
        *(uint2*)&Ql[r * P2B + 2 * j] = ul;
    }

    float o[8][4];
    #pragma unroll
    for (int nj = 0; nj < 8; nj++)
        #pragma unroll
        for (int c = 0; c < 4; c++) o[nj][c] = 0.f;
    float m0 = -1e30f, m1 = -1e30f, l0 = 0.f, l1 = 0.f;
    int wrow = wid * 16;
    int rowA = wrow + g, rowB = wrow + g + 8;

    for (int j0 = 0; j0 <= q0; j0 += 64) {
        __syncthreads();   // prev iter's PV reads of Vt/Ps done before refill
        // K tile: split-bf16
        for (int i = tid; i < 64 * 16; i += 128) {
            int r = i >> 4, j = i & 15;
            float4 kv = *(const float4*)&kbase[(size_t)(j0 + r) * RS + j * 4];
            float k4[4] = {kv.x, kv.y, kv.z, kv.w};
            float hi[4], lo[4];
            #pragma unroll
            for (int c = 0; c < 4; c++) {
                __nv_bfloat16 hb = __float2bfloat16(k4[c]);
                hi[c] = __bfloat162float(hb);
                lo[c] = k4[c] - hi[c];
            }
            uint2 uh = {bf2(hi[0], hi[1]), bf2(hi[2], hi[3])};
            uint2 ul = {bf2(lo[0], lo[1]), bf2(lo[2], lo[3])};
            *(uint2*)&Kh[r * P2B + 2 * j] = uh;
            *(uint2*)&Kl[r * P2B + 2 * j] = ul;
        }
        // V tile: fp16 packed across row pairs -> [kpair][n]
        for (int i = tid; i < 32 * 16; i += 128) {
            int rp = i >> 4, j = i & 15;
            float4 v0 = *(const float4*)&vbase[(size_t)(j0 + 2 * rp)     * RS + j * 4];
            float4 v1 = *(const float4*)&vbase[(size_t)(j0 + 2 * rp + 1) * RS + j * 4];
            uint4 uv = {h2(v0.x, v1.x), h2(v0.y, v1.y),
                        h2(v0.z, v1.z), h2(v0.w, v1.w)};
            *(uint4*)&Vt[rp * PVP + 4 * j] = uv;
        }
        __syncthreads();

        // ---- S = Q K^T (split-bf16, m16n8k16) ----
        float s[8][4];
        #pragma unroll
        for (int nj = 0; nj < 8; nj++)
            #pragma unroll
            for (int c = 0; c < 4; c++) s[nj][c] = 0.f;

        #pragma unroll
        for (int kw = 0; kw < 32; kw += 8) {
            uint32_t ah[4], al[4];
            ah[0] = Qh[rowA * P2B + kw + tig];
            ah[1] = Qh[rowB * P2B + kw + tig];
            ah[2] = Qh[rowA * P2B + kw + tig + 4];
            ah[3] = Qh[rowB * P2B + kw + tig + 4];
            al[0] = Ql[rowA * P2B + kw + tig];
            al[1] = Ql[rowB * P2B + kw + tig];
            al[2] = Ql[rowA * P2B + kw + tig + 4];
            al[3] = Ql[rowB * P2B + kw + tig + 4];
            #pragma unroll
            for (int nj = 0; nj < 8; nj++) {
                int kr = nj * 8 + g;
                uint32_t bh2[2] = {Kh[kr * P2B + kw + tig], Kh[kr * P2B + kw + tig + 4]};
                uint32_t bl2[2] = {Kl[kr * P2B + kw + tig], Kl[kr * P2B + kw + tig + 4]};
                mma_bf16(s[nj], ah, bh2);
                mma_bf16(s[nj], al, bh2);
                mma_bf16(s[nj], ah, bl2);
            }
        }

        if (j0 == q0) {
            #pragma unroll
            for (int nj = 0; nj < 8; nj++) {
                int k0c = nj * 8 + 2 * tig;
                if (k0c     > rowA) s[nj][0] = -1e30f;
                if (k0c + 1 > rowA) s[nj][1] = -1e30f;
                if (k0c     > rowB) s[nj][2] = -1e30f;
                if (k0c + 1 > rowB) s[nj][3] = -1e30f;
            }
        }

        // ---- online softmax in registers ----
        float mx0 = m0, mx1 = m1;
        #pragma unroll
        for (int nj = 0; nj < 8; nj++) {
            mx0 = fmaxf(mx0, fmaxf(s[nj][0], s[nj][1]));
            mx1 = fmaxf(mx1, fmaxf(s[nj][2], s[nj][3]));
        }
        mx0 = fmaxf(mx0, __shfl_xor_sync(0xffffffffu, mx0, 1));
        mx0 = fmaxf(mx0, __shfl_xor_sync(0xffffffffu, mx0, 2));
        mx1 = fmaxf(mx1, __shfl_xor_sync(0xffffffffu, mx1, 1));
        mx1 = fmaxf(mx1, __shfl_xor_sync(0xffffffffu, mx1, 2));

        float fac0 = __expf(m0 - mx0), fac1 = __expf(m1 - mx1);
        float sum0 = 0.f, sum1 = 0.f;
        #pragma unroll
        for (int nj = 0; nj < 8; nj++) {
            s[nj][0] = __expf(s[nj][0] - mx0);
            s[nj][1] = __expf(s[nj][1] - mx0);
            s[nj][2] = __expf(s[nj][2] - mx1);
            s[nj][3] = __expf(s[nj][3] - mx1);
            sum0 += s[nj][0] + s[nj][1];
            sum1 += s[nj][2] + s[nj][3];
        }
        sum0 += __shfl_xor_sync(0xffffffffu, sum0, 1);
        sum0 += __shfl_xor_sync(0xffffffffu, sum0, 2);
        sum1 += __shfl_xor_sync(0xffffffffu, sum1, 1);
        sum1 += __shfl_xor_sync(0xffffffffu, sum1, 2);
        l0 = l0 * fac0 + sum0;
        l1 = l1 * fac1 + sum1;
        m0 = mx0; m1 = mx1;
        #pragma unroll
        for (int nj = 0; nj < 8; nj++) {
            o[nj][0] *= fac0; o[nj][1] *= fac0;
            o[nj][2] *= fac1; o[nj][3] *= fac1;
        }

        // P -> fp16 packed k-pairs (cols 2tig,2tig+1 are adjacent = one pair)
        #pragma unroll
        for (int nj = 0; nj < 8; nj++) {
            Ps[rowA * PSP + nj * 4 + tig] = h2(s[nj][0], s[nj][1]);
            Ps[rowB * PSP + nj * 4 + tig] = h2(s[nj][2], s[nj][3]);
        }
        __syncwarp();      // Ps rows are warp-private

        // ---- O += P V (fp16, m16n8k16: 4 k-blocks x 8 nj = 32 MMAs) ----
        #pragma unroll
        for (int kb = 0; kb < 4; kb++) {
            uint32_t a[4];
            a[0] = Ps[rowA * PSP + kb * 8 + tig];
            a[1] = Ps[rowB * PSP + kb * 8 + tig];
            a[2] = Ps[rowA * PSP + kb * 8 + tig + 4];
            a[3] = Ps[rowB * PSP + kb * 8 + tig + 4];
            #pragma unroll
            for (int nj = 0; nj < 8; nj++) {
                uint32_t bv[2] = {Vt[(kb * 8 + tig    ) * PVP + nj * 8 + g],
                                  Vt[(kb * 8 + tig + 4) * PVP + nj * 8 + g]};
                mma_fp16(o[nj], a, bv);
            }
        }
    }

    float inv0 = 1.f / l0, inv1 = 1.f / l1;
    size_t rA = (size_t)(b * TLEN + q0 + rowA) * DMODEL + h * HDIM;
    size_t rB = (size_t)(b * TLEN + q0 + rowB) * DMODEL + h * HDIM;
    #pragma unroll
    for (int nj = 0; nj < 8; nj++) {
        int cc = nj * 8 + 2 * tig;
        out[rA + cc]     = o[nj][0] * inv0;
        out[rA + cc + 1] = o[nj][1] * inv0;
        out[rB + cc]     = o[nj][2] * inv1;
        out[rB + cc + 1] = o[nj][3] * inv1;
    }
}

// ---------------- driver ----------------------------------------------------
extern "C" void kernel_launch(void* const* d_in, const int* in_sizes, int n_in,
                              void* d_out, int out_size) {
    const float* wte    = (const float*)d_in[0];
    const float* wpe    = (const float*)d_in[1];
    const float* ln1_w  = (const float*)d_in[2];
    const float* ln1_b  = (const float*)d_in[3];
    const float* attn_w = (const float*)d_in[4];
    const float* attn_b = (const float*)d_in[5];
    const float* proj_w = (const float*)d_in[6];
    const float* proj_b = (const float*)d_in[7];
    const float* ln2_w  = (const float*)d_in[8];
    const float* ln2_b  = (const float*)d_in[9];
    const float* fc_w   = (const float*)d_in[10];
    const float* fc_b   = (const float*)d_in[11];
    const float* fc2_w  = (const float*)d_in[12];
    const float* fc2_b  = (const float*)d_in[13];
    const float* lnf_w  = (const float*)d_in[14];
    const float* lnf_b  = (const float*)d_in[15];
    const int*   idx    = (const int*)d_in[16];
    float* out = (float*)d_out;

    void *px, *ph, *pqkv, *patt, *pfc;
    cudaGetSymbolAddress(&px, g_x);
    cudaGetSymbolAddress(&ph, g_h);
    cudaGetSymbolAddress(&pqkv, g_qkv);
    cudaGetSymbolAddress(&patt, g_att);
    cudaGetSymbolAddress(&pfc, g_fc);
    float* x   = (float*)px;
    float* h   = (float*)ph;
    float* qkv = (float*)pqkv;
    float* att = (float*)patt;
    float* fcb = (float*)pfc;

    cudaFuncSetAttribute(attn_tc_kernel,
                         cudaFuncAttributeMaxDynamicSharedMemorySize, ATTN_SMEM_TC);

    embed_kernel<<<MROWS, 256>>>(wte, wpe, idx, x);

    for (int l = 0; l < NLAYER; l++) {
        const float* aw  = attn_w + (size_t)l * DMODEL * 3 * DMODEL;
        const float* ab  = attn_b + (size_t)l * 3 * DMODEL;
        const float* pw  = proj_w + (size_t)l * DMODEL * DMODEL;
        const float* pb  = proj_b + (size_t)l * DMODEL;
        const float* fw  = fc_w   + (size_t)l * DMODEL * 4 * DMODEL;
        const float* fb  = fc_b   + (size_t)l * 4 * DMODEL;
        const float* f2w = fc2_w  + (size_t)l * 4 * DMODEL * DMODEL;
        const float* f2b = fc2_b  + (size_t)l * DMODEL;

        ln_kernel<<<MROWS, 256>>>(x, ln1_w + l * DMODEL, ln1_b + l * DMODEL, h);
        gemm_fp16<false><<<dim3(3 * DMODEL / 128, MROWS / 128), 256>>>(
            h, aw, ab, nullptr, qkv, MROWS, 3 * DMODEL, DMODEL, 0);
        attn_tc_kernel<<<dim3(TLEN / 64, BATCH * NHEAD), 128, ATTN_SMEM_TC>>>(qkv, att);
        gemm_fp16_m64<<<dim3(DMODEL / 128, MROWS / 64), 256>>>(
            att, pw, pb, x, x, MROWS, DMODEL, DMODEL, 0);
        ln_kernel<<<MROWS, 256>>>(x, ln2_w + l * DMODEL, ln2_b + l * DMODEL, h);
        gemm_fp16<false><<<dim3(4 * DMODEL / 128, MROWS / 128), 256>>>(
            h, fw, fb, nullptr, fcb, MROWS, 4 * DMODEL, DMODEL, 1);
        gemm_fp16_m64<<<dim3(DMODEL / 128, MROWS / 64), 256>>>(
            fcb, f2w, f2b, x, x, MROWS, DMODEL, 4 * DMODEL, 0);
    }

    ln_kernel<<<MROWS, 256>>>(x, lnf_w, lnf_b, h);
    gemm_fp16<true><<<dim3(MROWS / 128, VOCAB / 128), 256>>>(
        h, wte, nullptr, nullptr, out, MROWS, VOCAB, DMODEL, 0);
}

// round 16
// speedup vs baseline: 2.6284x; 1.0264x over previous
#include <cuda_runtime.h>
#include <cuda_bf16.h>
#include <math.h>
#include <stdint.h>

// ---------------- problem constants ----------------
#define NLAYER 4
#define NHEAD  8
#define DMODEL 512
#define TLEN   2048
#define BATCH  2
#define VOCAB  32000
#define HDIM   64
#define MROWS  (BATCH * TLEN)   // 4096
#define EPS    1e-5f

// ---------------- scratch (static device globals; no allocs allowed) -------
__device__ float g_x  [MROWS * DMODEL];
__device__ float g_h  [MROWS * DMODEL];
__device__ float g_qkv[MROWS * 3 * DMODEL];
__device__ float g_att[MROWS * DMODEL];
__device__ float g_fc [MROWS * 4 * DMODEL];

// ---------------- embedding ----------------
__global__ void embed_kernel(const float* __restrict__ wte,
                             const float* __restrict__ wpe,
                             const int*   __restrict__ idx,
                             float* __restrict__ x) {
    int m = blockIdx.x;
    int t = m % TLEN;
    int tok = idx[m];
    const float* we = wte + (size_t)tok * DMODEL;
    const float* pe = wpe + (size_t)t * DMODEL;
    float* xr = x + (size_t)m * DMODEL;
    for (int d = threadIdx.x; d < DMODEL; d += blockDim.x)
        xr[d] = we[d] + pe[d];
}

// ---------------- layernorm ----------------
__global__ __launch_bounds__(256)
void ln_kernel(const float* __restrict__ x, const float* __restrict__ w,
               const float* __restrict__ b, float* __restrict__ y) {
    int row = blockIdx.x;
    int tid = threadIdx.x;
    const float* xr = x + (size_t)row * DMODEL;
    float v0 = xr[tid];
    float v1 = xr[tid + 256];

    __shared__ float red[8];
    __shared__ float bc;

    float s = v0 + v1;
    #pragma unroll
    for (int o = 16; o; o >>= 1) s += __shfl_xor_sync(0xffffffffu, s, o);
    if ((tid & 31) == 0) red[tid >> 5] = s;
    __syncthreads();
    if (tid == 0) {
        float t = 0.f;
        #pragma unroll
        for (int i = 0; i < 8; i++) t += red[i];
        bc = t;
    }
    __syncthreads();
    float mu = bc * (1.f / DMODEL);
    float d0 = v0 - mu, d1 = v1 - mu;

    float s2 = d0 * d0 + d1 * d1;
    #pragma unroll
    for (int o = 16; o; o >>= 1) s2 += __shfl_xor_sync(0xffffffffu, s2, o);
    __syncthreads();
    if ((tid & 31) == 0) red[tid >> 5] = s2;
    __syncthreads();
    if (tid == 0) {
        float t = 0.f;
        #pragma unroll
        for (int i = 0; i < 8; i++) t += red[i];
        bc = t;
    }
    __syncthreads();
    float inv = rsqrtf(bc * (1.f / DMODEL) + EPS);

    float* yr = y + (size_t)row * DMODEL;
    yr[tid]       = d0 * inv * w[tid]       + b[tid];
    yr[tid + 256] = d1 * inv * w[tid + 256] + b[tid + 256];
}

// ---------------- mma helpers ----------------------------------------------
__device__ __forceinline__ uint32_t f2tf32(float v) {
    uint32_t r;
    asm("cvt.rna.tf32.f32 %0, %1;" : "=r"(r) : "f"(v));
    return r;
}
__device__ __forceinline__ uint32_t bf2(float lo, float hi) {
    uint32_t r;
    asm("cvt.rn.bf16x2.f32 %0, %1, %2;" : "=r"(r) : "f"(hi), "f"(lo));
    return r;
}
__device__ __forceinline__ uint32_t h2(float lo, float hi) {
    uint32_t r;
    asm("cvt.rn.f16x2.f32 %0, %1, %2;" : "=r"(r) : "f"(hi), "f"(lo));
    return r;
}

__device__ __forceinline__ void mma_tf32(float* d, const uint32_t* a, const uint32_t* b) {
    asm volatile(
        "mma.sync.aligned.m16n8k8.row.col.f32.tf32.tf32.f32 "
        "{%0,%1,%2,%3},{%4,%5,%6,%7},{%8,%9},{%0,%1,%2,%3};\n"
        : "+f"(d[0]), "+f"(d[1]), "+f"(d[2]), "+f"(d[3])
        : "r"(a[0]), "r"(a[1]), "r"(a[2]), "r"(a[3]), "r"(b[0]), "r"(b[1]));
}
__device__ __forceinline__ void mma_bf16(float* d, const uint32_t* a, const uint32_t* b) {
    asm volatile(
        "mma.sync.aligned.m16n8k16.row.col.f32.bf16.bf16.f32 "
        "{%0,%1,%2,%3},{%4,%5,%6,%7},{%8,%9},{%0,%1,%2,%3};\n"
        : "+f"(d[0]), "+f"(d[1]), "+f"(d[2]), "+f"(d[3])
        : "r"(a[0]), "r"(a[1]), "r"(a[2]), "r"(a[3]), "r"(b[0]), "r"(b[1]));
}
__device__ __forceinline__ void mma_fp16(float* d, const uint32_t* a, const uint32_t* b) {
    asm volatile(
        "mma.sync.aligned.m16n8k16.row.col.f32.f16.f16.f32 "
        "{%0,%1,%2,%3},{%4,%5,%6,%7},{%8,%9},{%0,%1,%2,%3};\n"
        : "+f"(d[0]), "+f"(d[1]), "+f"(d[2]), "+f"(d[3])
        : "r"(a[0]), "r"(a[1]), "r"(a[2]), "r"(a[3]), "r"(b[0]), "r"(b[1]));
}

// ---------------- pipelined fp16 GEMM, BK=32, 128x128 tile (r15 winner) ------
#define APH 20
#define BPH 136
template<bool BTRANS>
__global__ __launch_bounds__(256)
void gemm_fp16(const float* __restrict__ A, const float* __restrict__ Bm,
               const float* __restrict__ bias, const float* __restrict__ resid,
               float* __restrict__ Cm, int M, int N, int K, int gelu_flag) {
    __shared__ uint32_t As[2][128 * APH];
    __shared__ uint32_t Bs[2][16 * BPH];

    int tid  = threadIdx.x;
    int lane = tid & 31;
    int w    = tid >> 5;
    int g    = lane >> 2;
    int tig  = lane & 3;
    int wm   = (w >> 2) * 64;
    int wn   = (w & 3) * 32;
    int m0 = (BTRANS ? blockIdx.x : blockIdx.y) * 128;
    int n0 = (BTRANS ? blockIdx.y : blockIdx.x) * 128;

    int aR[4], aQ[4];
    #pragma unroll
    for (int s = 0; s < 4; s++) { int idx = tid + s * 256; aR[s] = idx >> 3; aQ[s] = idx & 7; }
    int bKp0 = tid >> 5, bNq = tid & 31;
    int bN[4], bQ[4];
    #pragma unroll
    for (int s = 0; s < 4; s++) { int idx = tid + s * 256; bN[s] = idx >> 3; bQ[s] = idx & 7; }

    float4 arg[4], brg[4];

    auto load_tile = [&](int k0) {
        #pragma unroll
        for (int s = 0; s < 4; s++)
            arg[s] = *(const float4*)&A[(size_t)(m0 + aR[s]) * K + k0 + aQ[s] * 4];
        if (!BTRANS) {
            #pragma unroll
            for (int s = 0; s < 2; s++) {
                int kp = bKp0 + s * 8;
                brg[2 * s]     = *(const float4*)&Bm[(size_t)(k0 + 2 * kp)     * N + n0 + bNq * 4];
                brg[2 * s + 1] = *(const float4*)&Bm[(size_t)(k0 + 2 * kp + 1) * N + n0 + bNq * 4];
            }
        } else {
            #pragma unroll
            for (int s = 0; s < 4; s++)
                brg[s] = *(const float4*)&Bm[(size_t)(n0 + bN[s]) * K + k0 + bQ[s] * 4];
        }
    };
    auto store_tile = [&](int buf) {
        #pragma unroll
        for (int s = 0; s < 4; s++) {
            uint2 a2 = {h2(arg[s].x, arg[s].y), h2(arg[s].z, arg[s].w)};
            *(uint2*)&As[buf][aR[s] * APH + aQ[s] * 2] = a2;
        }
        if (!BTRANS) {
            #pragma unroll
            for (int s = 0; s < 2; s++) {
                int kp = bKp0 + s * 8;
                float4 b0 = brg[2 * s], b1 = brg[2 * s + 1];
                uint4 bv = {h2(b0.x, b1.x), h2(b0.y, b1.y),
                            h2(b0.z, b1.z), h2(b0.w, b1.w)};
                *(uint4*)&Bs[buf][kp * BPH + bNq * 4] = bv;
            }
        } else {
            #pragma unroll
            for (int s = 0; s < 4; s++) {
                Bs[buf][(bQ[s] * 2    ) * BPH + bN[s]] = h2(brg[s].x, brg[s].y);
                Bs[buf][(bQ[s] * 2 + 1) * BPH + bN[s]] = h2(brg[s].z, brg[s].w);
            }
        }
    };

    float d[4][4][4];
    #pragma unroll
    for (int i = 0; i < 4; i++)
        #pragma unroll
        for (int j = 0; j < 4; j++)
            #pragma unroll
            for (int r = 0; r < 4; r++) d[i][j][r] = 0.f;

    load_tile(0);
    store_tile(0);
    __syncthreads();

    int buf = 0;
    for (int k0 = 0; k0 < K; k0 += 32) {
        int nk = k0 + 32;
        if (nk < K) load_tile(nk);

        const uint32_t* Ac = As[buf];
        const uint32_t* Bc = Bs[buf];
        #pragma unroll
        for (int kb = 0; kb < 2; kb++) {
            uint32_t af[4][4];
            #pragma unroll
            for (int mi = 0; mi < 4; mi++) {
                int rb = wm + mi * 16;
                af[mi][0] = Ac[(rb + g    ) * APH + kb * 8 + tig    ];
                af[mi][1] = Ac[(rb + g + 8) * APH + kb * 8 + tig    ];
                af[mi][2] = Ac[(rb + g    ) * APH + kb * 8 + tig + 4];
                af[mi][3] = Ac[(rb + g + 8) * APH + kb * 8 + tig + 4];
            }
            uint32_t bf[4][2];
            #pragma unroll
            for (int nj = 0; nj < 4; nj++) {
                int cb = wn + nj * 8;
                bf[nj][0] = Bc[(kb * 8 + tig    ) * BPH + cb + g];
                bf[nj][1] = Bc[(kb * 8 + tig + 4) * BPH + cb + g];
            }
            #pragma unroll
            for (int mi = 0; mi < 4; mi++)
                #pragma unroll
                for (int nj = 0; nj < 4; nj++)
                    mma_fp16(d[mi][nj], af[mi], bf[nj]);
        }

        if (nk < K) store_tile(buf ^ 1);
        __syncthreads();
        buf ^= 1;
    }

    #pragma unroll
    for (int mi = 0; mi < 4; mi++) {
        #pragma unroll
        for (int rr = 0; rr < 2; rr++) {
            int m = m0 + wm + mi * 16 + g + rr * 8;
            float* crow = Cm + (size_t)m * N;
            const float* rrow = resid ? resid + (size_t)m * N : nullptr;
            #pragma unroll
            for (int nj = 0; nj < 4; nj++) {
                int n = n0 + wn + nj * 8 + tig * 2;
                #pragma unroll
                for (int cc = 0; cc < 2; cc++) {
                    float c = d[mi][nj][rr * 2 + cc];
                    if (bias) c += bias[n + cc];
                    if (rrow) c += rrow[n + cc];
                    if (gelu_flag)
                        c = 0.5f * c * (1.f + erff(c * 0.70710678118654752f));
                    crow[n + cc] = c;
                }
            }
        }
    }
}

// ---------------- fp16 GEMM, BK=32, 64x128 tile (N=512 shapes) ---------------
__global__ __launch_bounds__(256)
void gemm_fp16_m64(const float* __restrict__ A, const float* __restrict__ Bm,
                   const float* __restrict__ bias, const float* __restrict__ resid,
                   float* __restrict__ Cm, int M, int N, int K, int gelu_flag) {
    __shared__ uint32_t As[2][64 * APH];
    __shared__ uint32_t Bs[2][16 * BPH];

    int tid  = threadIdx.x;
    int lane = tid & 31;
    int w    = tid >> 5;
    int g    = lane >> 2;
    int tig  = lane & 3;
    int wn   = w * 16;
    int m0 = blockIdx.y * 64;
    int n0 = blockIdx.x * 128;

    int aR[2], aQ[2];
    #pragma unroll
    for (int s = 0; s < 2; s++) { int idx = tid + s * 256; aR[s] = idx >> 3; aQ[s] = idx & 7; }
    int bKp0 = tid >> 5, bNq = tid & 31;

    float4 arg[2], brg[4];

    auto load_tile = [&](int k0) {
        #pragma unroll
        for (int s = 0; s < 2; s++)
            arg[s] = *(const float4*)&A[(size_t)(m0 + aR[s]) * K + k0 + aQ[s] * 4];
        #pragma unroll
        for (int s = 0; s < 2; s++) {
            int kp = bKp0 + s * 8;
            brg[2 * s]     = *(const float4*)&Bm[(size_t)(k0 + 2 * kp)     * N + n0 + bNq * 4];
            brg[2 * s + 1] = *(const float4*)&Bm[(size_t)(k0 + 2 * kp + 1) * N + n0 + bNq * 4];
        }
    };
    auto store_tile = [&](int buf) {
        #pragma unroll
        for (int s = 0; s < 2; s++) {
            uint2 a2 = {h2(arg[s].x, arg[s].y), h2(arg[s].z, arg[s].w)};
            *(uint2*)&As[buf][aR[s] * APH + aQ[s] * 2] = a2;
        }
        #pragma unroll
        for (int s = 0; s < 2; s++) {
            int kp = bKp0 + s * 8;
            float4 b0 = brg[2 * s], b1 = brg[2 * s + 1];
            uint4 bv = {h2(b0.x, b1.x), h2(b0.y, b1.y),
                        h2(b0.z, b1.z), h2(b0.w, b1.w)};
            *(uint4*)&Bs[buf][kp * BPH + bNq * 4] = bv;
        }
    };

    float d[4][2][4];
    #pragma unroll
    for (int i = 0; i < 4; i++)
        #pragma unroll
        for (int j = 0; j < 2; j++)
            #pragma unroll
            for (int r = 0; r < 4; r++) d[i][j][r] = 0.f;

    load_tile(0);
    store_tile(0);
    __syncthreads();

    int buf = 0;
    for (int k0 = 0; k0 < K; k0 += 32) {
        int nk = k0 + 32;
        if (nk < K) load_tile(nk);

        const uint32_t* Ac = As[buf];
        const uint32_t* Bc = Bs[buf];
        #pragma unroll
        for (int kb = 0; kb < 2; kb++) {
            uint32_t af[4][4];
            #pragma unroll
            for (int mi = 0; mi < 4; mi++) {
                int rb = mi * 16;
                af[mi][0] = Ac[(rb + g    ) * APH + kb * 8 + tig    ];
                af[mi][1] = Ac[(rb + g + 8) * APH + kb * 8 + tig    ];
                af[mi][2] = Ac[(rb + g    ) * APH + kb * 8 + tig + 4];
                af[mi][3] = Ac[(rb + g + 8) * APH + kb * 8 + tig + 4];
            }
            uint32_t bf[2][2];
            #pragma unroll
            for (int nj = 0; nj < 2; nj++) {
                int cb = wn + nj * 8;
                bf[nj][0] = Bc[(kb * 8 + tig    ) * BPH + cb + g];
                bf[nj][1] = Bc[(kb * 8 + tig + 4) * BPH + cb + g];
            }
            #pragma unroll
            for (int mi = 0; mi < 4; mi++)
                #pragma unroll
                for (int nj = 0; nj < 2; nj++)
                    mma_fp16(d[mi][nj], af[mi], bf[nj]);
        }

        if (nk < K) store_tile(buf ^ 1);
        __syncthreads();
        buf ^= 1;
    }

    #pragma unroll
    for (int mi = 0; mi < 4; mi++) {
        #pragma unroll
        for (int rr = 0; rr < 2; rr++) {
            int m = m0 + mi * 16 + g + rr * 8;
            float* crow = Cm + (size_t)m * N;
            const float* rrow = resid ? resid + (size_t)m * N : nullptr;
            #pragma unroll
            for (int nj = 0; nj < 2; nj++) {
                int n = n0 + wn + nj * 8 + tig * 2;
                #pragma unroll
                for (int cc = 0; cc < 2; cc++) {
                    float c = d[mi][nj][rr * 2 + cc];
                    if (bias) c += bias[n + cc];
                    if (rrow) c += rrow[n + cc];
                    if (gelu_flag)
                        c = 0.5f * c * (1.f + erff(c * 0.70710678118654752f));
                    crow[n + cc] = c;
                }
            }
        }
    }
}

// ---------------- tensor-core causal flash attention (round-12 proven) -------
// split-bf16 QK m16n8k16, tf32-k8 PV, dedicated Ps, 2 syncthreads/tile.
// Heavy tiles launch first (reversed q0) to shrink the tail wave.
#define P2B 36
#define PVP 72
#define ATTN_SMEM_TC ((4 * 64 * P2B + 2 * 64 * PVP) * (int)sizeof(uint32_t)) // 73728

__global__ __launch_bounds__(128)
void attn_tc_kernel(const float* __restrict__ qkv, float* __restrict__ out) {
    extern __shared__ uint32_t smu[];
    uint32_t* Qh = smu;
    uint32_t* Ql = Qh + 64 * P2B;
    uint32_t* Kh = Ql + 64 * P2B;
    uint32_t* Kl = Kh + 64 * P2B;
    uint32_t* Vt = Kl + 64 * P2B;
    uint32_t* Ps = Vt + 64 * PVP;

    int tid  = threadIdx.x;
    int lane = tid & 31;
    int wid  = tid >> 5;
    int g    = lane >> 2;
    int tig  = lane & 3;
    int b = blockIdx.y >> 3, h = blockIdx.y & 7;
    int q0 = (int)(gridDim.x - 1 - blockIdx.x) * 64;   // heavy tiles first
    const int RS = 3 * DMODEL;
    const float* qbase = qkv + (size_t)b * TLEN * RS + h * HDIM;
    const float* kbase = qbase + DMODEL;
    const float* vbase = qbase + 2 * DMODEL;

    for (int i = tid; i < 64 * 16; i += 128) {
        int r = i >> 4, j = i & 15;
        float4 v = *(const float4*)&qbase[(size_t)(q0 + r) * RS + j * 4];
        float q4[4] = {v.x * 0.125f, v.y * 0.125f, v.z * 0.125f, v.w * 0.125f};
        float hi[4], lo[4];
        #pragma unroll
        for (int c = 0; c < 4; c++) {
            __nv_bfloat16 hb = __float2bfloat16(q4[c]);
            hi[c] = __bfloat162float(hb);
            lo[c] = q4[c] - hi[c];
        }
        uint2 uh = {bf2(hi[0], hi[1]), bf2(hi[2], hi[3])};
        uint2 ul = {bf2(lo[0], lo[1]), bf2(lo[2], lo[3])};
        *(uint2*)&Qh[r * P2B + 2 * j] = uh;
        *(uint2*)&Ql[r * P2B + 2 * j] = ul;
    }

    float o[8][4];
    #pragma unroll
    for (int nj = 0; nj < 8; nj++)
        #pragma unroll
        for (int c = 0; c < 4; c++) o[nj][c] = 0.f;
    float m0 = -1e30f, m1 = -1e30f, l0 = 0.f, l1 = 0.f;
    int wrow = wid * 16;
    int rowA = wrow + g, rowB = wrow + g + 8;

    for (int j0 = 0; j0 <= q0; j0 += 64) {
        __syncthreads();
        for (int i = tid; i < 64 * 16; i += 128) {
            int r = i >> 4, j = i & 15;
            float4 kv = *(const float4*)&kbase[(size_t)(j0 + r) * RS + j * 4];
            float4 vv = *(const float4*)&vbase[(size_t)(j0 + r) * RS + j * 4];
            float k4[4] = {kv.x, kv.y, kv.z, kv.w};
            float hi[4], lo[4];
            #pragma unroll
            for (int c = 0; c < 4; c++) {
                __nv_bfloat16 hb = __float2bfloat16(k4[c]);
                hi[c] = __bfloat162float(hb);
                lo[c] = k4[c] - hi[c];
            }
            uint2 uh = {bf2(hi[0], hi[1]), bf2(hi[2], hi[3])};
            uint2 ul = {bf2(lo[0], lo[1]), bf2(lo[2], lo[3])};
            *(uint2*)&Kh[r * P2B + 2 * j] = uh;
            *(uint2*)&Kl[r * P2B + 2 * j] = ul;
            uint4 uv = {f2tf32(vv.x), f2tf32(vv.y), f2tf32(vv.z), f2tf32(vv.w)};
            *(uint4*)&Vt[r * PVP + 4 * j] = uv;
        }
        __syncthreads();

        float s[8][4];
        #pragma unroll
        for (int nj = 0; nj < 8; nj++)
            #pragma unroll
            for (int c = 0; c < 4; c++) s[nj][c] = 0.f;

        #pragma unroll
        for (int kw = 0; kw < 32; kw += 8) {
            uint32_t ah[4], al[4];
            ah[0] = Qh[rowA * P2B + kw + tig];
            ah[1] = Qh[rowB * P2B + kw + tig];
            ah[2] = Qh[rowA * P2B + kw + tig + 4];
            ah[3] = Qh[rowB * P2B + kw + tig + 4];
            al[0] = Ql[rowA * P2B + kw + tig];
            al[1] = Ql[rowB * P2B + kw + tig];
            al[2] = Ql[rowA * P2B + kw + tig + 4];
            al[3] = Ql[rowB * P2B + kw + tig + 4];
            #pragma unroll
            for (int nj = 0; nj < 8; nj++) {
                int kr = nj * 8 + g;
                uint32_t bh2[2] = {Kh[kr * P2B + kw + tig], Kh[kr * P2B + kw + tig + 4]};
                uint32_t bl2[2] = {Kl[kr * P2B + kw + tig], Kl[kr * P2B + kw + tig + 4]};
                mma_bf16(s[nj], ah, bh2);
                mma_bf16(s[nj], al, bh2);
                mma_bf16(s[nj], ah, bl2);
            }
        }

        if (j0 == q0) {
            #pragma unroll
            for (int nj = 0; nj < 8; nj++) {
                int k0c = nj * 8 + 2 * tig;
                if (k0c     > rowA) s[nj][0] = -1e30f;
                if (k0c + 1 > rowA) s[nj][1] = -1e30f;
                if (k0c     > rowB) s[nj][2] = -1e30f;
                if (k0c + 1 > rowB) s[nj][3] = -1e30f;
            }
        }

        float mx0 = m0, mx1 = m1;
        #pragma unroll
        for (int nj = 0; nj < 8; nj++) {
            mx0 = fmaxf(mx0, fmaxf(s[nj][0], s[nj][1]));
            mx1 = fmaxf(mx1, fmaxf(s[nj][2], s[nj][3]));
        }
        mx0 = fmaxf(mx0, __shfl_xor_sync(0xffffffffu, mx0, 1));
        mx0 = fmaxf(mx0, __shfl_xor_sync(0xffffffffu, mx0, 2));
        mx1 = fmaxf(mx1, __shfl_xor_sync(0xffffffffu, mx1, 1));
        mx1 = fmaxf(mx1, __shfl_xor_sync(0xffffffffu, mx1, 2));

        float fac0 = __expf(m0 - mx0), fac1 = __expf(m1 - mx1);
        float sum0 = 0.f, sum1 = 0.f;
        #pragma unroll
        for (int nj = 0; nj < 8; nj++) {
            s[nj][0] = __expf(s[nj][0] - mx0);
            s[nj][1] = __expf(s[nj][1] - mx0);
            s[nj][2] = __expf(s[nj][2] - mx1);
            s[nj][3] = __expf(s[nj][3] - mx1);
            sum0 += s[nj][0] + s[nj][1];
            sum1 += s[nj][2] + s[nj][3];
        }
        sum0 += __shfl_xor_sync(0xffffffffu, sum0, 1);
        sum0 += __shfl_xor_sync(0xffffffffu, sum0, 2);
        sum1 += __shfl_xor_sync(0xffffffffu, sum1, 1);
        sum1 += __shfl_xor_sync(0xffffffffu, sum1, 2);
        l0 = l0 * fac0 + sum0;
        l1 = l1 * fac1 + sum1;
        m0 = mx0; m1 = mx1;
        #pragma unroll
        for (int nj = 0; nj < 8; nj++) {
            o[nj][0] *= fac0; o[nj][1] *= fac0;
            o[nj][2] *= fac1; o[nj][3] *= fac1;
        }

        #pragma unroll
        for (int nj = 0; nj < 8; nj++) {
            int cc = nj * 8 + 2 * tig;
            uint2 pa = {f2tf32(s[nj][0]), f2tf32(s[nj][1])};
            uint2 pb = {f2tf32(s[nj][2]), f2tf32(s[nj][3])};
            *(uint2*)&Ps[rowA * PVP + cc] = pa;
            *(uint2*)&Ps[rowB * PVP + cc] = pb;
        }
        __syncwarp();

        #pragma unroll
        for (int k8 = 0; k8 < 64; k8 += 8) {
            uint32_t a[4];
            a[0] = Ps[rowA * PVP + k8 + tig];
            a[1] = Ps[rowB * PVP + k8 + tig];
            a[2] = Ps[rowA * PVP + k8 + tig + 4];
            a[3] = Ps[rowB * PVP + k8 + tig + 4];
            #pragma unroll
            for (int nj = 0; nj < 8; nj++) {
                uint32_t bv[2] = {Vt[(k8 + tig) * PVP + nj * 8 + g],
                                  Vt[(k8 + tig + 4) * PVP + nj * 8 + g]};
                mma_tf32(o[nj], a, bv);
            }
        }
    }

    float inv0 = 1.f / l0, inv1 = 1.f / l1;
    size_t rA = (size_t)(b * TLEN + q0 + rowA) * DMODEL + h * HDIM;
    size_t rB = (size_t)(b * TLEN + q0 + rowB) * DMODEL + h * HDIM;
    #pragma unroll
    for (int nj = 0; nj < 8; nj++) {
        int cc = nj * 8 + 2 * tig;
        out[rA + cc]     = o[nj][0] * inv0;
        out[rA + cc + 1] = o[nj][1] * inv0;
        out[rB + cc]     = o[nj][2] * inv1;
        out[rB + cc + 1] = o[nj][3] * inv1;
    }
}

// ---------------- driver ----------------------------------------------------
extern "C" void kernel_launch(void* const* d_in, const int* in_sizes, int n_in,
                              void* d_out, int out_size) {
    const float* wte    = (const float*)d_in[0];
    const float* wpe    = (const float*)d_in[1];
    const float* ln1_w  = (const float*)d_in[2];
    const float* ln1_b  = (const float*)d_in[3];
    const float* attn_w = (const float*)d_in[4];
    const float* attn_b = (const float*)d_in[5];
    const float* proj_w = (const float*)d_in[6];
    const float* proj_b = (const float*)d_in[7];
    const float* ln2_w  = (const float*)d_in[8];
    const float* ln2_b  = (const float*)d_in[9];
    const float* fc_w   = (const float*)d_in[10];
    const float* fc_b   = (const float*)d_in[11];
    const float* fc2_w  = (const float*)d_in[12];
    const float* fc2_b  = (const float*)d_in[13];
    const float* lnf_w  = (const float*)d_in[14];
    const float* lnf_b  = (const float*)d_in[15];
    const int*   idx    = (const int*)d_in[16];
    float* out = (float*)d_out;

    void *px, *ph, *pqkv, *patt, *pfc;
    cudaGetSymbolAddress(&px, g_x);
    cudaGetSymbolAddress(&ph, g_h);
    cudaGetSymbolAddress(&pqkv, g_qkv);
    cudaGetSymbolAddress(&patt, g_att);
    cudaGetSymbolAddress(&pfc, g_fc);
    float* x   = (float*)px;
    float* h   = (float*)ph;
    float* qkv = (float*)pqkv;
    float* att = (float*)patt;
    float* fcb = (float*)pfc;

    cudaFuncSetAttribute(attn_tc_kernel,
                         cudaFuncAttributeMaxDynamicSharedMemorySize, ATTN_SMEM_TC);

    embed_kernel<<<MROWS, 256>>>(wte, wpe, idx, x);

    for (int l = 0; l < NLAYER; l++) {
        const float* aw  = attn_w + (size_t)l * DMODEL * 3 * DMODEL;
        const float* ab  = attn_b + (size_t)l * 3 * DMODEL;
        const float* pw  = proj_w + (size_t)l * DMODEL * DMODEL;
        const float* pb  = proj_b + (size_t)l * DMODEL;
        const float* fw  = fc_w   + (size_t)l * DMODEL * 4 * DMODEL;
        const float* fb  = fc_b   + (size_t)l * 4 * DMODEL;
        const float* f2w = fc2_w  + (size_t)l * 4 * DMODEL * DMODEL;
        const float* f2b = fc2_b  + (size_t)l * DMODEL;

        ln_kernel<<<MROWS, 256>>>(x, ln1_w + l * DMODEL, ln1_b + l * DMODEL, h);
        gemm_fp16<false><<<dim3(3 * DMODEL / 128, MROWS / 128), 256>>>(
            h, aw, ab, nullptr, qkv, MROWS, 3 * DMODEL, DMODEL, 0);
        attn_tc_kernel<<<dim3(TLEN / 64, BATCH * NHEAD), 128, ATTN_SMEM_TC>>>(qkv, att);
        gemm_fp16_m64<<<dim3(DMODEL / 128, MROWS / 64), 256>>>(
            att, pw, pb, x, x, MROWS, DMODEL, DMODEL, 0);
        ln_kernel<<<MROWS, 256>>>(x, ln2_w + l * DMODEL, ln2_b + l * DMODEL, h);
        gemm_fp16<false><<<dim3(4 * DMODEL / 128, MROWS / 128), 256>>>(
            h, fw, fb, nullptr, fcb, MROWS, 4 * DMODEL, DMODEL, 1);
        gemm_fp16_m64<<<dim3(DMODEL / 128, MROWS / 64), 256>>>(
            fcb, f2w, f2b, x, x, MROWS, DMODEL, 4 * DMODEL, 0);
    }

    ln_kernel<<<MROWS, 256>>>(x, lnf_w, lnf_b, h);
    gemm_fp16<true><<<dim3(MROWS / 128, VOCAB / 128), 256>>>(
        h, wte, nullptr, nullptr, out, MROWS, VOCAB, DMODEL, 0);
}

// round 17
// speedup vs baseline: 2.7977x; 1.0644x over previous
#include <cuda_runtime.h>
#include <cuda_bf16.h>
#include <math.h>
#include <stdint.h>

// ---------------- problem constants ----------------
#define NLAYER 4
#define NHEAD  8
#define DMODEL 512
#define TLEN   2048
#define BATCH  2
#define VOCAB  32000
#define HDIM   64
#define MROWS  (BATCH * TLEN)   // 4096
#define DW     (DMODEL / 2)     // 256 words per row
#define EPS    1e-5f

// ---------------- scratch (static device globals; no allocs allowed) -------
__device__ float    g_x   [MROWS * DMODEL];           // residual (fp32)
__device__ float    g_qkv [MROWS * 3 * DMODEL];       // qkv (fp32)
__device__ uint32_t g_h16 [MROWS * DW];               // LN out (fp16x2)
__device__ uint32_t g_att16[MROWS * DW];              // attn out (fp16x2)
__device__ uint32_t g_fc16[MROWS * 2 * DMODEL];       // mlp hidden (fp16x2)
// fp16x2 packed weights: [K/2 kpair rows][N] word layout (B operand ready)
__device__ uint32_t g_aw16 [NLAYER * DW * 3 * DMODEL];
__device__ uint32_t g_pw16 [NLAYER * DW * DMODEL];
__device__ uint32_t g_fw16 [NLAYER * DW * 4 * DMODEL];
__device__ uint32_t g_f2w16[NLAYER * 2 * DMODEL * DMODEL];
__device__ uint32_t g_wte16[VOCAB * DW];              // [n][kpair] words

// ---------------- helpers ----------------------------------------------------
__device__ __forceinline__ uint32_t f2tf32(float v) {
    uint32_t r;
    asm("cvt.rna.tf32.f32 %0, %1;" : "=r"(r) : "f"(v));
    return r;
}
__device__ __forceinline__ uint32_t bf2(float lo, float hi) {
    uint32_t r;
    asm("cvt.rn.bf16x2.f32 %0, %1, %2;" : "=r"(r) : "f"(hi), "f"(lo));
    return r;
}
__device__ __forceinline__ uint32_t h2(float lo, float hi) {
    uint32_t r;
    asm("cvt.rn.f16x2.f32 %0, %1, %2;" : "=r"(r) : "f"(hi), "f"(lo));
    return r;
}
__device__ __forceinline__ void mma_tf32(float* d, const uint32_t* a, const uint32_t* b) {
    asm volatile(
        "mma.sync.aligned.m16n8k8.row.col.f32.tf32.tf32.f32 "
        "{%0,%1,%2,%3},{%4,%5,%6,%7},{%8,%9},{%0,%1,%2,%3};\n"
        : "+f"(d[0]), "+f"(d[1]), "+f"(d[2]), "+f"(d[3])
        : "r"(a[0]), "r"(a[1]), "r"(a[2]), "r"(a[3]), "r"(b[0]), "r"(b[1]));
}
__device__ __forceinline__ void mma_bf16(float* d, const uint32_t* a, const uint32_t* b) {
    asm volatile(
        "mma.sync.aligned.m16n8k16.row.col.f32.bf16.bf16.f32 "
        "{%0,%1,%2,%3},{%4,%5,%6,%7},{%8,%9},{%0,%1,%2,%3};\n"
        : "+f"(d[0]), "+f"(d[1]), "+f"(d[2]), "+f"(d[3])
        : "r"(a[0]), "r"(a[1]), "r"(a[2]), "r"(a[3]), "r"(b[0]), "r"(b[1]));
}
__device__ __forceinline__ void mma_fp16(float* d, const uint32_t* a, const uint32_t* b) {
    asm volatile(
        "mma.sync.aligned.m16n8k16.row.col.f32.f16.f16.f32 "
        "{%0,%1,%2,%3},{%4,%5,%6,%7},{%8,%9},{%0,%1,%2,%3};\n"
        : "+f"(d[0]), "+f"(d[1]), "+f"(d[2]), "+f"(d[3])
        : "r"(a[0]), "r"(a[1]), "r"(a[2]), "r"(a[3]), "r"(b[0]), "r"(b[1]));
}

// ---------------- one-time weight conversion ---------------------------------
// [Kt][N] fp32 -> [Kt/2][N] fp16x2 words: word(kp,n) = (in[2kp][n], in[2kp+1][n])
__global__ void wcvt_col(const float* __restrict__ in, uint32_t* __restrict__ outp,
                         int Kt, int N) {
    size_t i = (size_t)blockIdx.x * blockDim.x + threadIdx.x;
    size_t total = (size_t)(Kt / 2) * N;
    if (i >= total) return;
    size_t kp = i / N, n = i - kp * N;
    outp[i] = h2(in[(2 * kp) * (size_t)N + n], in[(2 * kp + 1) * (size_t)N + n]);
}
// row-major pair pack (wte): word i = (in[2i], in[2i+1])
__global__ void wcvt_row(const float* __restrict__ in, uint32_t* __restrict__ outp,
                         size_t total) {
    size_t i = (size_t)blockIdx.x * blockDim.x + threadIdx.x;
    if (i >= total) return;
    float2 v = ((const float2*)in)[i];
    outp[i] = h2(v.x, v.y);
}

// ---------------- embedding ----------------
__global__ void embed_kernel(const float* __restrict__ wte,
                             const float* __restrict__ wpe,
                             const int*   __restrict__ idx,
                             float* __restrict__ x) {
    int m = blockIdx.x;
    int t = m % TLEN;
    int tok = idx[m];
    const float* we = wte + (size_t)tok * DMODEL;
    const float* pe = wpe + (size_t)t * DMODEL;
    float* xr = x + (size_t)m * DMODEL;
    for (int d = threadIdx.x; d < DMODEL; d += blockDim.x)
        xr[d] = we[d] + pe[d];
}

// ---------------- layernorm -> packed fp16 output ----------------------------
__global__ __launch_bounds__(256)
void ln16_kernel(const float* __restrict__ x, const float* __restrict__ w,
                 const float* __restrict__ b, uint32_t* __restrict__ y16) {
    int row = blockIdx.x;
    int tid = threadIdx.x;
    const float* xr = x + (size_t)row * DMODEL;
    float2 v = *(const float2*)&xr[2 * tid];

    __shared__ float red[8];
    __shared__ float bc;

    float s = v.x + v.y;
    #pragma unroll
    for (int o = 16; o; o >>= 1) s += __shfl_xor_sync(0xffffffffu, s, o);
    if ((tid & 31) == 0) red[tid >> 5] = s;
    __syncthreads();
    if (tid == 0) {
        float t = 0.f;
        #pragma unroll
        for (int i = 0; i < 8; i++) t += red[i];
        bc = t;
    }
    __syncthreads();
    float mu = bc * (1.f / DMODEL);
    float d0 = v.x - mu, d1 = v.y - mu;

    float s2 = d0 * d0 + d1 * d1;
    #pragma unroll
    for (int o = 16; o; o >>= 1) s2 += __shfl_xor_sync(0xffffffffu, s2, o);
    __syncthreads();
    if ((tid & 31) == 0) red[tid >> 5] = s2;
    __syncthreads();
    if (tid == 0) {
        float t = 0.f;
        #pragma unroll
        for (int i = 0; i < 8; i++) t += red[i];
        bc = t;
    }
    __syncthreads();
    float inv = rsqrtf(bc * (1.f / DMODEL) + EPS);

    float2 w2 = *(const float2*)&w[2 * tid];
    float2 b2 = *(const float2*)&b[2 * tid];
    float y0 = d0 * inv * w2.x + b2.x;
    float y1 = d1 * inv * w2.y + b2.y;
    y16[(size_t)row * DW + tid] = h2(y0, y1);
}

// ---------------- fp16 GEMM, BK=32, 128x128 tile, packed operands ------------
// C[M,N] = A16[M,Kw] @ B16 (+bias) (+resid) (opt gelu).
// A16: [m][kpair] words. B16 (!BT): [kpair][N] words. B16 (BT): [n][kpair].
// No conversions in the mainloop: LDG.128 -> STS.128 raw.
// CMODE 0: fp32 C.  CMODE 1: packed fp16 C (no resid).
#define APH 20
#define BPH 136
template<bool BTRANS, int CMODE>
__global__ __launch_bounds__(256)
void gemm16(const uint32_t* __restrict__ A16, const uint32_t* __restrict__ B16,
            const float* __restrict__ bias, const float* __restrict__ resid,
            void* __restrict__ Cv, int M, int N, int K, int gelu_flag) {
    __shared__ uint32_t As[2][128 * APH];
    __shared__ uint32_t Bs[2][16 * BPH];

    int Kw = K >> 1;
    int tid  = threadIdx.x;
    int lane = tid & 31;
    int w    = tid >> 5;
    int g    = lane >> 2;
    int tig  = lane & 3;
    int wm   = (w >> 2) * 64;
    int wn   = (w & 3) * 32;
    int m0 = (BTRANS ? blockIdx.x : blockIdx.y) * 128;
    int n0 = (BTRANS ? blockIdx.y : blockIdx.x) * 128;

    // A: 2 uint4/thread: u = tid + s*256 -> r = u>>2 (0..127), q4 = u&3
    int aR[2], aQ4[2];
    #pragma unroll
    for (int s = 0; s < 2; s++) { int u = tid + s * 256; aR[s] = u >> 2; aQ4[s] = u & 3; }
    // B !BT: 2 uint4/thread: kp = tid>>5 + s*8, nq = tid&31
    int bKp0 = tid >> 5, bNq = tid & 31;
    // B BT: 2 uint4/thread: n = u>>2, q4 = tid&3
    int bN[2];
    #pragma unroll
    for (int s = 0; s < 2; s++) { bN[s] = (tid + s * 256) >> 2; }
    int bQ4 = tid & 3;

    uint4 aReg[2], bReg[2];

    auto load_tile = [&](int k0w) {
        #pragma unroll
        for (int s = 0; s < 2; s++)
            aReg[s] = *(const uint4*)&A16[(size_t)(m0 + aR[s]) * Kw + k0w + aQ4[s] * 4];
        if (!BTRANS) {
            #pragma unroll
            for (int s = 0; s < 2; s++)
                bReg[s] = *(const uint4*)&B16[(size_t)(k0w + bKp0 + s * 8) * N + n0 + bNq * 4];
        } else {
            #pragma unroll
            for (int s = 0; s < 2; s++)
                bReg[s] = *(const uint4*)&B16[(size_t)(n0 + bN[s]) * Kw + k0w + bQ4 * 4];
        }
    };
    auto store_tile = [&](int buf) {
        #pragma unroll
        for (int s = 0; s < 2; s++)
            *(uint4*)&As[buf][aR[s] * APH + aQ4[s] * 4] = aReg[s];
        if (!BTRANS) {
            #pragma unroll
            for (int s = 0; s < 2; s++)
                *(uint4*)&Bs[buf][(bKp0 + s * 8) * BPH + bNq * 4] = bReg[s];
        } else {
            #pragma unroll
            for (int s = 0; s < 2; s++) {
                const uint32_t* wv = (const uint32_t*)&bReg[s];
                #pragma unroll
                for (int j = 0; j < 4; j++)
                    Bs[buf][(bQ4 * 4 + j) * BPH + bN[s]] = wv[j];
            }
        }
    };

    float d[4][4][4];
    #pragma unroll
    for (int i = 0; i < 4; i++)
        #pragma unroll
        for (int j = 0; j < 4; j++)
            #pragma unroll
            for (int r = 0; r < 4; r++) d[i][j][r] = 0.f;

    load_tile(0);
    store_tile(0);
    __syncthreads();

    int buf = 0;
    for (int k0w = 0; k0w < Kw; k0w += 16) {
        int nk = k0w + 16;
        if (nk < Kw) load_tile(nk);

        const uint32_t* Ac = As[buf];
        const uint32_t* Bc = Bs[buf];
        #pragma unroll
        for (int kb = 0; kb < 2; kb++) {
            uint32_t af[4][4];
            #pragma unroll
            for (int mi = 0; mi < 4; mi++) {
                int rb = wm + mi * 16;
                af[mi][0] = Ac[(rb + g    ) * APH + kb * 8 + tig    ];
                af[mi][1] = Ac[(rb + g + 8) * APH + kb * 8 + tig    ];
                af[mi][2] = Ac[(rb + g    ) * APH + kb * 8 + tig + 4];
                af[mi][3] = Ac[(rb + g + 8) * APH + kb * 8 + tig + 4];
            }
            uint32_t bf[4][2];
            #pragma unroll
            for (int nj = 0; nj < 4; nj++) {
                int cb = wn + nj * 8;
                bf[nj][0] = Bc[(kb * 8 + tig    ) * BPH + cb + g];
                bf[nj][1] = Bc[(kb * 8 + tig + 4) * BPH + cb + g];
            }
            #pragma unroll
            for (int mi = 0; mi < 4; mi++)
                #pragma unroll
                for (int nj = 0; nj < 4; nj++)
                    mma_fp16(d[mi][nj], af[mi], bf[nj]);
        }

        if (nk < Kw) store_tile(buf ^ 1);
        __syncthreads();
        buf ^= 1;
    }

    #pragma unroll
    for (int mi = 0; mi < 4; mi++) {
        #pragma unroll
        for (int rr = 0; rr < 2; rr++) {
            int m = m0 + wm + mi * 16 + g + rr * 8;
            #pragma unroll
            for (int nj = 0; nj < 4; nj++) {
                int n = n0 + wn + nj * 8 + tig * 2;
                float c0 = d[mi][nj][rr * 2];
                float c1 = d[mi][nj][rr * 2 + 1];
                if (bias) { c0 += bias[n]; c1 += bias[n + 1]; }
                if (CMODE == 0 && resid) {
                    const float* rrow = resid + (size_t)m * N;
                    c0 += rrow[n]; c1 += rrow[n + 1];
                }
                if (gelu_flag) {
                    c0 = 0.5f * c0 * (1.f + erff(c0 * 0.70710678118654752f));
                    c1 = 0.5f * c1 * (1.f + erff(c1 * 0.70710678118654752f));
                }
                if (CMODE == 0) {
                    float* crow = (float*)Cv + (size_t)m * N;
                    crow[n] = c0; crow[n + 1] = c1;
                } else {
                    uint32_t* crow = (uint32_t*)Cv + (size_t)m * (N >> 1);
                    crow[n >> 1] = h2(c0, c1);
                }
            }
        }
    }
}

// ---------------- fp16 GEMM, BK=32, 64x128 tile (N=512 shapes, fp32 C) -------
__global__ __launch_bounds__(256)
void gemm16_m64(const uint32_t* __restrict__ A16, const uint32_t* __restrict__ B16,
                const float* __restrict__ bias, const float* __restrict__ resid,
                float* __restrict__ Cm, int M, int N, int K, int gelu_flag) {
    __shared__ uint32_t As[2][64 * APH];
    __shared__ uint32_t Bs[2][16 * BPH];

    int Kw = K >> 1;
    int tid  = threadIdx.x;
    int lane = tid & 31;
    int w    = tid >> 5;
    int g    = lane >> 2;
    int tig  = lane & 3;
    int wn   = w * 16;
    int m0 = blockIdx.y * 64;
    int n0 = blockIdx.x * 128;

    int aR = tid >> 2, aQ4 = tid & 3;      // 1 uint4/thread (64 x 16 words)
    int bKp0 = tid >> 5, bNq = tid & 31;   // 2 uint4/thread

    uint4 aReg, bReg[2];

    auto load_tile = [&](int k0w) {
        aReg = *(const uint4*)&A16[(size_t)(m0 + aR) * Kw + k0w + aQ4 * 4];
        #pragma unroll
        for (int s = 0; s < 2; s++)
            bReg[s] = *(const uint4*)&B16[(size_t)(k0w + bKp0 + s * 8) * N + n0 + bNq * 4];
    };
    auto store_tile = [&](int buf) {
        *(uint4*)&As[buf][aR * APH + aQ4 * 4] = aReg;
        #pragma unroll
        for (int s = 0; s < 2; s++)
            *(uint4*)&Bs[buf][(bKp0 + s * 8) * BPH + bNq * 4] = bReg[s];
    };

    float d[4][2][4];
    #pragma unroll
    for (int i = 0; i < 4; i++)
        #pragma unroll
        for (int j = 0; j < 2; j++)
            #pragma unroll
            for (int r = 0; r < 4; r++) d[i][j][r] = 0.f;

    load_tile(0);
    store_tile(0);
    __syncthreads();

    int buf = 0;
    for (int k0w = 0; k0w < Kw; k0w += 16) {
        int nk = k0w + 16;
        if (nk < Kw) load_tile(nk);

        const uint32_t* Ac = As[buf];
        const uint32_t* Bc = Bs[buf];
        #pragma unroll
        for (int kb = 0; kb < 2; kb++) {
            uint32_t af[4][4];
            #pragma unroll
            for (int mi = 0; mi < 4; mi++) {
                int rb = mi * 16;
                af[mi][0] = Ac[(rb + g    ) * APH + kb * 8 + tig    ];
                af[mi][1] = Ac[(rb + g + 8) * APH + kb * 8 + tig    ];
                af[mi][2] = Ac[(rb + g    ) * APH + kb * 8 + tig + 4];
                af[mi][3] = Ac[(rb + g + 8) * APH + kb * 8 + tig + 4];
            }
            uint32_t bf[2][2];
            #pragma unroll
            for (int nj = 0; nj < 2; nj++) {
                int cb = wn + nj * 8;
                bf[nj][0] = Bc[(kb * 8 + tig    ) * BPH + cb + g];
                bf[nj][1] = Bc[(kb * 8 + tig + 4) * BPH + cb + g];
            }
            #pragma unroll
            for (int mi = 0; mi < 4; mi++)
                #pragma unroll
                for (int nj = 0; nj < 2; nj++)
                    mma_fp16(d[mi][nj], af[mi], bf[nj]);
        }

        if (nk < Kw) store_tile(buf ^ 1);
        __syncthreads();
        buf ^= 1;
    }

    #pragma unroll
    for (int mi = 0; mi < 4; mi++) {
        #pragma unroll
        for (int rr = 0; rr < 2; rr++) {
            int m = m0 + mi * 16 + g + rr * 8;
            float* crow = Cm + (size_t)m * N;
            const float* rrow = resid ? resid + (size_t)m * N : nullptr;
            #pragma unroll
            for (int nj = 0; nj < 2; nj++) {
                int n = n0 + wn + nj * 8 + tig * 2;
                #pragma unroll
                for (int cc = 0; cc < 2; cc++) {
                    float c = d[mi][nj][rr * 2 + cc];
                    if (bias) c += bias[n + cc];
                    if (rrow) c += rrow[n + cc];
                    if (gelu_flag)
                        c = 0.5f * c * (1.f + erff(c * 0.70710678118654752f));
                    crow[n + cc] = c;
                }
            }
        }
    }
}

// ---------------- tensor-core causal flash attention (round-16 proven) -------
// split-bf16 QK m16n8k16, tf32-k8 PV, dedicated Ps; epilogue writes fp16 att.
#define P2B 36
#define PVP 72
#define ATTN_SMEM_TC ((4 * 64 * P2B + 2 * 64 * PVP) * (int)sizeof(uint32_t)) // 73728

__global__ __launch_bounds__(128)
void attn_tc_kernel(const float* __restrict__ qkv, uint32_t* __restrict__ out16) {
    extern __shared__ uint32_t smu[];
    uint32_t* Qh = smu;
    uint32_t* Ql = Qh + 64 * P2B;
    uint32_t* Kh = Ql + 64 * P2B;
    uint32_t* Kl = Kh + 64 * P2B;
    uint32_t* Vt = Kl + 64 * P2B;
    uint32_t* Ps = Vt + 64 * PVP;

    int tid  = threadIdx.x;
    int lane = tid & 31;
    int wid  = tid >> 5;
    int g    = lane >> 2;
    int tig  = lane & 3;
    int b = blockIdx.y >> 3, h = blockIdx.y & 7;
    int q0 = (int)(gridDim.x - 1 - blockIdx.x) * 64;   // heavy tiles first
    const int RS = 3 * DMODEL;
    const float* qbase = qkv + (size_t)b * TLEN * RS + h * HDIM;
    const float* kbase = qbase + DMODEL;
    const float* vbase = qbase + 2 * DMODEL;

    for (int i = tid; i < 64 * 16; i += 128) {
        int r = i >> 4, j = i & 15;
        float4 v = *(const float4*)&qbase[(size_t)(q0 + r) * RS + j * 4];
        float q4[4] = {v.x * 0.125f, v.y * 0.125f, v.z * 0.125f, v.w * 0.125f};
        float hi[4], lo[4];
        #pragma unroll
        for (int c = 0; c < 4; c++) {
            __nv_bfloat16 hb = __float2bfloat16(q4[c]);
            hi[c] = __bfloat162float(hb);
            lo[c] = q4[c] - hi[c];
        }
        uint2 uh = {bf2(hi[0], hi[1]), bf2(hi[2], hi[3])};
        uint2 ul = {bf2(lo[0], lo[1]), bf2(lo[2], lo[3])};
        *(uint2*)&Qh[r * P2B + 2 * j] = uh;
        *(uint2*)&Ql[r * P2B + 2 * j] = ul;
    }

    float o[8][4];
    #pragma unroll
    for (int nj = 0; nj < 8; nj++)
        #pragma unroll
        for (int c = 0; c < 4; c++) o[nj][c] = 0.f;
    float m0 = -1e30f, m1 = -1e30f, l0 = 0.f, l1 = 0.f;
    int wrow = wid * 16;
    int rowA = wrow + g, rowB = wrow + g + 8;

    for (int j0 = 0; j0 <= q0; j0 += 64) {
        __syncthreads();
        for (int i = tid; i < 64 * 16; i += 128) {
            int r = i >> 4, j = i & 15;
            float4 kv = *(const float4*)&kbase[(size_t)(j0 + r) * RS + j * 4];
            float4 vv = *(const float4*)&vbase[(size_t)(j0 + r) * RS + j * 4];
            float k4[4] = {kv.x, kv.y, kv.z, kv.w};
            float hi[4], lo[4];
            #pragma unroll
            for (int c = 0; c < 4; c++) {
                __nv_bfloat16 hb = __float2bfloat16(k4[c]);
                hi[c] = __bfloat162float(hb);
                lo[c] = k4[c] - hi[c];
            }
            uint2 uh = {bf2(hi[0], hi[1]), bf2(hi[2], hi[3])};
            uint2 ul = {bf2(lo[0], lo[1]), bf2(lo[2], lo[3])};
            *(uint2*)&Kh[r * P2B + 2 * j] = uh;
            *(uint2*)&Kl[r * P2B + 2 * j] = ul;
            uint4 uv = {f2tf32(vv.x), f2tf32(vv.y), f2tf32(vv.z), f2tf32(vv.w)};
            *(uint4*)&Vt[r * PVP + 4 * j] = uv;
        }
        __syncthreads();

        float s[8][4];
        #pragma unroll
        for (int nj = 0; nj < 8; nj++)
            #pragma unroll
            for (int c = 0; c < 4; c++) s[nj][c] = 0.f;

        #pragma unroll
        for (int kw = 0; kw < 32; kw += 8) {
            uint32_t ah[4], al[4];
            ah[0] = Qh[rowA * P2B + kw + tig];
            ah[1] = Qh[rowB * P2B + kw + tig];
            ah[2] = Qh[rowA * P2B + kw + tig + 4];
            ah[3] = Qh[rowB * P2B + kw + tig + 4];
            al[0] = Ql[rowA * P2B + kw + tig];
            al[1] = Ql[rowB * P2B + kw + tig];
            al[2] = Ql[rowA * P2B + kw + tig + 4];
            al[3] = Ql[rowB * P2B + kw + tig + 4];
            #pragma unroll
            for (int nj = 0; nj < 8; nj++) {
                int kr = nj * 8 + g;
                uint32_t bh2[2] = {Kh[kr * P2B + kw + tig], Kh[kr * P2B + kw + tig + 4]};
                uint32_t bl2[2] = {Kl[kr * P2B + kw + tig], Kl[kr * P2B + kw + tig + 4]};
                mma_bf16(s[nj], ah, bh2);
                mma_bf16(s[nj], al, bh2);
                mma_bf16(s[nj], ah, bl2);
            }
        }

        if (j0 == q0) {
            #pragma unroll
            for (int nj = 0; nj < 8; nj++) {
                int k0c = nj * 8 + 2 * tig;
                if (k0c     > rowA) s[nj][0] = -1e30f;
                if (k0c + 1 > rowA) s[nj][1] = -1e30f;
                if (k0c     > rowB) s[nj][2] = -1e30f;
                if (k0c + 1 > rowB) s[nj][3] = -1e30f;
            }
        }

        float mx0 = m0, mx1 = m1;
        #pragma unroll
        for (int nj = 0; nj < 8; nj++) {
            mx0 = fmaxf(mx0, fmaxf(s[nj][0], s[nj][1]));
            mx1 = fmaxf(mx1, fmaxf(s[nj][2], s[nj][3]));
        }
        mx0 = fmaxf(mx0, __shfl_xor_sync(0xffffffffu, mx0, 1));
        mx0 = fmaxf(mx0, __shfl_xor_sync(0xffffffffu, mx0, 2));
        mx1 = fmaxf(mx1, __shfl_xor_sync(0xffffffffu, mx1, 1));
        mx1 = fmaxf(mx1, __shfl_xor_sync(0xffffffffu, mx1, 2));

        float fac0 = __expf(m0 - mx0), fac1 = __expf(m1 - mx1);
        float sum0 = 0.f, sum1 = 0.f;
        #pragma unroll
        for (int nj = 0; nj < 8; nj++) {
            s[nj][0] = __expf(s[nj][0] - mx0);
            s[nj][1] = __expf(s[nj][1] - mx0);
            s[nj][2] = __expf(s[nj][2] - mx1);
            s[nj][3] = __expf(s[nj][3] - mx1);
            sum0 += s[nj][0] + s[nj][1];
            sum1 += s[nj][2] + s[nj][3];
        }
        sum0 += __shfl_xor_sync(0xffffffffu, sum0, 1);
        sum0 += __shfl_xor_sync(0xffffffffu, sum0, 2);
        sum1 += __shfl_xor_sync(0xffffffffu, sum1, 1);
        sum1 += __shfl_xor_sync(0xffffffffu, sum1, 2);
        l0 = l0 * fac0 + sum0;
        l1 = l1 * fac1 + sum1;
        m0 = mx0; m1 = mx1;
        #pragma unroll
        for (int nj = 0; nj < 8; nj++) {
            o[nj][0] *= fac0; o[nj][1] *= fac0;
            o[nj][2] *= fac1; o[nj][3] *= fac1;
        }

        #pragma unroll
        for (int nj = 0; nj < 8; nj++) {
            int cc = nj * 8 + 2 * tig;
            uint2 pa = {f2tf32(s[nj][0]), f2tf32(s[nj][1])};
            uint2 pb = {f2tf32(s[nj][2]), f2tf32(s[nj][3])};
            *(uint2*)&Ps[rowA * PVP + cc] = pa;
            *(uint2*)&Ps[rowB * PVP + cc] = pb;
        }
        __syncwarp();

        #pragma unroll
        for (int k8 = 0; k8 < 64; k8 += 8) {
            uint32_t a[4];
            a[0] = Ps[rowA * PVP + k8 + tig];
            a[1] = Ps[rowB * PVP + k8 + tig];
            a[2] = Ps[rowA * PVP + k8 + tig + 4];
            a[3] = Ps[rowB * PVP + k8 + tig + 4];
            #pragma unroll
            for (int nj = 0; nj < 8; nj++) {
                uint32_t bv[2] = {Vt[(k8 + tig) * PVP + nj * 8 + g],
                                  Vt[(k8 + tig + 4) * PVP + nj * 8 + g]};
                mma_tf32(o[nj], a, bv);
            }
        }
    }

    // epilogue -> packed fp16 att (word = pair of adjacent head cols)
    float inv0 = 1.f / l0, inv1 = 1.f / l1;
    size_t rAw = (size_t)(b * TLEN + q0 + rowA) * DW + h * (HDIM / 2);
    size_t rBw = (size_t)(b * TLEN + q0 + rowB) * DW + h * (HDIM / 2);
    #pragma unroll
    for (int nj = 0; nj < 8; nj++) {
        out16[rAw + nj * 4 + tig] = h2(o[nj][0] * inv0, o[nj][1] * inv0);
        out16[rBw + nj * 4 + tig] = h2(o[nj][2] * inv1, o[nj][3] * inv1);
    }
}

// ---------------- driver ----------------------------------------------------
extern "C" void kernel_launch(void* const* d_in, const int* in_sizes, int n_in,
                              void* d_out, int out_size) {
    const float* wte    = (const float*)d_in[0];
    const float* wpe    = (const float*)d_in[1];
    const float* ln1_w  = (const float*)d_in[2];
    const float* ln1_b  = (const float*)d_in[3];
    const float* attn_w = (const float*)d_in[4];
    const float* attn_b = (const float*)d_in[5];
    const float* proj_w = (const float*)d_in[6];
    const float* proj_b = (const float*)d_in[7];
    const float* ln2_w  = (const float*)d_in[8];
    const float* ln2_b  = (const float*)d_in[9];
    const float* fc_w   = (const float*)d_in[10];
    const float* fc_b   = (const float*)d_in[11];
    const float* fc2_w  = (const float*)d_in[12];
    const float* fc2_b  = (const float*)d_in[13];
    const float* lnf_w  = (const float*)d_in[14];
    const float* lnf_b  = (const float*)d_in[15];
    const int*   idx    = (const int*)d_in[16];
    float* out = (float*)d_out;

    void *px, *pqkv, *ph16, *patt16, *pfc16;
    void *paw, *ppw, *pfw, *pf2w, *pwt;
    cudaGetSymbolAddress(&px, g_x);
    cudaGetSymbolAddress(&pqkv, g_qkv);
    cudaGetSymbolAddress(&ph16, g_h16);
    cudaGetSymbolAddress(&patt16, g_att16);
    cudaGetSymbolAddress(&pfc16, g_fc16);
    cudaGetSymbolAddress(&paw, g_aw16);
    cudaGetSymbolAddress(&ppw, g_pw16);
    cudaGetSymbolAddress(&pfw, g_fw16);
    cudaGetSymbolAddress(&pf2w, g_f2w16);
    cudaGetSymbolAddress(&pwt, g_wte16);
    float*    x     = (float*)px;
    float*    qkv   = (float*)pqkv;
    uint32_t* h16   = (uint32_t*)ph16;
    uint32_t* att16 = (uint32_t*)patt16;
    uint32_t* fc16  = (uint32_t*)pfc16;
    uint32_t* aw16  = (uint32_t*)paw;
    uint32_t* pw16  = (uint32_t*)ppw;
    uint32_t* fw16  = (uint32_t*)pfw;
    uint32_t* f2w16 = (uint32_t*)pf2w;
    uint32_t* wte16 = (uint32_t*)pwt;

    cudaFuncSetAttribute(attn_tc_kernel,
                         cudaFuncAttributeMaxDynamicSharedMemorySize, ATTN_SMEM_TC);

    // one-time weight conversions (graph-captured; deterministic)
    {
        size_t t1 = (size_t)NLAYER * DW * 3 * DMODEL;
        wcvt_col<<<(unsigned)((t1 + 255) / 256), 256>>>(attn_w, aw16,
            NLAYER * DMODEL, 3 * DMODEL);
        size_t t2 = (size_t)NLAYER * DW * DMODEL;
        wcvt_col<<<(unsigned)((t2 + 255) / 256), 256>>>(proj_w, pw16,
            NLAYER * DMODEL, DMODEL);
        size_t t3 = (size_t)NLAYER * DW * 4 * DMODEL;
        wcvt_col<<<(unsigned)((t3 + 255) / 256), 256>>>(fc_w, fw16,
            NLAYER * DMODEL, 4 * DMODEL);
        size_t t4 = (size_t)NLAYER * 2 * DMODEL * DMODEL;
        wcvt_col<<<(unsigned)((t4 + 255) / 256), 256>>>(fc2_w, f2w16,
            NLAYER * 4 * DMODEL, DMODEL);
        size_t t5 = (size_t)VOCAB * DW;
        wcvt_row<<<(unsigned)((t5 + 255) / 256), 256>>>(wte, wte16, t5);
    }

    embed_kernel<<<MROWS, 256>>>(wte, wpe, idx, x);

    for (int l = 0; l < NLAYER; l++) {
        const uint32_t* aw  = aw16  + (size_t)l * DW * 3 * DMODEL;
        const float*    ab  = attn_b + (size_t)l * 3 * DMODEL;
        const uint32_t* pw  = pw16  + (size_t)l * DW * DMODEL;
        const float*    pb  = proj_b + (size_t)l * DMODEL;
        const uint32_t* fw  = fw16  + (size_t)l * DW * 4 * DMODEL;
        const float*    fb  = fc_b  + (size_t)l * 4 * DMODEL;
        const uint32_t* f2w = f2w16 + (size_t)l * 2 * DMODEL * DMODEL;
        const float*    f2b = fc2_b + (size_t)l * DMODEL;

        ln16_kernel<<<MROWS, 256>>>(x, ln1_w + l * DMODEL, ln1_b + l * DMODEL, h16);
        gemm16<false, 0><<<dim3(3 * DMODEL / 128, MROWS / 128), 256>>>(
            h16, aw, ab, nullptr, qkv, MROWS, 3 * DMODEL, DMODEL, 0);
        attn_tc_kernel<<<dim3(TLEN / 64, BATCH * NHEAD), 128, ATTN_SMEM_TC>>>(qkv, att16);
        gemm16_m64<<<dim3(DMODEL / 128, MROWS / 64), 256>>>(
            att16, pw, pb, x, x, MROWS, DMODEL, DMODEL, 0);
        ln16_kernel<<<MROWS, 256>>>(x, ln2_w + l * DMODEL, ln2_b + l * DMODEL, h16);
        gemm16<false, 1><<<dim3(4 * DMODEL / 128, MROWS / 128), 256>>>(
            h16, fw, fb, nullptr, fc16, MROWS, 4 * DMODEL, DMODEL, 1);
        gemm16_m64<<<dim3(DMODEL / 128, MROWS / 64), 256>>>(
            fc16, f2w, f2b, x, x, MROWS, DMODEL, 4 * DMODEL, 0);
    }

    ln16_kernel<<<MROWS, 256>>>(x, lnf_w, lnf_b, h16);
    gemm16<true, 0><<<dim3(MROWS / 128, VOCAB / 128), 256>>>(
        h16, wte16, nullptr, nullptr, out, MROWS, VOCAB, DMODEL, 0);
}